// round 10
// baseline (speedup 1.0000x reference)
#include <cuda_runtime.h>
#include <math.h>

#define BB   8
#define SS   4096
#define EE   512
#define PP   64
#define LL   4
#define HH   256
#define CC   2
#define FF   2048
#define MROWS (BB*SS)
#define NSPLIT 8

enum { EPI_NONE = 0, EPI_PHI = 1, EPI_GELU = 2, EPI_RES = 3, EPI_DIV = 4 };

// ---------------- scratch ----------------
__device__ float g_H  [(size_t)MROWS*EE];
__device__ float g_A  [(size_t)MROWS*EE];
__device__ float g_V  [(size_t)MROWS*EE];
__device__ float g_Mb [(size_t)MROWS*FF];
__device__ float g_Q  [(size_t)MROWS*PP];
__device__ float g_K  [(size_t)MROWS*PP];
__device__ float g_KV [(size_t)BB*PP*EE];
__device__ float g_KVp[(size_t)NSPLIT*BB*PP*EE];
__device__ float g_Z  [(size_t)BB*PP];
__device__ float g_Zp [(size_t)NSPLIT*BB*PP];
__device__ float g_DEN[(size_t)MROWS];

// packed bf16x2 hi/lo
__device__ unsigned g_Hh [(size_t)MROWS*(EE/2)],  g_Hl [(size_t)MROWS*(EE/2)];
__device__ unsigned g_NMh[(size_t)MROWS*(EE/2)],  g_NMl[(size_t)MROWS*(EE/2)];
__device__ unsigned g_Qh [(size_t)MROWS*(PP/2)],  g_Ql [(size_t)MROWS*(PP/2)];
__device__ unsigned g_KVTh[(size_t)BB*EE*(PP/2)], g_KVTl[(size_t)BB*EE*(PP/2)];
// bf16 weights [N][K/2]
__device__ unsigned g_Wqh[(size_t)LL*PP*(EE/2)],  g_Wql_[(size_t)LL*PP*(EE/2)];
__device__ unsigned g_Wkh[(size_t)LL*PP*(EE/2)],  g_Wkl_[(size_t)LL*PP*(EE/2)];
__device__ unsigned g_Wvh[(size_t)LL*EE*(EE/2)],  g_Wvl_[(size_t)LL*EE*(EE/2)];
__device__ unsigned g_Woh[(size_t)LL*EE*(EE/2)],  g_Wol_[(size_t)LL*EE*(EE/2)];
// int8 2-chunk activations (word = 4 consecutive-k int8) + row scales
__device__ unsigned g_LN1[(size_t)MROWS*(EE/4)],  g_LN2[(size_t)MROWS*(EE/4)];
__device__ float    g_saLN[(size_t)MROWS];
__device__ unsigned g_Mb1[(size_t)MROWS*(FF/4)],  g_Mb2[(size_t)MROWS*(FF/4)];
__device__ float    g_saMb[(size_t)MROWS];
// int8 2-chunk weights [N][K/4] + col scales
__device__ unsigned g_W1s1[(size_t)LL*FF*(EE/4)], g_W1s2[(size_t)LL*FF*(EE/4)];
__device__ float    g_sbW1[(size_t)LL*FF];
__device__ unsigned g_W2s1[(size_t)LL*EE*(FF/4)], g_W2s2[(size_t)LL*EE*(FF/4)];
__device__ float    g_sbW2[(size_t)LL*EE];

// ---------------- helpers ----------------
__device__ __forceinline__ void cp_async16(void* smem, const void* gmem) {
    unsigned sa = (unsigned)__cvta_generic_to_shared(smem);
    asm volatile("cp.async.cg.shared.global [%0], [%1], 16;" :: "r"(sa), "l"(gmem));
}
__device__ __forceinline__ void cp_commit() { asm volatile("cp.async.commit_group;"); }
template<int N>
__device__ __forceinline__ void cp_wait() {
    asm volatile("cp.async.wait_group %0;" :: "n"(N));
}

__device__ __forceinline__ void split2(float x, float y, unsigned& hi, unsigned& lo) {
    asm("cvt.rn.bf16x2.f32 %0, %1, %2;" : "=r"(hi) : "f"(y), "f"(x));
    float hx = __uint_as_float(hi << 16);
    float hy = __uint_as_float(hi & 0xFFFF0000u);
    asm("cvt.rn.bf16x2.f32 %0, %1, %2;" : "=r"(lo) : "f"(y - hy), "f"(x - hx));
}

__device__ __forceinline__ void mma_bf16(float c[4], const unsigned a[4], const unsigned b[2]) {
    asm volatile(
        "mma.sync.aligned.m16n8k16.row.col.f32.bf16.bf16.f32 "
        "{%0,%1,%2,%3}, {%4,%5,%6,%7}, {%8,%9}, {%0,%1,%2,%3};"
        : "+f"(c[0]), "+f"(c[1]), "+f"(c[2]), "+f"(c[3])
        : "r"(a[0]), "r"(a[1]), "r"(a[2]), "r"(a[3]), "r"(b[0]), "r"(b[1]));
}

__device__ __forceinline__ void mma_s8(int c[4], const unsigned a[4], const unsigned b[2]) {
    asm volatile(
        "mma.sync.aligned.m16n8k32.row.col.s32.s8.s8.s32 "
        "{%0,%1,%2,%3}, {%4,%5,%6,%7}, {%8,%9}, {%0,%1,%2,%3};"
        : "+r"(c[0]), "+r"(c[1]), "+r"(c[2]), "+r"(c[3])
        : "r"(a[0]), "r"(a[1]), "r"(a[2]), "r"(a[3]), "r"(b[0]), "r"(b[1]));
}

__device__ __forceinline__ void quant2(float x, float invs, int& c1, int& c2) {
    float q = x * invs;
    c1 = max(-127, min(127, __float2int_rn(q)));
    c2 = max(-128, min(127, __float2int_rn((q - (float)c1) * 256.f)));
}
__device__ __forceinline__ unsigned pack4(int a, int b, int c, int d) {
    return (unsigned)(a & 0xFF) | ((unsigned)(b & 0xFF) << 8) |
           ((unsigned)(c & 0xFF) << 16) | ((unsigned)(d & 0xFF) << 24);
}
__device__ __forceinline__ float gelu_f(float v) {
    float u = 0.7978845608028654f * (v + 0.044715f * v * v * v);
    return 0.5f * v * (1.f + tanhf(u));
}

// ---------------- bf16 weight transpose+split ----------------
__device__ __forceinline__ void wsplit_tile(const float* Wl, unsigned* Th, unsigned* Tl,
                                            int K, int N, int k0, int n0, float (*t)[33]) {
    int tx = threadIdx.x, ty = threadIdx.y;
    #pragma unroll
    for (int i = 0; i < 4; i++)
        t[ty + i * 8][tx] = Wl[(size_t)(k0 + ty + i * 8) * N + n0 + tx];
    __syncthreads();
    int tid = ty * 32 + tx;
    #pragma unroll
    for (int i = 0; i < 2; i++) {
        int w = tid + i * 256;
        int n = w >> 4, kp = w & 15;
        unsigned h, l;
        split2(t[2 * kp][n], t[2 * kp + 1][n], h, l);
        size_t o = (size_t)(n0 + n) * (K >> 1) + (k0 >> 1) + kp;
        Th[o] = h; Tl[o] = l;
    }
}

__global__ void wsplit_kernel(const float* __restrict__ W,
                              unsigned* __restrict__ Th, unsigned* __restrict__ Tl,
                              int K, int N) {
    __shared__ float t[32][33];
    wsplit_tile(W + (size_t)blockIdx.z * K * N,
                Th + (size_t)blockIdx.z * N * (K >> 1),
                Tl + (size_t)blockIdx.z * N * (K >> 1),
                K, N, blockIdx.y * 32, blockIdx.x * 32, t);
}

struct WSEntry { const float* W; unsigned* Th; unsigned* Tl; int K; int N; int nblk; };
struct WSPack  { WSEntry e[4]; int cnt; };
__global__ void wsplit_multi(WSPack p) {
    __shared__ float t[32][33];
    int bid = blockIdx.x, i = 0;
    while (i + 1 < p.cnt && bid >= p.e[i].nblk) { bid -= p.e[i].nblk; i++; }
    WSEntry E = p.e[i];
    int tiles_n = E.N / 32, tpl = tiles_n * (E.K / 32);
    int layer = bid / tpl, rem = bid % tpl;
    wsplit_tile(E.W + (size_t)layer * E.K * E.N,
                E.Th + (size_t)layer * E.N * (E.K >> 1),
                E.Tl + (size_t)layer * E.N * (E.K >> 1),
                E.K, E.N, (rem / tiles_n) * 32, (rem % tiles_n) * 32, t);
}

// ---------------- int8 weight prep ----------------
__global__ void colmax_kernel(const float* __restrict__ W, float* __restrict__ sb,
                              int K, int N) {
    int l = blockIdx.y, n = blockIdx.x * 256 + threadIdx.x;
    const float* Wl = W + (size_t)l * K * N;
    float m = 0.f;
    for (int k = 0; k < K; k++) m = fmaxf(m, fabsf(Wl[(size_t)k * N + n]));
    sb[(size_t)l * N + n] = m > 0.f ? m / 127.f : 0.f;
}

__global__ void wsplit_s8(const float* __restrict__ W,
                          unsigned* __restrict__ T1, unsigned* __restrict__ T2,
                          const float* __restrict__ sb, int K, int N) {
    int l = blockIdx.z;
    const float* Wl = W + (size_t)l * K * N;
    unsigned* T1l = T1 + (size_t)l * N * (K >> 2);
    unsigned* T2l = T2 + (size_t)l * N * (K >> 2);
    const float* sbl = sb + (size_t)l * N;
    __shared__ float t[32][33];
    int k0 = blockIdx.y * 32, n0 = blockIdx.x * 32;
    int tx = threadIdx.x, ty = threadIdx.y;
    #pragma unroll
    for (int i = 0; i < 4; i++)
        t[ty + i * 8][tx] = Wl[(size_t)(k0 + ty + i * 8) * N + n0 + tx];
    __syncthreads();
    int tid = ty * 32 + tx;
    int n = tid >> 3, w = tid & 7;
    float s = sbl[n0 + n];
    float invs = s > 0.f ? 1.f / s : 0.f;
    int c1[4], c2[4];
    #pragma unroll
    for (int b = 0; b < 4; b++) quant2(t[w * 4 + b][n], invs, c1[b], c2[b]);
    size_t o = (size_t)(n0 + n) * (K >> 2) + (k0 >> 2) + w;
    T1l[o] = pack4(c1[0], c1[1], c1[2], c1[3]);
    T2l[o] = pack4(c2[0], c2[1], c2[2], c2[3]);
}

// ---------------- embedding ----------------
__global__ void embed_kernel(const int* __restrict__ x, const float* __restrict__ emb,
                             const float* __restrict__ pos, float* __restrict__ H,
                             unsigned* __restrict__ Hh, unsigned* __restrict__ Hl) {
    int row = blockIdx.x, s = row & (SS - 1), tok = x[row];
    const float4* e4 = (const float4*)(emb + (size_t)tok * EE);
    const float4* p4 = (const float4*)(pos + (size_t)s * EE);
    int t = threadIdx.x;
    float4 a = e4[t], b = p4[t];
    float4 o = make_float4(a.x + b.x, a.y + b.y, a.z + b.z, a.w + b.w);
    ((float4*)(H + (size_t)row * EE))[t] = o;
    unsigned h0, l0, h1, l1;
    split2(o.x, o.y, h0, l0);
    split2(o.z, o.w, h1, l1);
    size_t wo = (size_t)row * (EE / 2) + 2 * t;
    Hh[wo] = h0; Hh[wo + 1] = h1;
    Hl[wo] = l0; Hl[wo + 1] = l1;
}

// ---------------- bf16x2 split GEMM (R7 ordering) ----------------
template<int BM, int BN, int WM, int WN, int EPI, bool WF32, bool WPACK, bool BATCHB>
__global__ void __launch_bounds__((BM/WM)*(BN/WN)*32)
gemm_pk(int M, int N, int K,
        const unsigned* __restrict__ Ah, const unsigned* __restrict__ Al,
        const unsigned* __restrict__ Bh, const unsigned* __restrict__ Bl,
        const float* __restrict__ bias, const float* __restrict__ res,
        float* __restrict__ C, unsigned* __restrict__ Ch, unsigned* __restrict__ Cl)
{
    constexpr int WARPS_N = BN / WN;
    constexpr int NTH = (BM / WM) * WARPS_N * 32;
    constexpr int LDW = 20;
    constexpr int ASZ = BM * LDW, BSZ = BN * LDW;
    constexpr int MT = WM / 16, NT = WN / 8;
    constexpr int A_CNT = BM * 4 / NTH, B_CNT = BN * 4 / NTH;

    extern __shared__ unsigned smw[];
    unsigned* Ash = smw;
    unsigned* Asl = smw + 3 * ASZ;
    unsigned* Bsh = smw + 6 * ASZ;
    unsigned* Bsl = smw + 6 * ASZ + 3 * BSZ;

    const int tid = threadIdx.x, lane = tid & 31, warp = tid >> 5;
    const int wm = warp / WARPS_N, wn = warp % WARPS_N;
    const int lr = lane >> 2, lc = lane & 3;
    const int row0 = blockIdx.y * BM, col0 = blockIdx.x * BN;
    const int KW = K >> 1, KT = K / 32;

    const unsigned* Bhp = Bh;
    const unsigned* Blp = Bl;
    if (BATCHB) {
        size_t boff = (size_t)(blockIdx.y / (SS / BM)) * N * KW;
        Bhp += boff; Blp += boff;
    }

    float acc[MT][NT][4];
    #pragma unroll
    for (int i = 0; i < MT; i++)
        #pragma unroll
        for (int j = 0; j < NT; j++)
            #pragma unroll
            for (int q = 0; q < 4; q++) acc[i][j][q] = 0.f;

    auto issue = [&](int kt, int st) {
        int goff = kt * 16;
        #pragma unroll
        for (int i = 0; i < A_CNT; i++) {
            int idx = tid + i * NTH;
            int r = idx >> 2, c = (idx & 3) * 4;
            size_t g = (size_t)(row0 + r) * KW + goff + c;
            cp_async16(Ash + st * ASZ + r * LDW + c, Ah + g);
            cp_async16(Asl + st * ASZ + r * LDW + c, Al + g);
        }
        #pragma unroll
        for (int i = 0; i < B_CNT; i++) {
            int idx = tid + i * NTH;
            int r = idx >> 2, c = (idx & 3) * 4;
            size_t g = (size_t)(col0 + r) * KW + goff + c;
            cp_async16(Bsh + st * BSZ + r * LDW + c, Bhp + g);
            cp_async16(Bsl + st * BSZ + r * LDW + c, Blp + g);
        }
    };

    auto compute = [&](int st) {
        const unsigned* Ah_ = Ash + st * ASZ;
        const unsigned* Al_ = Asl + st * ASZ;
        const unsigned* Bh_ = Bsh + st * BSZ;
        const unsigned* Bl_ = Bsl + st * BSZ;
        #pragma unroll
        for (int kk = 0; kk < 2; kk++) {
            unsigned ah[MT][4], al[MT][4];
            #pragma unroll
            for (int i = 0; i < MT; i++) {
                int base = (wm * WM + i * 16 + lr) * LDW + kk * 8 + lc;
                ah[i][0] = Ah_[base];               al[i][0] = Al_[base];
                ah[i][1] = Ah_[base + 8 * LDW];     al[i][1] = Al_[base + 8 * LDW];
                ah[i][2] = Ah_[base + 4];           al[i][2] = Al_[base + 4];
                ah[i][3] = Ah_[base + 8 * LDW + 4]; al[i][3] = Al_[base + 8 * LDW + 4];
            }
            #pragma unroll
            for (int j = 0; j < NT; j++) {
                int bbase = (wn * WN + j * 8 + lr) * LDW + kk * 8 + lc;
                unsigned bh[2], bl[2];
                bh[0] = Bh_[bbase];     bl[0] = Bl_[bbase];
                bh[1] = Bh_[bbase + 4]; bl[1] = Bl_[bbase + 4];
                #pragma unroll
                for (int i = 0; i < MT; i++) {
                    mma_bf16(acc[i][j], ah[i], bh);
                    mma_bf16(acc[i][j], ah[i], bl);
                    mma_bf16(acc[i][j], al[i], bh);
                }
            }
        }
    };

    issue(0, 0); cp_commit();
    issue(1, 1); cp_commit();
    cp_wait<1>();
    __syncthreads();
    for (int kt = 0; kt < KT; kt++) {
        if (kt + 2 < KT) issue(kt + 2, (kt + 2) % 3);
        cp_commit();
        compute(kt % 3);
        cp_wait<1>();
        __syncthreads();
    }

    auto epi = [&](float v, int rr, int cc) -> float {
        if (EPI == EPI_PHI)  return v > 0.f ? v + 1.f : expf(v);
        if (EPI == EPI_GELU) return gelu_f(v + bias[cc]);
        if (EPI == EPI_RES)  return v + bias[cc] + res[(size_t)rr * N + cc];
        if (EPI == EPI_DIV)  return v * bias[rr];
        return v;
    };

    #pragma unroll
    for (int i = 0; i < MT; i++) {
        #pragma unroll
        for (int j = 0; j < NT; j++) {
            int rr = row0 + wm * WM + i * 16 + lr;
            int cc = col0 + wn * WN + j * 8 + 2 * lc;
            float e00 = epi(acc[i][j][0], rr, cc);
            float e01 = epi(acc[i][j][1], rr, cc + 1);
            float e10 = epi(acc[i][j][2], rr + 8, cc);
            float e11 = epi(acc[i][j][3], rr + 8, cc + 1);
            if (WF32) {
                *(float2*)(C + (size_t)rr * N + cc)       = make_float2(e00, e01);
                *(float2*)(C + (size_t)(rr + 8) * N + cc) = make_float2(e10, e11);
            }
            if (WPACK) {
                unsigned h, l;
                split2(e00, e01, h, l);
                size_t w0 = (size_t)rr * (N >> 1) + (cc >> 1);
                Ch[w0] = h; Cl[w0] = l;
                split2(e10, e11, h, l);
                size_t w1 = (size_t)(rr + 8) * (N >> 1) + (cc >> 1);
                Ch[w1] = h; Cl[w1] = l;
            }
        }
    }
}

// ---------------- int8 2-chunk GEMM (W1 / W2) ----------------
// A: int8 2-chunk [M][K/4] words, per-row scale saA; B: [N][K/4], per-col scale sbB.
// 128x256 tile, 512 threads (WM=64, WN=32). BK=64 (2 k32 steps), 3-stage cp.async.
template<int EPI>
__global__ void __launch_bounds__(512)
gemm_s8(int M, int N, int K,
        const unsigned* __restrict__ A1, const unsigned* __restrict__ A2,
        const unsigned* __restrict__ B1, const unsigned* __restrict__ B2,
        const float* __restrict__ saA, const float* __restrict__ sbB,
        const float* __restrict__ bias, const float* __restrict__ res,
        float* __restrict__ C, unsigned* __restrict__ Ch, unsigned* __restrict__ Cl)
{
    constexpr int LDW = 20;
    constexpr int ASZ = 128 * LDW, BSZ = 256 * LDW;
    constexpr int MT = 4, NT = 4;          // WM=64 WN=32, 2x8 warps

    extern __shared__ unsigned smw[];
    unsigned* As1 = smw;
    unsigned* As2 = smw + 3 * ASZ;
    unsigned* Bs1 = smw + 6 * ASZ;
    unsigned* Bs2 = smw + 6 * ASZ + 3 * BSZ;

    const int tid = threadIdx.x, lane = tid & 31, warp = tid >> 5;
    const int wm = warp >> 3, wn = warp & 7;
    const int lr = lane >> 2, lc = lane & 3;
    const int row0 = blockIdx.y * 128, col0 = blockIdx.x * 256;
    const int KW4 = K >> 2, KT = K / 64;

    int p1[MT][NT][4], p2[MT][NT][4];
    #pragma unroll
    for (int i = 0; i < MT; i++)
        #pragma unroll
        for (int j = 0; j < NT; j++)
            #pragma unroll
            for (int q = 0; q < 4; q++) { p1[i][j][q] = 0; p2[i][j][q] = 0; }

    auto issue = [&](int kt, int st) {
        int goff = kt * 16;
        {   // A: 128 rows x 16 words = 512 chunks, 512 threads -> 1 each
            int r = tid >> 2, c = (tid & 3) * 4;
            size_t g = (size_t)(row0 + r) * KW4 + goff + c;
            cp_async16(As1 + st * ASZ + r * LDW + c, A1 + g);
            cp_async16(As2 + st * ASZ + r * LDW + c, A2 + g);
        }
        #pragma unroll
        for (int i = 0; i < 2; i++) {     // B: 256 rows -> 1024 chunks
            int idx = tid + i * 512;
            int r = idx >> 2, c = (idx & 3) * 4;
            size_t g = (size_t)(col0 + r) * KW4 + goff + c;
            cp_async16(Bs1 + st * BSZ + r * LDW + c, B1 + g);
            cp_async16(Bs2 + st * BSZ + r * LDW + c, B2 + g);
        }
    };

    auto compute = [&](int st) {
        const unsigned* A1_ = As1 + st * ASZ;
        const unsigned* A2_ = As2 + st * ASZ;
        const unsigned* B1_ = Bs1 + st * BSZ;
        const unsigned* B2_ = Bs2 + st * BSZ;
        #pragma unroll
        for (int kk = 0; kk < 2; kk++) {
            unsigned a1[MT][4], a2[MT][4];
            #pragma unroll
            for (int i = 0; i < MT; i++) {
                int base = (wm * 64 + i * 16 + lr) * LDW + kk * 8 + lc;
                a1[i][0] = A1_[base];               a2[i][0] = A2_[base];
                a1[i][1] = A1_[base + 8 * LDW];     a2[i][1] = A2_[base + 8 * LDW];
                a1[i][2] = A1_[base + 4];           a2[i][2] = A2_[base + 4];
                a1[i][3] = A1_[base + 8 * LDW + 4]; a2[i][3] = A2_[base + 8 * LDW + 4];
            }
            #pragma unroll
            for (int j = 0; j < NT; j++) {
                int bbase = (wn * 32 + j * 8 + lr) * LDW + kk * 8 + lc;
                unsigned b1[2], b2[2];
                b1[0] = B1_[bbase];     b2[0] = B2_[bbase];
                b1[1] = B1_[bbase + 4]; b2[1] = B2_[bbase + 4];
                #pragma unroll
                for (int i = 0; i < MT; i++) {
                    mma_s8(p1[i][j], a1[i], b1);
                    mma_s8(p2[i][j], a1[i], b2);
                    mma_s8(p2[i][j], a2[i], b1);
                }
            }
        }
    };

    issue(0, 0); cp_commit();
    issue(1, 1); cp_commit();
    cp_wait<1>();
    __syncthreads();
    for (int kt = 0; kt < KT; kt++) {
        if (kt + 2 < KT) issue(kt + 2, (kt + 2) % 3);
        cp_commit();
        compute(kt % 3);
        cp_wait<1>();
        __syncthreads();
    }

    const float c256 = 1.f / 256.f;
    #pragma unroll
    for (int i = 0; i < MT; i++) {
        int rr = row0 + wm * 64 + i * 16 + lr;
        float sa0 = saA[rr], sa1 = saA[rr + 8];
        #pragma unroll
        for (int j = 0; j < NT; j++) {
            int cc = col0 + wn * 32 + j * 8 + 2 * lc;
            float sb0 = sbB[cc], sb1 = sbB[cc + 1];
            float v00 = ((float)p1[i][j][0] + (float)p2[i][j][0] * c256) * sa0 * sb0;
            float v01 = ((float)p1[i][j][1] + (float)p2[i][j][1] * c256) * sa0 * sb1;
            float v10 = ((float)p1[i][j][2] + (float)p2[i][j][2] * c256) * sa1 * sb0;
            float v11 = ((float)p1[i][j][3] + (float)p2[i][j][3] * c256) * sa1 * sb1;
            if (EPI == EPI_GELU) {
                v00 = gelu_f(v00 + bias[cc]);
                v01 = gelu_f(v01 + bias[cc + 1]);
                v10 = gelu_f(v10 + bias[cc]);
                v11 = gelu_f(v11 + bias[cc + 1]);
                *(float2*)(C + (size_t)rr * N + cc)       = make_float2(v00, v01);
                *(float2*)(C + (size_t)(rr + 8) * N + cc) = make_float2(v10, v11);
            } else {   // EPI_RES: + bias + residual, fp32 + bf16 pack
                v00 += bias[cc]     + res[(size_t)rr * N + cc];
                v01 += bias[cc + 1] + res[(size_t)rr * N + cc + 1];
                v10 += bias[cc]     + res[(size_t)(rr + 8) * N + cc];
                v11 += bias[cc + 1] + res[(size_t)(rr + 8) * N + cc + 1];
                *(float2*)(C + (size_t)rr * N + cc)       = make_float2(v00, v01);
                *(float2*)(C + (size_t)(rr + 8) * N + cc) = make_float2(v10, v11);
                unsigned h, l;
                split2(v00, v01, h, l);
                size_t w0 = (size_t)rr * (N >> 1) + (cc >> 1);
                Ch[w0] = h; Cl[w0] = l;
                split2(v10, v11, h, l);
                size_t w1 = (size_t)(rr + 8) * (N >> 1) + (cc >> 1);
                Ch[w1] = h; Cl[w1] = l;
            }
        }
    }
}

// ---------------- kv / z / den / num helpers ----------------
__global__ void __launch_bounds__(256)
kv_kernel(const float* __restrict__ Kp, const float* __restrict__ V,
          float* __restrict__ KVp)
{
    int b = blockIdx.y, f0 = blockIdx.x * 64, sp = blockIdx.z;
    const float* Kb = Kp + (size_t)b * SS * PP;
    const float* Vb = V  + (size_t)b * SS * EE;
    __shared__ float Ks[32 * 64];
    __shared__ float Vs[32 * 64];
    int tid = threadIdx.x, tx = tid % 16, ty = tid / 16;
    float acc[4][4];
    #pragma unroll
    for (int i = 0; i < 4; i++)
        #pragma unroll
        for (int j = 0; j < 4; j++) acc[i][j] = 0.f;
    int sbeg = sp * (SS / NSPLIT), send = sbeg + (SS / NSPLIT);
    for (int s0 = sbeg; s0 < send; s0 += 32) {
        #pragma unroll
        for (int i = 0; i < 2; i++) {
            int idx = tid + i * 256;
            int r = idx / 16, c4 = idx % 16;
            *(float4*)(Ks + r * 64 + c4 * 4) =
                *(const float4*)(Kb + (size_t)(s0 + r) * PP + c4 * 4);
            *(float4*)(Vs + r * 64 + c4 * 4) =
                *(const float4*)(Vb + (size_t)(s0 + r) * EE + f0 + c4 * 4);
        }
        __syncthreads();
        #pragma unroll
        for (int k = 0; k < 32; k++) {
            float rp[4], rv[4];
            #pragma unroll
            for (int i = 0; i < 4; i++) rp[i] = Ks[k * 64 + ty * 4 + i];
            #pragma unroll
            for (int j = 0; j < 4; j++) rv[j] = Vs[k * 64 + tx * 4 + j];
            #pragma unroll
            for (int i = 0; i < 4; i++)
                #pragma unroll
                for (int j = 0; j < 4; j++)
                    acc[i][j] = fmaf(rp[i], rv[j], acc[i][j]);
        }
        __syncthreads();
    }
    float* out = KVp + (size_t)sp * BB * PP * EE;
    #pragma unroll
    for (int i = 0; i < 4; i++)
        #pragma unroll
        for (int j = 0; j < 4; j++)
            out[((size_t)b * PP + ty * 4 + i) * EE + f0 + tx * 4 + j] = acc[i][j];
}

__global__ void reduce_kv(const float* __restrict__ KVp, float* __restrict__ KV) {
    size_t idx = (size_t)blockIdx.x * 256 + threadIdx.x;
    float s = 0.f;
    #pragma unroll
    for (int sp = 0; sp < NSPLIT; sp++) s += KVp[(size_t)sp * BB * PP * EE + idx];
    KV[idx] = s;
}

__global__ void z_kernel(const float* __restrict__ Kp, float* __restrict__ Zp) {
    int b = blockIdx.x, sp = blockIdx.y;
    int tid = threadIdx.x, p = tid & 63, g = tid >> 6;
    const float* Kb = Kp + (size_t)b * SS * PP;
    float acc = 0.f;
    int sbeg = sp * (SS / NSPLIT), send = sbeg + (SS / NSPLIT);
    for (int s = sbeg + g; s < send; s += 4) acc += Kb[(size_t)s * PP + p];
    __shared__ float smem[256];
    smem[tid] = acc;
    __syncthreads();
    if (g == 0)
        Zp[(size_t)sp * BB * PP + b * PP + p] =
            smem[p] + smem[64 + p] + smem[128 + p] + smem[192 + p];
}

__global__ void reduce_z(const float* __restrict__ Zp, float* __restrict__ Z) {
    int idx = blockIdx.x * 256 + threadIdx.x;
    if (idx < BB * PP) {
        float s = 0.f;
        #pragma unroll
        for (int sp = 0; sp < NSPLIT; sp++) s += Zp[sp * BB * PP + idx];
        Z[idx] = s;
    }
}

__global__ void den_kernel(const float* __restrict__ Q, const float* __restrict__ Z,
                           float* __restrict__ inv) {
    int row = blockIdx.x * 8 + (threadIdx.x >> 5);
    int lane = threadIdx.x & 31;
    int b = row >> 12;
    const float* q = Q + (size_t)row * PP;
    const float* z = Z + b * PP;
    float s = q[lane] * z[lane] + q[lane + 32] * z[lane + 32];
    #pragma unroll
    for (int o = 16; o; o >>= 1) s += __shfl_xor_sync(0xffffffffu, s, o);
    if (lane == 0) inv[row] = 1.f / (s + 1e-6f);
}

// ---------------- layernorm: fp32 in -> int8 2-chunk + row scale ----------------
__global__ void ln_kernel(const float* __restrict__ X,
                          const float* __restrict__ gam, const float* __restrict__ bet,
                          unsigned* __restrict__ O1, unsigned* __restrict__ O2,
                          float* __restrict__ saOut) {
    int row = blockIdx.x;
    const float* xr = X + (size_t)row * EE;
    int tid = threadIdx.x;                 // 128
    float4 v = ((const float4*)xr)[tid];
    float s = v.x + v.y + v.z + v.w;
    float q = v.x * v.x + v.y * v.y + v.z * v.z + v.w * v.w;
    #pragma unroll
    for (int o = 16; o; o >>= 1) {
        s += __shfl_xor_sync(0xffffffffu, s, o);
        q += __shfl_xor_sync(0xffffffffu, q, o);
    }
    __shared__ float ss[4], qq[4], mm[4];
    int w = tid >> 5;
    if ((tid & 31) == 0) { ss[w] = s; qq[w] = q; }
    __syncthreads();
    s = ss[0] + ss[1] + ss[2] + ss[3];
    q = qq[0] + qq[1] + qq[2] + qq[3];
    float mu = s * (1.f / EE);
    float var = q * (1.f / EE) - mu * mu;
    float inv = rsqrtf(var + 1e-5f);
    float4 g4 = ((const float4*)gam)[tid];
    float4 b4 = ((const float4*)bet)[tid];
    float o0 = (v.x - mu) * inv * g4.x + b4.x;
    float o1 = (v.y - mu) * inv * g4.y + b4.y;
    float o2 = (v.z - mu) * inv * g4.z + b4.z;
    float o3 = (v.w - mu) * inv * g4.w + b4.w;
    float am = fmaxf(fmaxf(fabsf(o0), fabsf(o1)), fmaxf(fabsf(o2), fabsf(o3)));
    #pragma unroll
    for (int o = 16; o; o >>= 1) am = fmaxf(am, __shfl_xor_sync(0xffffffffu, am, o));
    if ((tid & 31) == 0) mm[w] = am;
    __syncthreads();
    am = fmaxf(fmaxf(mm[0], mm[1]), fmaxf(mm[2], mm[3]));
    float sa = am > 0.f ? am / 127.f : 0.f;
    float invs = am > 0.f ? 127.f / am : 0.f;
    int c1[4], c2[4];
    quant2(o0, invs, c1[0], c2[0]);
    quant2(o1, invs, c1[1], c2[1]);
    quant2(o2, invs, c1[2], c2[2]);
    quant2(o3, invs, c1[3], c2[3]);
    size_t wo = (size_t)row * (EE / 4) + tid;
    O1[wo] = pack4(c1[0], c1[1], c1[2], c1[3]);
    O2[wo] = pack4(c2[0], c2[1], c2[2], c2[3]);
    if (tid == 0) saOut[row] = sa;
}

// ---------------- Mb fp32 -> int8 2-chunk + row scale (row = FF) ----------------
__global__ void quant_row_kernel(const float* __restrict__ X,
                                 unsigned* __restrict__ O1, unsigned* __restrict__ O2,
                                 float* __restrict__ saOut) {
    int row = blockIdx.x;
    const float* xr = X + (size_t)row * FF;
    int tid = threadIdx.x;                 // 256, 8 elems each
    float e[8];
    float4 v0 = ((const float4*)xr)[2 * tid];
    float4 v1 = ((const float4*)xr)[2 * tid + 1];
    e[0] = v0.x; e[1] = v0.y; e[2] = v0.z; e[3] = v0.w;
    e[4] = v1.x; e[5] = v1.y; e[6] = v1.z; e[7] = v1.w;
    float am = 0.f;
    #pragma unroll
    for (int i = 0; i < 8; i++) am = fmaxf(am, fabsf(e[i]));
    #pragma unroll
    for (int o = 16; o; o >>= 1) am = fmaxf(am, __shfl_xor_sync(0xffffffffu, am, o));
    __shared__ float mm[8];
    int w = tid >> 5;
    if ((tid & 31) == 0) mm[w] = am;
    __syncthreads();
    am = mm[0];
    #pragma unroll
    for (int i = 1; i < 8; i++) am = fmaxf(am, mm[i]);
    float sa = am > 0.f ? am / 127.f : 0.f;
    float invs = am > 0.f ? 127.f / am : 0.f;
    int c1[8], c2[8];
    #pragma unroll
    for (int i = 0; i < 8; i++) quant2(e[i], invs, c1[i], c2[i]);
    size_t wo = (size_t)row * (FF / 4) + 2 * tid;
    O1[wo]     = pack4(c1[0], c1[1], c1[2], c1[3]);
    O1[wo + 1] = pack4(c1[4], c1[5], c1[6], c1[7]);
    O2[wo]     = pack4(c2[0], c2[1], c2[2], c2[3]);
    O2[wo + 1] = pack4(c2[4], c2[5], c2[6], c2[7]);
    if (tid == 0) saOut[row] = sa;
}

// ---------------- head ----------------
__global__ void head_kernel(const float* __restrict__ Hm, const float* __restrict__ Wh1,
                            const float* __restrict__ bh1, const float* __restrict__ Wh2,
                            const float* __restrict__ bh2, float* __restrict__ out) {
    int b = blockIdx.x, tid = threadIdx.x;
    const float* hr = Hm + (size_t)b * SS * EE;
    float acc = bh1[tid];
    for (int e = 0; e < EE; e++) acc = fmaf(hr[e], Wh1[e * HH + tid], acc);
    acc = fmaxf(acc, 0.f);
    __shared__ float hid[HH];
    hid[tid] = acc;
    __syncthreads();
    if (tid < CC) {
        float a = bh2[tid];
        for (int h = 0; h < HH; h++) a = fmaf(hid[h], Wh2[h * CC + tid], a);
        out[b * CC + tid] = a;
    }
}

// ---------------- launch ----------------
static size_t gemm_smem(int BM, int BN) {
    return (size_t)(3 * (BM * 20 * 2 + BN * 20 * 2)) * 4;
}

extern "C" void kernel_launch(void* const* d_in, const int* in_sizes, int n_in,
                              void* d_out, int out_size) {
    const int*   x    = (const int*)  d_in[0];
    const float* emb  = (const float*)d_in[1];
    const float* pos  = (const float*)d_in[2];
    const float* Wq   = (const float*)d_in[3];
    const float* Wk   = (const float*)d_in[4];
    const float* Wv   = (const float*)d_in[5];
    const float* Wo   = (const float*)d_in[6];
    const float* ln_g = (const float*)d_in[7];
    const float* ln_b = (const float*)d_in[8];
    const float* W1   = (const float*)d_in[9];
    const float* b1   = (const float*)d_in[10];
    const float* W2   = (const float*)d_in[11];
    const float* b2   = (const float*)d_in[12];
    const float* Wh1  = (const float*)d_in[13];
    const float* bh1  = (const float*)d_in[14];
    const float* Wh2  = (const float*)d_in[15];
    const float* bh2  = (const float*)d_in[16];
    float* out = (float*)d_out;

    float *H, *A, *V, *Mb, *Q, *Kq, *KV, *KVp, *Z, *Zp, *DEN, *saLN, *saMb, *sbW1, *sbW2;
    cudaGetSymbolAddress((void**)&H,    g_H);
    cudaGetSymbolAddress((void**)&A,    g_A);
    cudaGetSymbolAddress((void**)&V,    g_V);
    cudaGetSymbolAddress((void**)&Mb,   g_Mb);
    cudaGetSymbolAddress((void**)&Q,    g_Q);
    cudaGetSymbolAddress((void**)&Kq,   g_K);
    cudaGetSymbolAddress((void**)&KV,   g_KV);
    cudaGetSymbolAddress((void**)&KVp,  g_KVp);
    cudaGetSymbolAddress((void**)&Z,    g_Z);
    cudaGetSymbolAddress((void**)&Zp,   g_Zp);
    cudaGetSymbolAddress((void**)&DEN,  g_DEN);
    cudaGetSymbolAddress((void**)&saLN, g_saLN);
    cudaGetSymbolAddress((void**)&saMb, g_saMb);
    cudaGetSymbolAddress((void**)&sbW1, g_sbW1);
    cudaGetSymbolAddress((void**)&sbW2, g_sbW2);

    unsigned *Hh, *Hl, *NMh, *NMl, *Qh, *Ql, *KVTh, *KVTl;
    unsigned *LN1, *LN2, *Mb1, *Mb2, *W1s1, *W1s2, *W2s1, *W2s2;
    cudaGetSymbolAddress((void**)&Hh,   g_Hh);   cudaGetSymbolAddress((void**)&Hl,   g_Hl);
    cudaGetSymbolAddress((void**)&NMh,  g_NMh);  cudaGetSymbolAddress((void**)&NMl,  g_NMl);
    cudaGetSymbolAddress((void**)&Qh,   g_Qh);   cudaGetSymbolAddress((void**)&Ql,   g_Ql);
    cudaGetSymbolAddress((void**)&KVTh, g_KVTh); cudaGetSymbolAddress((void**)&KVTl, g_KVTl);
    cudaGetSymbolAddress((void**)&LN1,  g_LN1);  cudaGetSymbolAddress((void**)&LN2,  g_LN2);
    cudaGetSymbolAddress((void**)&Mb1,  g_Mb1);  cudaGetSymbolAddress((void**)&Mb2,  g_Mb2);
    cudaGetSymbolAddress((void**)&W1s1, g_W1s1); cudaGetSymbolAddress((void**)&W1s2, g_W1s2);
    cudaGetSymbolAddress((void**)&W2s1, g_W2s1); cudaGetSymbolAddress((void**)&W2s2, g_W2s2);

    unsigned *Wqh, *Wql, *Wkh, *Wkl, *Wvh, *Wvl, *Woh, *Wol;
    cudaGetSymbolAddress((void**)&Wqh, g_Wqh); cudaGetSymbolAddress((void**)&Wql, g_Wql_);
    cudaGetSymbolAddress((void**)&Wkh, g_Wkh); cudaGetSymbolAddress((void**)&Wkl, g_Wkl_);
    cudaGetSymbolAddress((void**)&Wvh, g_Wvh); cudaGetSymbolAddress((void**)&Wvl, g_Wvl_);
    cudaGetSymbolAddress((void**)&Woh, g_Woh); cudaGetSymbolAddress((void**)&Wol, g_Wol_);

    const size_t smQK  = gemm_smem(128, 64);
    const size_t smBIG = gemm_smem(128, 256);
    cudaFuncSetAttribute(gemm_pk<128, 64, 32, 32, EPI_PHI, true, true, false>,
                         cudaFuncAttributeMaxDynamicSharedMemorySize, (int)smQK);
    cudaFuncSetAttribute(gemm_pk<128, 64, 32, 32, EPI_PHI, true, false, false>,
                         cudaFuncAttributeMaxDynamicSharedMemorySize, (int)smQK);
    cudaFuncSetAttribute(gemm_pk<128, 256, 64, 32, EPI_NONE, true, false, false>,
                         cudaFuncAttributeMaxDynamicSharedMemorySize, (int)smBIG);
    cudaFuncSetAttribute(gemm_pk<128, 256, 64, 32, EPI_DIV, false, true, true>,
                         cudaFuncAttributeMaxDynamicSharedMemorySize, (int)smBIG);
    cudaFuncSetAttribute(gemm_s8<EPI_GELU>,
                         cudaFuncAttributeMaxDynamicSharedMemorySize, (int)smBIG);
    cudaFuncSetAttribute(gemm_s8<EPI_RES>,
                         cudaFuncAttributeMaxDynamicSharedMemorySize, (int)smBIG);

    // one-time weight prep
    dim3 wt(32, 8);
    {
        WSPack pA;
        pA.e[0] = { Wq, Wqh, Wql, EE, PP, LL * (EE / 32) * (PP / 32) };
        pA.e[1] = { Wk, Wkh, Wkl, EE, PP, LL * (EE / 32) * (PP / 32) };
        pA.e[2] = { Wv, Wvh, Wvl, EE, EE, LL * (EE / 32) * (EE / 32) };
        pA.e[3] = { Wo, Woh, Wol, EE, EE, LL * (EE / 32) * (EE / 32) };
        pA.cnt = 4;
        int nA = pA.e[0].nblk + pA.e[1].nblk + pA.e[2].nblk + pA.e[3].nblk;
        wsplit_multi<<<nA, wt>>>(pA);
    }
    colmax_kernel<<<dim3(FF / 256, LL), 256>>>(W1, sbW1, EE, FF);
    colmax_kernel<<<dim3(EE / 256, LL), 256>>>(W2, sbW2, FF, EE);
    wsplit_s8<<<dim3(FF / 32, EE / 32, LL), wt>>>(W1, W1s1, W1s2, sbW1, EE, FF);
    wsplit_s8<<<dim3(EE / 32, FF / 32, LL), wt>>>(W2, W2s1, W2s2, sbW2, FF, EE);

    embed_kernel<<<MROWS, 128>>>(x, emb, pos, H, Hh, Hl);

    for (int l = 0; l < LL; l++) {
        size_t oQK = (size_t)l * PP * (EE / 2);
        size_t oV  = (size_t)l * EE * (EE / 2);
        size_t o1  = (size_t)l * FF * (EE / 4);
        size_t o2  = (size_t)l * EE * (FF / 4);

        gemm_pk<128, 64, 32, 32, EPI_PHI, true, true, false>
            <<<dim3(PP / 64, MROWS / 128), 256, smQK>>>(
                MROWS, PP, EE, Hh, Hl, Wqh + oQK, Wql + oQK,
                nullptr, nullptr, Q, Qh, Ql);
        gemm_pk<128, 64, 32, 32, EPI_PHI, true, false, false>
            <<<dim3(PP / 64, MROWS / 128), 256, smQK>>>(
                MROWS, PP, EE, Hh, Hl, Wkh + oQK, Wkl + oQK,
                nullptr, nullptr, Kq, nullptr, nullptr);
        gemm_pk<128, 256, 64, 32, EPI_NONE, true, false, false>
            <<<dim3(EE / 256, MROWS / 128), 512, smBIG>>>(
                MROWS, EE, EE, Hh, Hl, Wvh + oV, Wvl + oV,
                nullptr, nullptr, V, nullptr, nullptr);

        kv_kernel<<<dim3(EE / 64, BB, NSPLIT), 256>>>(Kq, V, KVp);
        z_kernel<<<dim3(BB, NSPLIT), 256>>>(Kq, Zp);
        reduce_kv<<<(BB * PP * EE) / 256, 256>>>(KVp, KV);
        reduce_z<<<2, 256>>>(Zp, Z);
        wsplit_kernel<<<dim3(EE / 32, PP / 32, BB), wt>>>(KV, KVTh, KVTl, PP, EE);
        den_kernel<<<MROWS / 8, 256>>>(Q, Z, DEN);

        gemm_pk<128, 256, 64, 32, EPI_DIV, false, true, true>
            <<<dim3(EE / 256, MROWS / 128), 512, smBIG>>>(
                MROWS, EE, PP, Qh, Ql, KVTh, KVTl,
                DEN, nullptr, nullptr, NMh, NMl);

        gemm_pk<128, 256, 64, 32, EPI_NONE, true, false, false>
            <<<dim3(EE / 256, MROWS / 128), 512, smBIG>>>(
                MROWS, EE, EE, NMh, NMl, Woh + oV, Wol + oV,
                nullptr, nullptr, A, nullptr, nullptr);

        ln_kernel<<<MROWS, 128>>>(A, ln_g + (size_t)l * EE, ln_b + (size_t)l * EE,
                                  LN1, LN2, saLN);

        // W1 int8: Mb = GELU(LN @ W1 + b1), fp32 out
        gemm_s8<EPI_GELU>
            <<<dim3(FF / 256, MROWS / 128), 512, smBIG>>>(
                MROWS, FF, EE, LN1, LN2, W1s1 + o1, W1s2 + o1,
                saLN, sbW1 + (size_t)l * FF, b1 + (size_t)l * FF,
                nullptr, Mb, nullptr, nullptr);
        quant_row_kernel<<<MROWS, 256>>>(Mb, Mb1, Mb2, saMb);
        // W2 int8: H = Mb @ W2 + b2 + H, fp32 + packed bf16 out
        gemm_s8<EPI_RES>
            <<<dim3(EE / 256, MROWS / 128), 512, smBIG>>>(
                MROWS, EE, FF, Mb1, Mb2, W2s1 + o2, W2s2 + o2,
                saMb, sbW2 + (size_t)l * EE, b2 + (size_t)l * EE,
                H, H, Hh, Hl);
    }

    head_kernel<<<BB, HH>>>(H, Wh1, bh1, Wh2, bh2, out);
}

// round 11
// speedup vs baseline: 2.5148x; 2.5148x over previous
#include <cuda_runtime.h>
#include <math.h>

#define BB   8
#define SS   4096
#define EE   512
#define PP   64
#define LL   4
#define HH   256
#define CC   2
#define FF   2048
#define MROWS (BB*SS)
#define NSPLIT 8

enum { EPI_NONE = 0, EPI_PHI = 1, EPI_GELU = 2, EPI_RES = 3, EPI_DIV = 4 };

// ---------------- scratch ----------------
__device__ float g_H  [(size_t)MROWS*EE];
__device__ float g_A  [(size_t)MROWS*EE];
__device__ float g_V  [(size_t)MROWS*EE];
__device__ float g_Q  [(size_t)MROWS*PP];
__device__ float g_K  [(size_t)MROWS*PP];
__device__ float g_KV [(size_t)BB*PP*EE];
__device__ float g_KVp[(size_t)NSPLIT*BB*PP*EE];
__device__ float g_Z  [(size_t)BB*PP];
__device__ float g_Zp [(size_t)NSPLIT*BB*PP];
__device__ float g_DEN[(size_t)MROWS];
// last-layer small buffers
__device__ float g_PHI [(size_t)BB*PP];
__device__ float g_DEN8[(size_t)BB];
__device__ float g_ATT8[(size_t)BB*EE];
__device__ float g_LN8 [(size_t)BB*EE];
__device__ float g_M8  [(size_t)BB*FF];
__device__ float g_H8  [(size_t)BB*EE];

// packed bf16x2 hi/lo
__device__ unsigned g_Hh [(size_t)MROWS*(EE/2)],  g_Hl [(size_t)MROWS*(EE/2)];
__device__ unsigned g_NMh[(size_t)MROWS*(EE/2)],  g_NMl[(size_t)MROWS*(EE/2)];
__device__ unsigned g_LNh[(size_t)MROWS*(EE/2)],  g_LNl[(size_t)MROWS*(EE/2)];
__device__ unsigned g_Mbh[(size_t)MROWS*(FF/2)],  g_Mbl[(size_t)MROWS*(FF/2)];
__device__ unsigned g_Qh [(size_t)MROWS*(PP/2)],  g_Ql [(size_t)MROWS*(PP/2)];
__device__ unsigned g_KVTh[(size_t)BB*EE*(PP/2)], g_KVTl[(size_t)BB*EE*(PP/2)];
// bf16 weights [N][K/2]
__device__ unsigned g_Wqh[(size_t)LL*PP*(EE/2)],  g_Wql_[(size_t)LL*PP*(EE/2)];
__device__ unsigned g_Wkh[(size_t)LL*PP*(EE/2)],  g_Wkl_[(size_t)LL*PP*(EE/2)];
__device__ unsigned g_Wvh[(size_t)LL*EE*(EE/2)],  g_Wvl_[(size_t)LL*EE*(EE/2)];
__device__ unsigned g_Woh[(size_t)LL*EE*(EE/2)],  g_Wol_[(size_t)LL*EE*(EE/2)];
__device__ unsigned g_W1h[(size_t)LL*FF*(EE/2)],  g_W1l_[(size_t)LL*FF*(EE/2)];
__device__ unsigned g_W2h[(size_t)LL*EE*(FF/2)],  g_W2l_[(size_t)LL*EE*(FF/2)];

// ---------------- helpers ----------------
__device__ __forceinline__ void cp_async16(void* smem, const void* gmem) {
    unsigned sa = (unsigned)__cvta_generic_to_shared(smem);
    asm volatile("cp.async.cg.shared.global [%0], [%1], 16;" :: "r"(sa), "l"(gmem));
}
__device__ __forceinline__ void cp_commit() { asm volatile("cp.async.commit_group;"); }
template<int N>
__device__ __forceinline__ void cp_wait() {
    asm volatile("cp.async.wait_group %0;" :: "n"(N));
}

__device__ __forceinline__ void split2(float x, float y, unsigned& hi, unsigned& lo) {
    asm("cvt.rn.bf16x2.f32 %0, %1, %2;" : "=r"(hi) : "f"(y), "f"(x));
    float hx = __uint_as_float(hi << 16);
    float hy = __uint_as_float(hi & 0xFFFF0000u);
    asm("cvt.rn.bf16x2.f32 %0, %1, %2;" : "=r"(lo) : "f"(y - hy), "f"(x - hx));
}

__device__ __forceinline__ void mma_bf16(float c[4], const unsigned a[4], const unsigned b[2]) {
    asm volatile(
        "mma.sync.aligned.m16n8k16.row.col.f32.bf16.bf16.f32 "
        "{%0,%1,%2,%3}, {%4,%5,%6,%7}, {%8,%9}, {%0,%1,%2,%3};"
        : "+f"(c[0]), "+f"(c[1]), "+f"(c[2]), "+f"(c[3])
        : "r"(a[0]), "r"(a[1]), "r"(a[2]), "r"(a[3]), "r"(b[0]), "r"(b[1]));
}

__device__ __forceinline__ float gelu_f(float v) {
    float u = 0.7978845608028654f * (v + 0.044715f * v * v * v);
    return 0.5f * v * (1.f + tanhf(u));
}

// ---------------- transpose + split ----------------
__device__ __forceinline__ void wsplit_tile(const float* Wl, unsigned* Th, unsigned* Tl,
                                            int K, int N, int k0, int n0, float (*t)[33]) {
    int tx = threadIdx.x, ty = threadIdx.y;
    #pragma unroll
    for (int i = 0; i < 4; i++)
        t[ty + i * 8][tx] = Wl[(size_t)(k0 + ty + i * 8) * N + n0 + tx];
    __syncthreads();
    int tid = ty * 32 + tx;
    #pragma unroll
    for (int i = 0; i < 2; i++) {
        int w = tid + i * 256;
        int n = w >> 4, kp = w & 15;
        unsigned h, l;
        split2(t[2 * kp][n], t[2 * kp + 1][n], h, l);
        size_t o = (size_t)(n0 + n) * (K >> 1) + (k0 >> 1) + kp;
        Th[o] = h; Tl[o] = l;
    }
}

__global__ void wsplit_kernel(const float* __restrict__ W,
                              unsigned* __restrict__ Th, unsigned* __restrict__ Tl,
                              int K, int N) {
    __shared__ float t[32][33];
    wsplit_tile(W + (size_t)blockIdx.z * K * N,
                Th + (size_t)blockIdx.z * N * (K >> 1),
                Tl + (size_t)blockIdx.z * N * (K >> 1),
                K, N, blockIdx.y * 32, blockIdx.x * 32, t);
}

struct WSEntry { const float* W; unsigned* Th; unsigned* Tl; int K; int N; int nblk; };
struct WSPack  { WSEntry e[4]; int cnt; };
__global__ void wsplit_multi(WSPack p) {
    __shared__ float t[32][33];
    int bid = blockIdx.x, i = 0;
    while (i + 1 < p.cnt && bid >= p.e[i].nblk) { bid -= p.e[i].nblk; i++; }
    WSEntry E = p.e[i];
    int tiles_n = E.N / 32, tpl = tiles_n * (E.K / 32);
    int layer = bid / tpl, rem = bid % tpl;
    wsplit_tile(E.W + (size_t)layer * E.K * E.N,
                E.Th + (size_t)layer * E.N * (E.K >> 1),
                E.Tl + (size_t)layer * E.N * (E.K >> 1),
                E.K, E.N, (rem / tiles_n) * 32, (rem % tiles_n) * 32, t);
}

// ---------------- embedding ----------------
__global__ void embed_kernel(const int* __restrict__ x, const float* __restrict__ emb,
                             const float* __restrict__ pos, float* __restrict__ H,
                             unsigned* __restrict__ Hh, unsigned* __restrict__ Hl) {
    int row = blockIdx.x, s = row & (SS - 1), tok = x[row];
    const float4* e4 = (const float4*)(emb + (size_t)tok * EE);
    const float4* p4 = (const float4*)(pos + (size_t)s * EE);
    int t = threadIdx.x;
    float4 a = e4[t], b = p4[t];
    float4 o = make_float4(a.x + b.x, a.y + b.y, a.z + b.z, a.w + b.w);
    ((float4*)(H + (size_t)row * EE))[t] = o;
    unsigned h0, l0, h1, l1;
    split2(o.x, o.y, h0, l0);
    split2(o.z, o.w, h1, l1);
    size_t wo = (size_t)row * (EE / 2) + 2 * t;
    Hh[wo] = h0; Hh[wo + 1] = h1;
    Hl[wo] = l0; Hl[wo + 1] = l1;
}

// ---------------- bf16x2 split GEMM (best = R6 config) ----------------
template<int BM, int BN, int WM, int WN, int EPI, bool WF32, bool WPACK, bool BATCHB>
__global__ void __launch_bounds__((BM/WM)*(BN/WN)*32)
gemm_pk(int M, int N, int K,
        const unsigned* __restrict__ Ah, const unsigned* __restrict__ Al,
        const unsigned* __restrict__ Bh, const unsigned* __restrict__ Bl,
        const float* __restrict__ bias, const float* __restrict__ res,
        float* __restrict__ C, unsigned* __restrict__ Ch, unsigned* __restrict__ Cl)
{
    constexpr int WARPS_N = BN / WN;
    constexpr int NTH = (BM / WM) * WARPS_N * 32;
    constexpr int LDW = 20;
    constexpr int ASZ = BM * LDW, BSZ = BN * LDW;
    constexpr int MT = WM / 16, NT = WN / 8;
    constexpr int A_CNT = BM * 4 / NTH, B_CNT = BN * 4 / NTH;

    extern __shared__ unsigned smw[];
    unsigned* Ash = smw;
    unsigned* Asl = smw + 3 * ASZ;
    unsigned* Bsh = smw + 6 * ASZ;
    unsigned* Bsl = smw + 6 * ASZ + 3 * BSZ;

    const int tid = threadIdx.x, lane = tid & 31, warp = tid >> 5;
    const int wm = warp / WARPS_N, wn = warp % WARPS_N;
    const int lr = lane >> 2, lc = lane & 3;
    const int row0 = blockIdx.y * BM, col0 = blockIdx.x * BN;
    const int KW = K >> 1, KT = K / 32;

    const unsigned* Bhp = Bh;
    const unsigned* Blp = Bl;
    if (BATCHB) {
        size_t boff = (size_t)(blockIdx.y / (SS / BM)) * N * KW;
        Bhp += boff; Blp += boff;
    }

    float acc[MT][NT][4];
    #pragma unroll
    for (int i = 0; i < MT; i++)
        #pragma unroll
        for (int j = 0; j < NT; j++)
            #pragma unroll
            for (int q = 0; q < 4; q++) acc[i][j][q] = 0.f;

    auto issue = [&](int kt, int st) {
        int goff = kt * 16;
        #pragma unroll
        for (int i = 0; i < A_CNT; i++) {
            int idx = tid + i * NTH;
            int r = idx >> 2, c = (idx & 3) * 4;
            size_t g = (size_t)(row0 + r) * KW + goff + c;
            cp_async16(Ash + st * ASZ + r * LDW + c, Ah + g);
            cp_async16(Asl + st * ASZ + r * LDW + c, Al + g);
        }
        #pragma unroll
        for (int i = 0; i < B_CNT; i++) {
            int idx = tid + i * NTH;
            int r = idx >> 2, c = (idx & 3) * 4;
            size_t g = (size_t)(col0 + r) * KW + goff + c;
            cp_async16(Bsh + st * BSZ + r * LDW + c, Bhp + g);
            cp_async16(Bsl + st * BSZ + r * LDW + c, Blp + g);
        }
    };

    auto compute = [&](int st) {
        const unsigned* Ah_ = Ash + st * ASZ;
        const unsigned* Al_ = Asl + st * ASZ;
        const unsigned* Bh_ = Bsh + st * BSZ;
        const unsigned* Bl_ = Bsl + st * BSZ;
        #pragma unroll
        for (int kk = 0; kk < 2; kk++) {
            unsigned ah[MT][4], al[MT][4];
            #pragma unroll
            for (int i = 0; i < MT; i++) {
                int base = (wm * WM + i * 16 + lr) * LDW + kk * 8 + lc;
                ah[i][0] = Ah_[base];               al[i][0] = Al_[base];
                ah[i][1] = Ah_[base + 8 * LDW];     al[i][1] = Al_[base + 8 * LDW];
                ah[i][2] = Ah_[base + 4];           al[i][2] = Al_[base + 4];
                ah[i][3] = Ah_[base + 8 * LDW + 4]; al[i][3] = Al_[base + 8 * LDW + 4];
            }
            #pragma unroll
            for (int j = 0; j < NT; j++) {
                int bbase = (wn * WN + j * 8 + lr) * LDW + kk * 8 + lc;
                unsigned bh[2], bl[2];
                bh[0] = Bh_[bbase];     bl[0] = Bl_[bbase];
                bh[1] = Bh_[bbase + 4]; bl[1] = Bl_[bbase + 4];
                #pragma unroll
                for (int i = 0; i < MT; i++) {
                    mma_bf16(acc[i][j], ah[i], bh);
                    mma_bf16(acc[i][j], ah[i], bl);
                    mma_bf16(acc[i][j], al[i], bh);
                }
            }
        }
    };

    issue(0, 0); cp_commit();
    issue(1, 1); cp_commit();
    cp_wait<1>();
    __syncthreads();
    for (int kt = 0; kt < KT; kt++) {
        if (kt + 2 < KT) issue(kt + 2, (kt + 2) % 3);
        cp_commit();
        compute(kt % 3);
        cp_wait<1>();
        __syncthreads();
    }

    auto epi = [&](float v, int rr, int cc) -> float {
        if (EPI == EPI_PHI)  return v > 0.f ? v + 1.f : expf(v);
        if (EPI == EPI_GELU) return gelu_f(v + bias[cc]);
        if (EPI == EPI_RES)  return v + bias[cc] + res[(size_t)rr * N + cc];
        if (EPI == EPI_DIV)  return v * bias[rr];
        return v;
    };

    #pragma unroll
    for (int i = 0; i < MT; i++) {
        #pragma unroll
        for (int j = 0; j < NT; j++) {
            int rr = row0 + wm * WM + i * 16 + lr;
            int cc = col0 + wn * WN + j * 8 + 2 * lc;
            float e00 = epi(acc[i][j][0], rr, cc);
            float e01 = epi(acc[i][j][1], rr, cc + 1);
            float e10 = epi(acc[i][j][2], rr + 8, cc);
            float e11 = epi(acc[i][j][3], rr + 8, cc + 1);
            if (WF32) {
                *(float2*)(C + (size_t)rr * N + cc)       = make_float2(e00, e01);
                *(float2*)(C + (size_t)(rr + 8) * N + cc) = make_float2(e10, e11);
            }
            if (WPACK) {
                unsigned h, l;
                split2(e00, e01, h, l);
                size_t w0 = (size_t)rr * (N >> 1) + (cc >> 1);
                Ch[w0] = h; Cl[w0] = l;
                split2(e10, e11, h, l);
                size_t w1 = (size_t)(rr + 8) * (N >> 1) + (cc >> 1);
                Ch[w1] = h; Cl[w1] = l;
            }
        }
    }
}

// ---------------- kv / z / reductions ----------------
__global__ void __launch_bounds__(256)
kv_kernel(const float* __restrict__ Kp, const float* __restrict__ V,
          float* __restrict__ KVp)
{
    int b = blockIdx.y, f0 = blockIdx.x * 64, sp = blockIdx.z;
    const float* Kb = Kp + (size_t)b * SS * PP;
    const float* Vb = V  + (size_t)b * SS * EE;
    __shared__ float Ks[32 * 64];
    __shared__ float Vs[32 * 64];
    int tid = threadIdx.x, tx = tid % 16, ty = tid / 16;
    float acc[4][4];
    #pragma unroll
    for (int i = 0; i < 4; i++)
        #pragma unroll
        for (int j = 0; j < 4; j++) acc[i][j] = 0.f;
    int sbeg = sp * (SS / NSPLIT), send = sbeg + (SS / NSPLIT);
    for (int s0 = sbeg; s0 < send; s0 += 32) {
        #pragma unroll
        for (int i = 0; i < 2; i++) {
            int idx = tid + i * 256;
            int r = idx / 16, c4 = idx % 16;
            *(float4*)(Ks + r * 64 + c4 * 4) =
                *(const float4*)(Kb + (size_t)(s0 + r) * PP + c4 * 4);
            *(float4*)(Vs + r * 64 + c4 * 4) =
                *(const float4*)(Vb + (size_t)(s0 + r) * EE + f0 + c4 * 4);
        }
        __syncthreads();
        #pragma unroll
        for (int k = 0; k < 32; k++) {
            float rp[4], rv[4];
            #pragma unroll
            for (int i = 0; i < 4; i++) rp[i] = Ks[k * 64 + ty * 4 + i];
            #pragma unroll
            for (int j = 0; j < 4; j++) rv[j] = Vs[k * 64 + tx * 4 + j];
            #pragma unroll
            for (int i = 0; i < 4; i++)
                #pragma unroll
                for (int j = 0; j < 4; j++)
                    acc[i][j] = fmaf(rp[i], rv[j], acc[i][j]);
        }
        __syncthreads();
    }
    float* out = KVp + (size_t)sp * BB * PP * EE;
    #pragma unroll
    for (int i = 0; i < 4; i++)
        #pragma unroll
        for (int j = 0; j < 4; j++)
            out[((size_t)b * PP + ty * 4 + i) * EE + f0 + tx * 4 + j] = acc[i][j];
}

__global__ void reduce_kv(const float* __restrict__ KVp, float* __restrict__ KV) {
    size_t idx = (size_t)blockIdx.x * 256 + threadIdx.x;
    float s = 0.f;
    #pragma unroll
    for (int sp = 0; sp < NSPLIT; sp++) s += KVp[(size_t)sp * BB * PP * EE + idx];
    KV[idx] = s;
}

__global__ void z_kernel(const float* __restrict__ Kp, float* __restrict__ Zp) {
    int b = blockIdx.x, sp = blockIdx.y;
    int tid = threadIdx.x, p = tid & 63, g = tid >> 6;
    const float* Kb = Kp + (size_t)b * SS * PP;
    float acc = 0.f;
    int sbeg = sp * (SS / NSPLIT), send = sbeg + (SS / NSPLIT);
    for (int s = sbeg + g; s < send; s += 4) acc += Kb[(size_t)s * PP + p];
    __shared__ float smem[256];
    smem[tid] = acc;
    __syncthreads();
    if (g == 0)
        Zp[(size_t)sp * BB * PP + b * PP + p] =
            smem[p] + smem[64 + p] + smem[128 + p] + smem[192 + p];
}

__global__ void reduce_z(const float* __restrict__ Zp, float* __restrict__ Z) {
    int idx = blockIdx.x * 256 + threadIdx.x;
    if (idx < BB * PP) {
        float s = 0.f;
        #pragma unroll
        for (int sp = 0; sp < NSPLIT; sp++) s += Zp[sp * BB * PP + idx];
        Z[idx] = s;
    }
}

__global__ void den_kernel(const float* __restrict__ Q, const float* __restrict__ Z,
                           float* __restrict__ inv) {
    int row = blockIdx.x * 8 + (threadIdx.x >> 5);
    int lane = threadIdx.x & 31;
    int b = row >> 12;
    const float* q = Q + (size_t)row * PP;
    const float* z = Z + b * PP;
    float s = q[lane] * z[lane] + q[lane + 32] * z[lane + 32];
    #pragma unroll
    for (int o = 16; o; o >>= 1) s += __shfl_xor_sync(0xffffffffu, s, o);
    if (lane == 0) inv[row] = 1.f / (s + 1e-6f);
}

// ---------------- layernorm: fp32 in -> packed out ----------------
__global__ void ln_kernel(const float* __restrict__ X,
                          const float* __restrict__ gam, const float* __restrict__ bet,
                          unsigned* __restrict__ Oh, unsigned* __restrict__ Ol) {
    int row = blockIdx.x;
    const float* xr = X + (size_t)row * EE;
    int tid = threadIdx.x;
    float4 v = ((const float4*)xr)[tid];
    float s = v.x + v.y + v.z + v.w;
    float q = v.x * v.x + v.y * v.y + v.z * v.z + v.w * v.w;
    #pragma unroll
    for (int o = 16; o; o >>= 1) {
        s += __shfl_xor_sync(0xffffffffu, s, o);
        q += __shfl_xor_sync(0xffffffffu, q, o);
    }
    __shared__ float ss[4], qq[4];
    int w = tid >> 5;
    if ((tid & 31) == 0) { ss[w] = s; qq[w] = q; }
    __syncthreads();
    s = ss[0] + ss[1] + ss[2] + ss[3];
    q = qq[0] + qq[1] + qq[2] + qq[3];
    float mu = s * (1.f / EE);
    float var = q * (1.f / EE) - mu * mu;
    float inv = rsqrtf(var + 1e-5f);
    float4 g4 = ((const float4*)gam)[tid];
    float4 b4 = ((const float4*)bet)[tid];
    float o0 = (v.x - mu) * inv * g4.x + b4.x;
    float o1 = (v.y - mu) * inv * g4.y + b4.y;
    float o2 = (v.z - mu) * inv * g4.z + b4.z;
    float o3 = (v.w - mu) * inv * g4.w + b4.w;
    unsigned h0, l0, h1, l1;
    split2(o0, o1, h0, l0);
    split2(o2, o3, h1, l1);
    size_t wo = (size_t)row * (EE / 2) + 2 * tid;
    Oh[wo] = h0; Oh[wo + 1] = h1;
    Ol[wo] = l0; Ol[wo + 1] = l1;
}

// ---------------- last-layer (s=0 only) fp32 chain ----------------
__global__ void last_q_kernel(const float* __restrict__ H, const float* __restrict__ Wq,
                              const float* __restrict__ Z,
                              float* __restrict__ PHI, float* __restrict__ DEN8) {
    int b = blockIdx.x, p = threadIdx.x;           // 64 threads
    const float* hr = H + (size_t)b * SS * EE;
    float acc = 0.f;
    for (int e = 0; e < EE; e++) acc = fmaf(hr[e], Wq[e * PP + p], acc);
    float phi = acc > 0.f ? acc + 1.f : expf(acc);
    PHI[b * PP + p] = phi;
    __shared__ float sm[PP];
    sm[p] = phi * Z[b * PP + p];
    __syncthreads();
    if (p == 0) {
        float s = 0.f;
        for (int i = 0; i < PP; i++) s += sm[i];
        DEN8[b] = 1.f / (s + 1e-6f);
    }
}

__global__ void last_attn_kernel(const float* __restrict__ PHI,
                                 const float* __restrict__ KV,
                                 const float* __restrict__ DEN8,
                                 float* __restrict__ ATT8) {
    int b = blockIdx.x, tid = threadIdx.x;         // 256 threads
    __shared__ float ph[PP];
    if (tid < PP) ph[tid] = PHI[b * PP + tid];
    __syncthreads();
    float inv = DEN8[b];
    for (int f = tid; f < EE; f += 256) {
        float a = 0.f;
        for (int p = 0; p < PP; p++)
            a = fmaf(ph[p], KV[((size_t)b * PP + p) * EE + f], a);
        ATT8[b * EE + f] = a * inv;
    }
}

__global__ void last_wo_ln_kernel(const float* __restrict__ ATT8,
                                  const float* __restrict__ Wo,
                                  const float* __restrict__ gam,
                                  const float* __restrict__ bet,
                                  float* __restrict__ LN8) {
    int b = blockIdx.x, e = threadIdx.x;           // 512 threads = EE
    __shared__ float at[EE];
    at[e] = ATT8[b * EE + e];
    __syncthreads();
    float a = 0.f;
    for (int f = 0; f < EE; f++) a = fmaf(at[f], Wo[(size_t)f * EE + e], a);
    // block LN over 512 values
    float s = a, q = a * a;
    #pragma unroll
    for (int o = 16; o; o >>= 1) {
        s += __shfl_xor_sync(0xffffffffu, s, o);
        q += __shfl_xor_sync(0xffffffffu, q, o);
    }
    __shared__ float ssum[16], ssq[16];
    int w = e >> 5;
    if ((e & 31) == 0) { ssum[w] = s; ssq[w] = q; }
    __syncthreads();
    float S = 0.f, Qq = 0.f;
    #pragma unroll
    for (int i = 0; i < 16; i++) { S += ssum[i]; Qq += ssq[i]; }
    float mu = S * (1.f / EE);
    float var = Qq * (1.f / EE) - mu * mu;
    float inv = rsqrtf(var + 1e-5f);
    LN8[b * EE + e] = (a - mu) * inv * gam[e] + bet[e];
}

__global__ void last_mlp1_kernel(const float* __restrict__ LN8,
                                 const float* __restrict__ W1,
                                 const float* __restrict__ b1,
                                 float* __restrict__ M8) {
    int b = blockIdx.y, j = blockIdx.x * 512 + threadIdx.x;   // 4 x BB blocks
    __shared__ float ln[EE];
    for (int i = threadIdx.x; i < EE; i += 512) ln[i] = LN8[b * EE + i];
    __syncthreads();
    float acc = b1[j];
    for (int e = 0; e < EE; e++) acc = fmaf(ln[e], W1[(size_t)e * FF + j], acc);
    M8[b * FF + j] = gelu_f(acc);
}

__global__ void last_mlp2_kernel(const float* __restrict__ M8,
                                 const float* __restrict__ W2,
                                 const float* __restrict__ b2,
                                 const float* __restrict__ H,
                                 float* __restrict__ H8) {
    int b = blockIdx.x, e = threadIdx.x;           // 512 threads
    float acc = b2[e];
    const float* m = M8 + (size_t)b * FF;
    for (int j = 0; j < FF; j++) acc = fmaf(m[j], W2[(size_t)j * EE + e], acc);
    H8[b * EE + e] = acc + H[(size_t)b * SS * EE + e];
}

// ---------------- head (reads compact H8 [BB][EE]) ----------------
__global__ void head_kernel(const float* __restrict__ H8, const float* __restrict__ Wh1,
                            const float* __restrict__ bh1, const float* __restrict__ Wh2,
                            const float* __restrict__ bh2, float* __restrict__ out) {
    int b = blockIdx.x, tid = threadIdx.x;
    const float* hr = H8 + (size_t)b * EE;
    float acc = bh1[tid];
    for (int e = 0; e < EE; e++) acc = fmaf(hr[e], Wh1[e * HH + tid], acc);
    acc = fmaxf(acc, 0.f);
    __shared__ float hid[HH];
    hid[tid] = acc;
    __syncthreads();
    if (tid < CC) {
        float a = bh2[tid];
        for (int h = 0; h < HH; h++) a = fmaf(hid[h], Wh2[h * CC + tid], a);
        out[b * CC + tid] = a;
    }
}

// ---------------- launch ----------------
static size_t gemm_smem(int BM, int BN) {
    return (size_t)(3 * (BM * 20 * 2 + BN * 20 * 2)) * 4;
}

extern "C" void kernel_launch(void* const* d_in, const int* in_sizes, int n_in,
                              void* d_out, int out_size) {
    const int*   x    = (const int*)  d_in[0];
    const float* emb  = (const float*)d_in[1];
    const float* pos  = (const float*)d_in[2];
    const float* Wq   = (const float*)d_in[3];
    const float* Wk   = (const float*)d_in[4];
    const float* Wv   = (const float*)d_in[5];
    const float* Wo   = (const float*)d_in[6];
    const float* ln_g = (const float*)d_in[7];
    const float* ln_b = (const float*)d_in[8];
    const float* W1   = (const float*)d_in[9];
    const float* b1   = (const float*)d_in[10];
    const float* W2   = (const float*)d_in[11];
    const float* b2   = (const float*)d_in[12];
    const float* Wh1  = (const float*)d_in[13];
    const float* bh1  = (const float*)d_in[14];
    const float* Wh2  = (const float*)d_in[15];
    const float* bh2  = (const float*)d_in[16];
    float* out = (float*)d_out;

    float *H, *A, *V, *Q, *Kq, *KV, *KVp, *Z, *Zp, *DEN;
    float *PHI, *DEN8, *ATT8, *LN8, *M8, *H8;
    cudaGetSymbolAddress((void**)&H,    g_H);
    cudaGetSymbolAddress((void**)&A,    g_A);
    cudaGetSymbolAddress((void**)&V,    g_V);
    cudaGetSymbolAddress((void**)&Q,    g_Q);
    cudaGetSymbolAddress((void**)&Kq,   g_K);
    cudaGetSymbolAddress((void**)&KV,   g_KV);
    cudaGetSymbolAddress((void**)&KVp,  g_KVp);
    cudaGetSymbolAddress((void**)&Z,    g_Z);
    cudaGetSymbolAddress((void**)&Zp,   g_Zp);
    cudaGetSymbolAddress((void**)&DEN,  g_DEN);
    cudaGetSymbolAddress((void**)&PHI,  g_PHI);
    cudaGetSymbolAddress((void**)&DEN8, g_DEN8);
    cudaGetSymbolAddress((void**)&ATT8, g_ATT8);
    cudaGetSymbolAddress((void**)&LN8,  g_LN8);
    cudaGetSymbolAddress((void**)&M8,   g_M8);
    cudaGetSymbolAddress((void**)&H8,   g_H8);

    unsigned *Hh, *Hl, *NMh, *NMl, *LNh, *LNl, *Mbh, *Mbl, *Qh, *Ql, *KVTh, *KVTl;
    cudaGetSymbolAddress((void**)&Hh,   g_Hh);   cudaGetSymbolAddress((void**)&Hl,   g_Hl);
    cudaGetSymbolAddress((void**)&NMh,  g_NMh);  cudaGetSymbolAddress((void**)&NMl,  g_NMl);
    cudaGetSymbolAddress((void**)&LNh,  g_LNh);  cudaGetSymbolAddress((void**)&LNl,  g_LNl);
    cudaGetSymbolAddress((void**)&Mbh,  g_Mbh);  cudaGetSymbolAddress((void**)&Mbl,  g_Mbl);
    cudaGetSymbolAddress((void**)&Qh,   g_Qh);   cudaGetSymbolAddress((void**)&Ql,   g_Ql);
    cudaGetSymbolAddress((void**)&KVTh, g_KVTh); cudaGetSymbolAddress((void**)&KVTl, g_KVTl);

    unsigned *Wqh, *Wql, *Wkh, *Wkl, *Wvh, *Wvl, *Woh, *Wol, *W1h, *W1l, *W2h, *W2l;
    cudaGetSymbolAddress((void**)&Wqh, g_Wqh); cudaGetSymbolAddress((void**)&Wql, g_Wql_);
    cudaGetSymbolAddress((void**)&Wkh, g_Wkh); cudaGetSymbolAddress((void**)&Wkl, g_Wkl_);
    cudaGetSymbolAddress((void**)&Wvh, g_Wvh); cudaGetSymbolAddress((void**)&Wvl, g_Wvl_);
    cudaGetSymbolAddress((void**)&Woh, g_Woh); cudaGetSymbolAddress((void**)&Wol, g_Wol_);
    cudaGetSymbolAddress((void**)&W1h, g_W1h); cudaGetSymbolAddress((void**)&W1l, g_W1l_);
    cudaGetSymbolAddress((void**)&W2h, g_W2h); cudaGetSymbolAddress((void**)&W2l, g_W2l_);

    const size_t smQK  = gemm_smem(128, 64);
    const size_t smBIG = gemm_smem(128, 256);
    cudaFuncSetAttribute(gemm_pk<128, 64, 32, 32, EPI_PHI, true, true, false>,
                         cudaFuncAttributeMaxDynamicSharedMemorySize, (int)smQK);
    cudaFuncSetAttribute(gemm_pk<128, 64, 32, 32, EPI_PHI, true, false, false>,
                         cudaFuncAttributeMaxDynamicSharedMemorySize, (int)smQK);
    cudaFuncSetAttribute(gemm_pk<128, 256, 64, 64, EPI_NONE, true, false, false>,
                         cudaFuncAttributeMaxDynamicSharedMemorySize, (int)smBIG);
    cudaFuncSetAttribute(gemm_pk<128, 256, 64, 64, EPI_DIV, false, true, true>,
                         cudaFuncAttributeMaxDynamicSharedMemorySize, (int)smBIG);
    cudaFuncSetAttribute(gemm_pk<128, 256, 64, 64, EPI_GELU, false, true, false>,
                         cudaFuncAttributeMaxDynamicSharedMemorySize, (int)smBIG);
    cudaFuncSetAttribute(gemm_pk<128, 256, 64, 64, EPI_RES, true, true, false>,
                         cudaFuncAttributeMaxDynamicSharedMemorySize, (int)smBIG);

    // one-time weight transpose+split
    dim3 wt(32, 8);
    {
        WSPack pA;
        pA.e[0] = { Wq, Wqh, Wql, EE, PP, LL * (EE / 32) * (PP / 32) };
        pA.e[1] = { Wk, Wkh, Wkl, EE, PP, LL * (EE / 32) * (PP / 32) };
        pA.e[2] = { Wv, Wvh, Wvl, EE, EE, LL * (EE / 32) * (EE / 32) };
        pA.e[3] = { Wo, Woh, Wol, EE, EE, LL * (EE / 32) * (EE / 32) };
        pA.cnt = 4;
        int nA = pA.e[0].nblk + pA.e[1].nblk + pA.e[2].nblk + pA.e[3].nblk;
        wsplit_multi<<<nA, wt>>>(pA);

        WSPack pB;
        pB.e[0] = { W1, W1h, W1l, EE, FF, LL * (EE / 32) * (FF / 32) };
        pB.e[1] = { W2, W2h, W2l, FF, EE, LL * (FF / 32) * (EE / 32) };
        pB.e[2] = pB.e[0]; pB.e[3] = pB.e[0];
        pB.cnt = 2;
        int nB = pB.e[0].nblk + pB.e[1].nblk;
        wsplit_multi<<<nB, wt>>>(pB);
    }

    embed_kernel<<<MROWS, 128>>>(x, emb, pos, H, Hh, Hl);

    for (int l = 0; l < LL; l++) {
        size_t oQK = (size_t)l * PP * (EE / 2);
        size_t oV  = (size_t)l * EE * (EE / 2);
        size_t oW1 = (size_t)l * FF * (EE / 2);
        size_t oW2 = (size_t)l * EE * (FF / 2);
        const bool last = (l == LL - 1);

        if (!last) {
            gemm_pk<128, 64, 32, 32, EPI_PHI, true, true, false>
                <<<dim3(PP / 64, MROWS / 128), 256, smQK>>>(
                    MROWS, PP, EE, Hh, Hl, Wqh + oQK, Wql + oQK,
                    nullptr, nullptr, Q, Qh, Ql);
        }
        gemm_pk<128, 64, 32, 32, EPI_PHI, true, false, false>
            <<<dim3(PP / 64, MROWS / 128), 256, smQK>>>(
                MROWS, PP, EE, Hh, Hl, Wkh + oQK, Wkl + oQK,
                nullptr, nullptr, Kq, nullptr, nullptr);
        gemm_pk<128, 256, 64, 64, EPI_NONE, true, false, false>
            <<<dim3(EE / 256, MROWS / 128), 256, smBIG>>>(
                MROWS, EE, EE, Hh, Hl, Wvh + oV, Wvl + oV,
                nullptr, nullptr, V, nullptr, nullptr);

        kv_kernel<<<dim3(EE / 64, BB, NSPLIT), 256>>>(Kq, V, KVp);
        z_kernel<<<dim3(BB, NSPLIT), 256>>>(Kq, Zp);
        reduce_kv<<<(BB * PP * EE) / 256, 256>>>(KVp, KV);
        reduce_z<<<2, 256>>>(Zp, Z);

        if (!last) {
            wsplit_kernel<<<dim3(EE / 32, PP / 32, BB), wt>>>(KV, KVTh, KVTl, PP, EE);
            den_kernel<<<MROWS / 8, 256>>>(Q, Z, DEN);

            gemm_pk<128, 256, 64, 64, EPI_DIV, false, true, true>
                <<<dim3(EE / 256, MROWS / 128), 256, smBIG>>>(
                    MROWS, EE, PP, Qh, Ql, KVTh, KVTl,
                    DEN, nullptr, nullptr, NMh, NMl);

            gemm_pk<128, 256, 64, 64, EPI_NONE, true, false, false>
                <<<dim3(EE / 256, MROWS / 128), 256, smBIG>>>(
                    MROWS, EE, EE, NMh, NMl, Woh + oV, Wol + oV,
                    nullptr, nullptr, A, nullptr, nullptr);

            ln_kernel<<<MROWS, 128>>>(A, ln_g + (size_t)l * EE,
                                      ln_b + (size_t)l * EE, LNh, LNl);

            gemm_pk<128, 256, 64, 64, EPI_GELU, false, true, false>
                <<<dim3(FF / 256, MROWS / 128), 256, smBIG>>>(
                    MROWS, FF, EE, LNh, LNl, W1h + oW1, W1l + oW1,
                    b1 + (size_t)l * FF, nullptr, nullptr, Mbh, Mbl);
            gemm_pk<128, 256, 64, 64, EPI_RES, true, true, false>
                <<<dim3(EE / 256, MROWS / 128), 256, smBIG>>>(
                    MROWS, EE, FF, Mbh, Mbl, W2h + oW2, W2l + oW2,
                    b2 + (size_t)l * EE, H, H, Hh, Hl);
        } else {
            // last layer: only s=0 of each batch matters downstream
            const float* Wql3 = Wq + (size_t)l * EE * PP;
            const float* Wol3 = Wo + (size_t)l * EE * EE;
            const float* W1l3 = W1 + (size_t)l * EE * FF;
            const float* W2l3 = W2 + (size_t)l * FF * EE;
            last_q_kernel<<<BB, PP>>>(H, Wql3, Z, PHI, DEN8);
            last_attn_kernel<<<BB, 256>>>(PHI, KV, DEN8, ATT8);
            last_wo_ln_kernel<<<BB, EE>>>(ATT8, Wol3,
                                          ln_g + (size_t)l * EE,
                                          ln_b + (size_t)l * EE, LN8);
            last_mlp1_kernel<<<dim3(FF / 512, BB), 512>>>(LN8, W1l3,
                                                          b1 + (size_t)l * FF, M8);
            last_mlp2_kernel<<<BB, EE>>>(M8, W2l3, b2 + (size_t)l * EE, H, H8);
        }
    }

    head_kernel<<<BB, HH>>>(H8, Wh1, bh1, Wh2, bh2, out);
}

// round 12
// speedup vs baseline: 3.0242x; 1.2026x over previous
#include <cuda_runtime.h>
#include <math.h>

#define BB   8
#define SS   4096
#define EE   512
#define PP   64
#define LL   4
#define HH   256
#define CC   2
#define FF   2048
#define MROWS (BB*SS)
#define NSPLIT 8

enum { EPI_NONE = 0, EPI_PHI = 1, EPI_GELU = 2, EPI_RES = 3, EPI_DIV = 4 };

// ---------------- scratch ----------------
__device__ float g_H  [(size_t)MROWS*EE];
__device__ float g_A  [(size_t)MROWS*EE];
__device__ float g_Q  [(size_t)MROWS*PP];
__device__ float g_K  [(size_t)MROWS*PP];
__device__ float g_KH [(size_t)BB*PP*EE];      // phi_k^T @ H
__device__ float g_KHp[(size_t)NSPLIT*BB*PP*EE];
__device__ float g_KVW[(size_t)BB*PP*EE];      // KH @ WvWo
__device__ float g_WVWO[(size_t)LL*EE*EE];     // Wv @ Wo per layer
__device__ float g_Z  [(size_t)BB*PP];
__device__ float g_Zp [(size_t)NSPLIT*BB*PP];
__device__ float g_DEN[(size_t)MROWS];
// last-layer small buffers
__device__ float g_PHI [(size_t)BB*PP];
__device__ float g_DEN8[(size_t)BB];
__device__ float g_ATT8[(size_t)BB*EE];
__device__ float g_LN8 [(size_t)BB*EE];
__device__ float g_M8  [(size_t)BB*FF];
__device__ float g_H8  [(size_t)BB*EE];

// packed bf16x2 hi/lo
__device__ unsigned g_Hh [(size_t)MROWS*(EE/2)],  g_Hl [(size_t)MROWS*(EE/2)];
__device__ unsigned g_LNh[(size_t)MROWS*(EE/2)],  g_LNl[(size_t)MROWS*(EE/2)];
__device__ unsigned g_Mbh[(size_t)MROWS*(FF/2)],  g_Mbl[(size_t)MROWS*(FF/2)];
__device__ unsigned g_Qh [(size_t)MROWS*(PP/2)],  g_Ql [(size_t)MROWS*(PP/2)];
__device__ unsigned g_KVTh[(size_t)BB*EE*(PP/2)], g_KVTl[(size_t)BB*EE*(PP/2)];
// bf16 weights [N][K/2]
__device__ unsigned g_Wqh[(size_t)LL*PP*(EE/2)],  g_Wql_[(size_t)LL*PP*(EE/2)];
__device__ unsigned g_Wkh[(size_t)LL*PP*(EE/2)],  g_Wkl_[(size_t)LL*PP*(EE/2)];
__device__ unsigned g_W1h[(size_t)LL*FF*(EE/2)],  g_W1l_[(size_t)LL*FF*(EE/2)];
__device__ unsigned g_W2h[(size_t)LL*EE*(FF/2)],  g_W2l_[(size_t)LL*EE*(FF/2)];

// ---------------- helpers ----------------
__device__ __forceinline__ void cp_async16(void* smem, const void* gmem) {
    unsigned sa = (unsigned)__cvta_generic_to_shared(smem);
    asm volatile("cp.async.cg.shared.global [%0], [%1], 16;" :: "r"(sa), "l"(gmem));
}
__device__ __forceinline__ void cp_commit() { asm volatile("cp.async.commit_group;"); }
template<int N>
__device__ __forceinline__ void cp_wait() {
    asm volatile("cp.async.wait_group %0;" :: "n"(N));
}

__device__ __forceinline__ void split2(float x, float y, unsigned& hi, unsigned& lo) {
    asm("cvt.rn.bf16x2.f32 %0, %1, %2;" : "=r"(hi) : "f"(y), "f"(x));
    float hx = __uint_as_float(hi << 16);
    float hy = __uint_as_float(hi & 0xFFFF0000u);
    asm("cvt.rn.bf16x2.f32 %0, %1, %2;" : "=r"(lo) : "f"(y - hy), "f"(x - hx));
}

__device__ __forceinline__ void mma_bf16(float c[4], const unsigned a[4], const unsigned b[2]) {
    asm volatile(
        "mma.sync.aligned.m16n8k16.row.col.f32.bf16.bf16.f32 "
        "{%0,%1,%2,%3}, {%4,%5,%6,%7}, {%8,%9}, {%0,%1,%2,%3};"
        : "+f"(c[0]), "+f"(c[1]), "+f"(c[2]), "+f"(c[3])
        : "r"(a[0]), "r"(a[1]), "r"(a[2]), "r"(a[3]), "r"(b[0]), "r"(b[1]));
}

__device__ __forceinline__ float gelu_f(float v) {
    float u = 0.7978845608028654f * (v + 0.044715f * v * v * v);
    return 0.5f * v * (1.f + tanhf(u));
}

// ---------------- transpose + split ----------------
__device__ __forceinline__ void wsplit_tile(const float* Wl, unsigned* Th, unsigned* Tl,
                                            int K, int N, int k0, int n0, float (*t)[33]) {
    int tx = threadIdx.x, ty = threadIdx.y;
    #pragma unroll
    for (int i = 0; i < 4; i++)
        t[ty + i * 8][tx] = Wl[(size_t)(k0 + ty + i * 8) * N + n0 + tx];
    __syncthreads();
    int tid = ty * 32 + tx;
    #pragma unroll
    for (int i = 0; i < 2; i++) {
        int w = tid + i * 256;
        int n = w >> 4, kp = w & 15;
        unsigned h, l;
        split2(t[2 * kp][n], t[2 * kp + 1][n], h, l);
        size_t o = (size_t)(n0 + n) * (K >> 1) + (k0 >> 1) + kp;
        Th[o] = h; Tl[o] = l;
    }
}

__global__ void wsplit_kernel(const float* __restrict__ W,
                              unsigned* __restrict__ Th, unsigned* __restrict__ Tl,
                              int K, int N) {
    __shared__ float t[32][33];
    wsplit_tile(W + (size_t)blockIdx.z * K * N,
                Th + (size_t)blockIdx.z * N * (K >> 1),
                Tl + (size_t)blockIdx.z * N * (K >> 1),
                K, N, blockIdx.y * 32, blockIdx.x * 32, t);
}

struct WSEntry { const float* W; unsigned* Th; unsigned* Tl; int K; int N; int nblk; };
struct WSPack  { WSEntry e[4]; int cnt; };
__global__ void wsplit_multi(WSPack p) {
    __shared__ float t[32][33];
    int bid = blockIdx.x, i = 0;
    while (i + 1 < p.cnt && bid >= p.e[i].nblk) { bid -= p.e[i].nblk; i++; }
    WSEntry E = p.e[i];
    int tiles_n = E.N / 32, tpl = tiles_n * (E.K / 32);
    int layer = bid / tpl, rem = bid % tpl;
    wsplit_tile(E.W + (size_t)layer * E.K * E.N,
                E.Th + (size_t)layer * E.N * (E.K >> 1),
                E.Tl + (size_t)layer * E.N * (E.K >> 1),
                E.K, E.N, (rem / tiles_n) * 32, (rem % tiles_n) * 32, t);
}

// ---------------- WvWo = Wv @ Wo (per layer, fp32, one-time) ----------------
__global__ void __launch_bounds__(256)
wvwo_kernel(const float* __restrict__ Wv, const float* __restrict__ Wo,
            float* __restrict__ WVWO) {
    int l = blockIdx.z;
    const float* Av = Wv + (size_t)l * EE * EE;   // [k][e]
    const float* Bo = Wo + (size_t)l * EE * EE;   // [e][n]
    float* C = WVWO + (size_t)l * EE * EE;
    int k0 = blockIdx.y * 64, n0 = blockIdx.x * 64;
    __shared__ float As[32][65];   // [e][k]
    __shared__ float Bs[32][64];   // [e][n]
    int tid = threadIdx.x, tx = tid % 16, ty = tid / 16;
    float acc[4][4];
    #pragma unroll
    for (int i = 0; i < 4; i++)
        #pragma unroll
        for (int j = 0; j < 4; j++) acc[i][j] = 0.f;
    for (int e0 = 0; e0 < EE; e0 += 32) {
        #pragma unroll
        for (int i = 0; i < 8; i++) {
            int idx = tid + i * 256;
            int r = idx / 32, c = idx % 32;
            As[c][r] = Av[(size_t)(k0 + r) * EE + e0 + c];
        }
        #pragma unroll
        for (int i = 0; i < 2; i++) {
            int idx = tid + i * 256;
            int r = idx / 16, c4 = idx % 16;
            *(float4*)&Bs[r][c4 * 4] =
                *(const float4*)(Bo + (size_t)(e0 + r) * EE + n0 + c4 * 4);
        }
        __syncthreads();
        #pragma unroll
        for (int e = 0; e < 32; e++) {
            float ra[4], rb[4];
            #pragma unroll
            for (int i = 0; i < 4; i++) ra[i] = As[e][ty * 4 + i];
            #pragma unroll
            for (int j = 0; j < 4; j++) rb[j] = Bs[e][tx * 4 + j];
            #pragma unroll
            for (int i = 0; i < 4; i++)
                #pragma unroll
                for (int j = 0; j < 4; j++)
                    acc[i][j] = fmaf(ra[i], rb[j], acc[i][j]);
        }
        __syncthreads();
    }
    #pragma unroll
    for (int i = 0; i < 4; i++)
        #pragma unroll
        for (int j = 0; j < 4; j++)
            C[(size_t)(k0 + ty * 4 + i) * EE + n0 + tx * 4 + j] = acc[i][j];
}

// ---------------- KVW = KH @ WvWo (per batch, fp32) ----------------
__global__ void __launch_bounds__(256)
kvwo_kernel(const float* __restrict__ KH, const float* __restrict__ WVWOl,
            float* __restrict__ KVW) {
    int b = blockIdx.y, n0 = blockIdx.x * 64;
    const float* Ak = KH + (size_t)b * PP * EE;   // [64][512]
    float* C = KVW + (size_t)b * PP * EE;
    __shared__ float As[32][65];   // [e][p]
    __shared__ float Bs[32][64];   // [e][n]
    int tid = threadIdx.x, tx = tid % 16, ty = tid / 16;
    float acc[4][4];
    #pragma unroll
    for (int i = 0; i < 4; i++)
        #pragma unroll
        for (int j = 0; j < 4; j++) acc[i][j] = 0.f;
    for (int e0 = 0; e0 < EE; e0 += 32) {
        #pragma unroll
        for (int i = 0; i < 8; i++) {
            int idx = tid + i * 256;
            int r = idx / 32, c = idx % 32;
            As[c][r] = Ak[(size_t)r * EE + e0 + c];   // r < 64 = PP
        }
        #pragma unroll
        for (int i = 0; i < 2; i++) {
            int idx = tid + i * 256;
            int r = idx / 16, c4 = idx % 16;
            *(float4*)&Bs[r][c4 * 4] =
                *(const float4*)(WVWOl + (size_t)(e0 + r) * EE + n0 + c4 * 4);
        }
        __syncthreads();
        #pragma unroll
        for (int e = 0; e < 32; e++) {
            float ra[4], rb[4];
            #pragma unroll
            for (int i = 0; i < 4; i++) ra[i] = As[e][ty * 4 + i];
            #pragma unroll
            for (int j = 0; j < 4; j++) rb[j] = Bs[e][tx * 4 + j];
            #pragma unroll
            for (int i = 0; i < 4; i++)
                #pragma unroll
                for (int j = 0; j < 4; j++)
                    acc[i][j] = fmaf(ra[i], rb[j], acc[i][j]);
        }
        __syncthreads();
    }
    #pragma unroll
    for (int i = 0; i < 4; i++)
        #pragma unroll
        for (int j = 0; j < 4; j++)
            C[(size_t)(ty * 4 + i) * EE + n0 + tx * 4 + j] = acc[i][j];
}

// ---------------- embedding ----------------
__global__ void embed_kernel(const int* __restrict__ x, const float* __restrict__ emb,
                             const float* __restrict__ pos, float* __restrict__ H,
                             unsigned* __restrict__ Hh, unsigned* __restrict__ Hl) {
    int row = blockIdx.x, s = row & (SS - 1), tok = x[row];
    const float4* e4 = (const float4*)(emb + (size_t)tok * EE);
    const float4* p4 = (const float4*)(pos + (size_t)s * EE);
    int t = threadIdx.x;
    float4 a = e4[t], b = p4[t];
    float4 o = make_float4(a.x + b.x, a.y + b.y, a.z + b.z, a.w + b.w);
    ((float4*)(H + (size_t)row * EE))[t] = o;
    unsigned h0, l0, h1, l1;
    split2(o.x, o.y, h0, l0);
    split2(o.z, o.w, h1, l1);
    size_t wo = (size_t)row * (EE / 2) + 2 * t;
    Hh[wo] = h0; Hh[wo + 1] = h1;
    Hl[wo] = l0; Hl[wo + 1] = l1;
}

// ---------------- bf16x2 split GEMM ----------------
template<int BM, int BN, int WM, int WN, int EPI, bool WF32, bool WPACK, bool BATCHB>
__global__ void __launch_bounds__((BM/WM)*(BN/WN)*32)
gemm_pk(int M, int N, int K,
        const unsigned* __restrict__ Ah, const unsigned* __restrict__ Al,
        const unsigned* __restrict__ Bh, const unsigned* __restrict__ Bl,
        const float* __restrict__ bias, const float* __restrict__ res,
        float* __restrict__ C, unsigned* __restrict__ Ch, unsigned* __restrict__ Cl)
{
    constexpr int WARPS_N = BN / WN;
    constexpr int NTH = (BM / WM) * WARPS_N * 32;
    constexpr int LDW = 20;
    constexpr int ASZ = BM * LDW, BSZ = BN * LDW;
    constexpr int MT = WM / 16, NT = WN / 8;
    constexpr int A_CNT = BM * 4 / NTH, B_CNT = BN * 4 / NTH;

    extern __shared__ unsigned smw[];
    unsigned* Ash = smw;
    unsigned* Asl = smw + 3 * ASZ;
    unsigned* Bsh = smw + 6 * ASZ;
    unsigned* Bsl = smw + 6 * ASZ + 3 * BSZ;

    const int tid = threadIdx.x, lane = tid & 31, warp = tid >> 5;
    const int wm = warp / WARPS_N, wn = warp % WARPS_N;
    const int lr = lane >> 2, lc = lane & 3;
    const int row0 = blockIdx.y * BM, col0 = blockIdx.x * BN;
    const int KW = K >> 1, KT = K / 32;

    const unsigned* Bhp = Bh;
    const unsigned* Blp = Bl;
    if (BATCHB) {
        size_t boff = (size_t)(blockIdx.y / (SS / BM)) * N * KW;
        Bhp += boff; Blp += boff;
    }

    float acc[MT][NT][4];
    #pragma unroll
    for (int i = 0; i < MT; i++)
        #pragma unroll
        for (int j = 0; j < NT; j++)
            #pragma unroll
            for (int q = 0; q < 4; q++) acc[i][j][q] = 0.f;

    auto issue = [&](int kt, int st) {
        int goff = kt * 16;
        #pragma unroll
        for (int i = 0; i < A_CNT; i++) {
            int idx = tid + i * NTH;
            int r = idx >> 2, c = (idx & 3) * 4;
            size_t g = (size_t)(row0 + r) * KW + goff + c;
            cp_async16(Ash + st * ASZ + r * LDW + c, Ah + g);
            cp_async16(Asl + st * ASZ + r * LDW + c, Al + g);
        }
        #pragma unroll
        for (int i = 0; i < B_CNT; i++) {
            int idx = tid + i * NTH;
            int r = idx >> 2, c = (idx & 3) * 4;
            size_t g = (size_t)(col0 + r) * KW + goff + c;
            cp_async16(Bsh + st * BSZ + r * LDW + c, Bhp + g);
            cp_async16(Bsl + st * BSZ + r * LDW + c, Blp + g);
        }
    };

    auto compute = [&](int st) {
        const unsigned* Ah_ = Ash + st * ASZ;
        const unsigned* Al_ = Asl + st * ASZ;
        const unsigned* Bh_ = Bsh + st * BSZ;
        const unsigned* Bl_ = Bsl + st * BSZ;
        #pragma unroll
        for (int kk = 0; kk < 2; kk++) {
            unsigned ah[MT][4], al[MT][4];
            #pragma unroll
            for (int i = 0; i < MT; i++) {
                int base = (wm * WM + i * 16 + lr) * LDW + kk * 8 + lc;
                ah[i][0] = Ah_[base];               al[i][0] = Al_[base];
                ah[i][1] = Ah_[base + 8 * LDW];     al[i][1] = Al_[base + 8 * LDW];
                ah[i][2] = Ah_[base + 4];           al[i][2] = Al_[base + 4];
                ah[i][3] = Ah_[base + 8 * LDW + 4]; al[i][3] = Al_[base + 8 * LDW + 4];
            }
            #pragma unroll
            for (int j = 0; j < NT; j++) {
                int bbase = (wn * WN + j * 8 + lr) * LDW + kk * 8 + lc;
                unsigned bh[2], bl[2];
                bh[0] = Bh_[bbase];     bl[0] = Bl_[bbase];
                bh[1] = Bh_[bbase + 4]; bl[1] = Bl_[bbase + 4];
                #pragma unroll
                for (int i = 0; i < MT; i++) {
                    mma_bf16(acc[i][j], ah[i], bh);
                    mma_bf16(acc[i][j], ah[i], bl);
                    mma_bf16(acc[i][j], al[i], bh);
                }
            }
        }
    };

    issue(0, 0); cp_commit();
    issue(1, 1); cp_commit();
    cp_wait<1>();
    __syncthreads();
    for (int kt = 0; kt < KT; kt++) {
        if (kt + 2 < KT) issue(kt + 2, (kt + 2) % 3);
        cp_commit();
        compute(kt % 3);
        cp_wait<1>();
        __syncthreads();
    }

    auto epi = [&](float v, int rr, int cc) -> float {
        if (EPI == EPI_PHI)  return v > 0.f ? v + 1.f : expf(v);
        if (EPI == EPI_GELU) return gelu_f(v + bias[cc]);
        if (EPI == EPI_RES)  return v + bias[cc] + res[(size_t)rr * N + cc];
        if (EPI == EPI_DIV)  return v * bias[rr];
        return v;
    };

    #pragma unroll
    for (int i = 0; i < MT; i++) {
        #pragma unroll
        for (int j = 0; j < NT; j++) {
            int rr = row0 + wm * WM + i * 16 + lr;
            int cc = col0 + wn * WN + j * 8 + 2 * lc;
            float e00 = epi(acc[i][j][0], rr, cc);
            float e01 = epi(acc[i][j][1], rr, cc + 1);
            float e10 = epi(acc[i][j][2], rr + 8, cc);
            float e11 = epi(acc[i][j][3], rr + 8, cc + 1);
            if (WF32) {
                *(float2*)(C + (size_t)rr * N + cc)       = make_float2(e00, e01);
                *(float2*)(C + (size_t)(rr + 8) * N + cc) = make_float2(e10, e11);
            }
            if (WPACK) {
                unsigned h, l;
                split2(e00, e01, h, l);
                size_t w0 = (size_t)rr * (N >> 1) + (cc >> 1);
                Ch[w0] = h; Cl[w0] = l;
                split2(e10, e11, h, l);
                size_t w1 = (size_t)(rr + 8) * (N >> 1) + (cc >> 1);
                Ch[w1] = h; Cl[w1] = l;
            }
        }
    }
}

// ---------------- KH partials: phi_k^T @ H, split over S ----------------
__global__ void __launch_bounds__(256)
kv_kernel(const float* __restrict__ Kp, const float* __restrict__ Hm,
          float* __restrict__ KHp)
{
    int b = blockIdx.y, f0 = blockIdx.x * 64, sp = blockIdx.z;
    const float* Kb = Kp + (size_t)b * SS * PP;
    const float* Vb = Hm + (size_t)b * SS * EE;
    __shared__ float Ks[32 * 64];
    __shared__ float Vs[32 * 64];
    int tid = threadIdx.x, tx = tid % 16, ty = tid / 16;
    float acc[4][4];
    #pragma unroll
    for (int i = 0; i < 4; i++)
        #pragma unroll
        for (int j = 0; j < 4; j++) acc[i][j] = 0.f;
    int sbeg = sp * (SS / NSPLIT), send = sbeg + (SS / NSPLIT);
    for (int s0 = sbeg; s0 < send; s0 += 32) {
        #pragma unroll
        for (int i = 0; i < 2; i++) {
            int idx = tid + i * 256;
            int r = idx / 16, c4 = idx % 16;
            *(float4*)(Ks + r * 64 + c4 * 4) =
                *(const float4*)(Kb + (size_t)(s0 + r) * PP + c4 * 4);
            *(float4*)(Vs + r * 64 + c4 * 4) =
                *(const float4*)(Vb + (size_t)(s0 + r) * EE + f0 + c4 * 4);
        }
        __syncthreads();
        #pragma unroll
        for (int k = 0; k < 32; k++) {
            float rp[4], rv[4];
            #pragma unroll
            for (int i = 0; i < 4; i++) rp[i] = Ks[k * 64 + ty * 4 + i];
            #pragma unroll
            for (int j = 0; j < 4; j++) rv[j] = Vs[k * 64 + tx * 4 + j];
            #pragma unroll
            for (int i = 0; i < 4; i++)
                #pragma unroll
                for (int j = 0; j < 4; j++)
                    acc[i][j] = fmaf(rp[i], rv[j], acc[i][j]);
        }
        __syncthreads();
    }
    float* out = KHp + (size_t)sp * BB * PP * EE;
    #pragma unroll
    for (int i = 0; i < 4; i++)
        #pragma unroll
        for (int j = 0; j < 4; j++)
            out[((size_t)b * PP + ty * 4 + i) * EE + f0 + tx * 4 + j] = acc[i][j];
}

__global__ void reduce_kv(const float* __restrict__ KHp, float* __restrict__ KH) {
    size_t idx = (size_t)blockIdx.x * 256 + threadIdx.x;
    float s = 0.f;
    #pragma unroll
    for (int sp = 0; sp < NSPLIT; sp++) s += KHp[(size_t)sp * BB * PP * EE + idx];
    KH[idx] = s;
}

__global__ void z_kernel(const float* __restrict__ Kp, float* __restrict__ Zp) {
    int b = blockIdx.x, sp = blockIdx.y;
    int tid = threadIdx.x, p = tid & 63, g = tid >> 6;
    const float* Kb = Kp + (size_t)b * SS * PP;
    float acc = 0.f;
    int sbeg = sp * (SS / NSPLIT), send = sbeg + (SS / NSPLIT);
    for (int s = sbeg + g; s < send; s += 4) acc += Kb[(size_t)s * PP + p];
    __shared__ float smem[256];
    smem[tid] = acc;
    __syncthreads();
    if (g == 0)
        Zp[(size_t)sp * BB * PP + b * PP + p] =
            smem[p] + smem[64 + p] + smem[128 + p] + smem[192 + p];
}

__global__ void reduce_z(const float* __restrict__ Zp, float* __restrict__ Z) {
    int idx = blockIdx.x * 256 + threadIdx.x;
    if (idx < BB * PP) {
        float s = 0.f;
        #pragma unroll
        for (int sp = 0; sp < NSPLIT; sp++) s += Zp[sp * BB * PP + idx];
        Z[idx] = s;
    }
}

__global__ void den_kernel(const float* __restrict__ Q, const float* __restrict__ Z,
                           float* __restrict__ inv) {
    int row = blockIdx.x * 8 + (threadIdx.x >> 5);
    int lane = threadIdx.x & 31;
    int b = row >> 12;
    const float* q = Q + (size_t)row * PP;
    const float* z = Z + b * PP;
    float s = q[lane] * z[lane] + q[lane + 32] * z[lane + 32];
    #pragma unroll
    for (int o = 16; o; o >>= 1) s += __shfl_xor_sync(0xffffffffu, s, o);
    if (lane == 0) inv[row] = 1.f / (s + 1e-6f);
}

// ---------------- layernorm: fp32 in -> packed out ----------------
__global__ void ln_kernel(const float* __restrict__ X,
                          const float* __restrict__ gam, const float* __restrict__ bet,
                          unsigned* __restrict__ Oh, unsigned* __restrict__ Ol) {
    int row = blockIdx.x;
    const float* xr = X + (size_t)row * EE;
    int tid = threadIdx.x;
    float4 v = ((const float4*)xr)[tid];
    float s = v.x + v.y + v.z + v.w;
    float q = v.x * v.x + v.y * v.y + v.z * v.z + v.w * v.w;
    #pragma unroll
    for (int o = 16; o; o >>= 1) {
        s += __shfl_xor_sync(0xffffffffu, s, o);
        q += __shfl_xor_sync(0xffffffffu, q, o);
    }
    __shared__ float ss[4], qq[4];
    int w = tid >> 5;
    if ((tid & 31) == 0) { ss[w] = s; qq[w] = q; }
    __syncthreads();
    s = ss[0] + ss[1] + ss[2] + ss[3];
    q = qq[0] + qq[1] + qq[2] + qq[3];
    float mu = s * (1.f / EE);
    float var = q * (1.f / EE) - mu * mu;
    float inv = rsqrtf(var + 1e-5f);
    float4 g4 = ((const float4*)gam)[tid];
    float4 b4 = ((const float4*)bet)[tid];
    float o0 = (v.x - mu) * inv * g4.x + b4.x;
    float o1 = (v.y - mu) * inv * g4.y + b4.y;
    float o2 = (v.z - mu) * inv * g4.z + b4.z;
    float o3 = (v.w - mu) * inv * g4.w + b4.w;
    unsigned h0, l0, h1, l1;
    split2(o0, o1, h0, l0);
    split2(o2, o3, h1, l1);
    size_t wo = (size_t)row * (EE / 2) + 2 * tid;
    Oh[wo] = h0; Oh[wo + 1] = h1;
    Ol[wo] = l0; Ol[wo + 1] = l1;
}

// ---------------- last-layer (s=0 only) fp32 chain ----------------
__global__ void last_q_kernel(const float* __restrict__ H, const float* __restrict__ Wq,
                              const float* __restrict__ Z,
                              float* __restrict__ PHI, float* __restrict__ DEN8) {
    int b = blockIdx.x, p = threadIdx.x;
    const float* hr = H + (size_t)b * SS * EE;
    float acc = 0.f;
    for (int e = 0; e < EE; e++) acc = fmaf(hr[e], Wq[e * PP + p], acc);
    float phi = acc > 0.f ? acc + 1.f : expf(acc);
    PHI[b * PP + p] = phi;
    __shared__ float sm[PP];
    sm[p] = phi * Z[b * PP + p];
    __syncthreads();
    if (p == 0) {
        float s = 0.f;
        for (int i = 0; i < PP; i++) s += sm[i];
        DEN8[b] = 1.f / (s + 1e-6f);
    }
}

// ATT8 = phi_q @ KVW * inv  (= attn @ Wo already, via WvWo fusion)
__global__ void last_attn_kernel(const float* __restrict__ PHI,
                                 const float* __restrict__ KVW,
                                 const float* __restrict__ DEN8,
                                 float* __restrict__ ATT8) {
    int b = blockIdx.x, tid = threadIdx.x;
    __shared__ float ph[PP];
    if (tid < PP) ph[tid] = PHI[b * PP + tid];
    __syncthreads();
    float inv = DEN8[b];
    for (int f = tid; f < EE; f += 256) {
        float a = 0.f;
        for (int p = 0; p < PP; p++)
            a = fmaf(ph[p], KVW[((size_t)b * PP + p) * EE + f], a);
        ATT8[b * EE + f] = a * inv;
    }
}

__global__ void last_ln_kernel(const float* __restrict__ ATT8,
                               const float* __restrict__ gam,
                               const float* __restrict__ bet,
                               float* __restrict__ LN8) {
    int b = blockIdx.x, e = threadIdx.x;          // 512 threads
    float a = ATT8[b * EE + e];
    float s = a, q = a * a;
    #pragma unroll
    for (int o = 16; o; o >>= 1) {
        s += __shfl_xor_sync(0xffffffffu, s, o);
        q += __shfl_xor_sync(0xffffffffu, q, o);
    }
    __shared__ float ssum[16], ssq[16];
    int w = e >> 5;
    if ((e & 31) == 0) { ssum[w] = s; ssq[w] = q; }
    __syncthreads();
    float S = 0.f, Qq = 0.f;
    #pragma unroll
    for (int i = 0; i < 16; i++) { S += ssum[i]; Qq += ssq[i]; }
    float mu = S * (1.f / EE);
    float var = Qq * (1.f / EE) - mu * mu;
    float inv = rsqrtf(var + 1e-5f);
    LN8[b * EE + e] = (a - mu) * inv * gam[e] + bet[e];
}

__global__ void last_mlp1_kernel(const float* __restrict__ LN8,
                                 const float* __restrict__ W1,
                                 const float* __restrict__ b1,
                                 float* __restrict__ M8) {
    int b = blockIdx.y, j = blockIdx.x * 512 + threadIdx.x;
    __shared__ float ln[EE];
    for (int i = threadIdx.x; i < EE; i += 512) ln[i] = LN8[b * EE + i];
    __syncthreads();
    float acc = b1[j];
    for (int e = 0; e < EE; e++) acc = fmaf(ln[e], W1[(size_t)e * FF + j], acc);
    M8[b * FF + j] = gelu_f(acc);
}

__global__ void last_mlp2_kernel(const float* __restrict__ M8,
                                 const float* __restrict__ W2,
                                 const float* __restrict__ b2,
                                 const float* __restrict__ H,
                                 float* __restrict__ H8) {
    int b = blockIdx.x, e = threadIdx.x;
    float acc = b2[e];
    const float* m = M8 + (size_t)b * FF;
    for (int j = 0; j < FF; j++) acc = fmaf(m[j], W2[(size_t)j * EE + e], acc);
    H8[b * EE + e] = acc + H[(size_t)b * SS * EE + e];
}

// ---------------- head ----------------
__global__ void head_kernel(const float* __restrict__ H8, const float* __restrict__ Wh1,
                            const float* __restrict__ bh1, const float* __restrict__ Wh2,
                            const float* __restrict__ bh2, float* __restrict__ out) {
    int b = blockIdx.x, tid = threadIdx.x;
    const float* hr = H8 + (size_t)b * EE;
    float acc = bh1[tid];
    for (int e = 0; e < EE; e++) acc = fmaf(hr[e], Wh1[e * HH + tid], acc);
    acc = fmaxf(acc, 0.f);
    __shared__ float hid[HH];
    hid[tid] = acc;
    __syncthreads();
    if (tid < CC) {
        float a = bh2[tid];
        for (int h = 0; h < HH; h++) a = fmaf(hid[h], Wh2[h * CC + tid], a);
        out[b * CC + tid] = a;
    }
}

// ---------------- launch ----------------
static size_t gemm_smem(int BM, int BN) {
    return (size_t)(3 * (BM * 20 * 2 + BN * 20 * 2)) * 4;
}

extern "C" void kernel_launch(void* const* d_in, const int* in_sizes, int n_in,
                              void* d_out, int out_size) {
    const int*   x    = (const int*)  d_in[0];
    const float* emb  = (const float*)d_in[1];
    const float* pos  = (const float*)d_in[2];
    const float* Wq   = (const float*)d_in[3];
    const float* Wk   = (const float*)d_in[4];
    const float* Wv   = (const float*)d_in[5];
    const float* Wo   = (const float*)d_in[6];
    const float* ln_g = (const float*)d_in[7];
    const float* ln_b = (const float*)d_in[8];
    const float* W1   = (const float*)d_in[9];
    const float* b1   = (const float*)d_in[10];
    const float* W2   = (const float*)d_in[11];
    const float* b2   = (const float*)d_in[12];
    const float* Wh1  = (const float*)d_in[13];
    const float* bh1  = (const float*)d_in[14];
    const float* Wh2  = (const float*)d_in[15];
    const float* bh2  = (const float*)d_in[16];
    float* out = (float*)d_out;

    float *H, *A, *Q, *Kq, *KH, *KHp, *KVW, *WVWO, *Z, *Zp, *DEN;
    float *PHI, *DEN8, *ATT8, *LN8, *M8, *H8;
    cudaGetSymbolAddress((void**)&H,    g_H);
    cudaGetSymbolAddress((void**)&A,    g_A);
    cudaGetSymbolAddress((void**)&Q,    g_Q);
    cudaGetSymbolAddress((void**)&Kq,   g_K);
    cudaGetSymbolAddress((void**)&KH,   g_KH);
    cudaGetSymbolAddress((void**)&KHp,  g_KHp);
    cudaGetSymbolAddress((void**)&KVW,  g_KVW);
    cudaGetSymbolAddress((void**)&WVWO, g_WVWO);
    cudaGetSymbolAddress((void**)&Z,    g_Z);
    cudaGetSymbolAddress((void**)&Zp,   g_Zp);
    cudaGetSymbolAddress((void**)&DEN,  g_DEN);
    cudaGetSymbolAddress((void**)&PHI,  g_PHI);
    cudaGetSymbolAddress((void**)&DEN8, g_DEN8);
    cudaGetSymbolAddress((void**)&ATT8, g_ATT8);
    cudaGetSymbolAddress((void**)&LN8,  g_LN8);
    cudaGetSymbolAddress((void**)&M8,   g_M8);
    cudaGetSymbolAddress((void**)&H8,   g_H8);

    unsigned *Hh, *Hl, *LNh, *LNl, *Mbh, *Mbl, *Qh, *Ql, *KVTh, *KVTl;
    cudaGetSymbolAddress((void**)&Hh,   g_Hh);   cudaGetSymbolAddress((void**)&Hl,   g_Hl);
    cudaGetSymbolAddress((void**)&LNh,  g_LNh);  cudaGetSymbolAddress((void**)&LNl,  g_LNl);
    cudaGetSymbolAddress((void**)&Mbh,  g_Mbh);  cudaGetSymbolAddress((void**)&Mbl,  g_Mbl);
    cudaGetSymbolAddress((void**)&Qh,   g_Qh);   cudaGetSymbolAddress((void**)&Ql,   g_Ql);
    cudaGetSymbolAddress((void**)&KVTh, g_KVTh); cudaGetSymbolAddress((void**)&KVTl, g_KVTl);

    unsigned *Wqh, *Wql, *Wkh, *Wkl, *W1h, *W1l, *W2h, *W2l;
    cudaGetSymbolAddress((void**)&Wqh, g_Wqh); cudaGetSymbolAddress((void**)&Wql, g_Wql_);
    cudaGetSymbolAddress((void**)&Wkh, g_Wkh); cudaGetSymbolAddress((void**)&Wkl, g_Wkl_);
    cudaGetSymbolAddress((void**)&W1h, g_W1h); cudaGetSymbolAddress((void**)&W1l, g_W1l_);
    cudaGetSymbolAddress((void**)&W2h, g_W2h); cudaGetSymbolAddress((void**)&W2l, g_W2l_);

    const size_t smQK  = gemm_smem(128, 64);
    const size_t smBIG = gemm_smem(128, 256);
    cudaFuncSetAttribute(gemm_pk<128, 64, 32, 32, EPI_PHI, true, true, false>,
                         cudaFuncAttributeMaxDynamicSharedMemorySize, (int)smQK);
    cudaFuncSetAttribute(gemm_pk<128, 64, 32, 32, EPI_PHI, true, false, false>,
                         cudaFuncAttributeMaxDynamicSharedMemorySize, (int)smQK);
    cudaFuncSetAttribute(gemm_pk<128, 256, 64, 64, EPI_DIV, true, false, true>,
                         cudaFuncAttributeMaxDynamicSharedMemorySize, (int)smBIG);
    cudaFuncSetAttribute(gemm_pk<128, 256, 64, 64, EPI_GELU, false, true, false>,
                         cudaFuncAttributeMaxDynamicSharedMemorySize, (int)smBIG);
    cudaFuncSetAttribute(gemm_pk<128, 256, 64, 64, EPI_RES, true, true, false>,
                         cudaFuncAttributeMaxDynamicSharedMemorySize, (int)smBIG);

    // one-time weight prep
    dim3 wt(32, 8);
    {
        WSPack pA;
        pA.e[0] = { Wq, Wqh, Wql, EE, PP, LL * (EE / 32) * (PP / 32) };
        pA.e[1] = { Wk, Wkh, Wkl, EE, PP, LL * (EE / 32) * (PP / 32) };
        pA.e[2] = { W1, W1h, W1l, EE, FF, LL * (EE / 32) * (FF / 32) };
        pA.e[3] = { W2, W2h, W2l, FF, EE, LL * (FF / 32) * (EE / 32) };
        pA.cnt = 4;
        int nA = pA.e[0].nblk + pA.e[1].nblk + pA.e[2].nblk + pA.e[3].nblk;
        wsplit_multi<<<nA, wt>>>(pA);
    }
    wvwo_kernel<<<dim3(EE / 64, EE / 64, LL), 256>>>(Wv, Wo, WVWO);

    embed_kernel<<<MROWS, 128>>>(x, emb, pos, H, Hh, Hl);

    for (int l = 0; l < LL; l++) {
        size_t oQK = (size_t)l * PP * (EE / 2);
        size_t oW1 = (size_t)l * FF * (EE / 2);
        size_t oW2 = (size_t)l * EE * (FF / 2);
        const bool last = (l == LL - 1);

        if (!last) {
            gemm_pk<128, 64, 32, 32, EPI_PHI, true, true, false>
                <<<dim3(PP / 64, MROWS / 128), 256, smQK>>>(
                    MROWS, PP, EE, Hh, Hl, Wqh + oQK, Wql + oQK,
                    nullptr, nullptr, Q, Qh, Ql);
        }
        gemm_pk<128, 64, 32, 32, EPI_PHI, true, false, false>
            <<<dim3(PP / 64, MROWS / 128), 256, smQK>>>(
                MROWS, PP, EE, Hh, Hl, Wkh + oQK, Wkl + oQK,
                nullptr, nullptr, Kq, nullptr, nullptr);

        // KH = phi_k^T @ H (split over S), z
        kv_kernel<<<dim3(EE / 64, BB, NSPLIT), 256>>>(Kq, H, KHp);
        z_kernel<<<dim3(BB, NSPLIT), 256>>>(Kq, Zp);
        reduce_kv<<<(BB * PP * EE) / 256, 256>>>(KHp, KH);
        reduce_z<<<2, 256>>>(Zp, Z);
        // KVW = KH @ (Wv@Wo)  — fuses V projection and Wo into the kv state
        kvwo_kernel<<<dim3(EE / 64, BB), 256>>>(KH, WVWO + (size_t)l * EE * EE, KVW);

        if (!last) {
            wsplit_kernel<<<dim3(EE / 32, PP / 32, BB), wt>>>(KVW, KVTh, KVTl, PP, EE);
            den_kernel<<<MROWS / 8, 256>>>(Q, Z, DEN);

            // A = (phi_q @ KVW) * inv  ( = attn @ Wo, pre-LN )
            gemm_pk<128, 256, 64, 64, EPI_DIV, true, false, true>
                <<<dim3(EE / 256, MROWS / 128), 256, smBIG>>>(
                    MROWS, EE, PP, Qh, Ql, KVTh, KVTl,
                    DEN, nullptr, A, nullptr, nullptr);

            ln_kernel<<<MROWS, 128>>>(A, ln_g + (size_t)l * EE,
                                      ln_b + (size_t)l * EE, LNh, LNl);

            gemm_pk<128, 256, 64, 64, EPI_GELU, false, true, false>
                <<<dim3(FF / 256, MROWS / 128), 256, smBIG>>>(
                    MROWS, FF, EE, LNh, LNl, W1h + oW1, W1l + oW1,
                    b1 + (size_t)l * FF, nullptr, nullptr, Mbh, Mbl);
            gemm_pk<128, 256, 64, 64, EPI_RES, true, true, false>
                <<<dim3(EE / 256, MROWS / 128), 256, smBIG>>>(
                    MROWS, EE, FF, Mbh, Mbl, W2h + oW2, W2l + oW2,
                    b2 + (size_t)l * EE, H, H, Hh, Hl);
        } else {
            const float* Wql3 = Wq + (size_t)l * EE * PP;
            const float* W1l3 = W1 + (size_t)l * EE * FF;
            const float* W2l3 = W2 + (size_t)l * FF * EE;
            last_q_kernel<<<BB, PP>>>(H, Wql3, Z, PHI, DEN8);
            last_attn_kernel<<<BB, 256>>>(PHI, KVW, DEN8, ATT8);
            last_ln_kernel<<<BB, EE>>>(ATT8, ln_g + (size_t)l * EE,
                                       ln_b + (size_t)l * EE, LN8);
            last_mlp1_kernel<<<dim3(FF / 512, BB), 512>>>(LN8, W1l3,
                                                          b1 + (size_t)l * FF, M8);
            last_mlp2_kernel<<<BB, EE>>>(M8, W2l3, b2 + (size_t)l * EE, H, H8);
        }
    }

    head_kernel<<<BB, HH>>>(H8, Wh1, bh1, Wh2, bh2, out);
}

// round 13
// speedup vs baseline: 3.0394x; 1.0050x over previous
#include <cuda_runtime.h>
#include <math.h>

#define BB   8
#define SS   4096
#define EE   512
#define PP   64
#define LL   4
#define HH   256
#define CC   2
#define FF   2048
#define MROWS (BB*SS)
#define NSPLIT 32

enum { EPI_NONE = 0, EPI_PHI = 1, EPI_GELU = 2, EPI_RES = 3, EPI_DIV = 4, EPI_QK = 5 };

// ---------------- scratch ----------------
__device__ float g_H  [(size_t)MROWS*EE];
__device__ float g_A  [(size_t)MROWS*EE];
__device__ float g_QK [(size_t)MROWS*2*PP];    // [row][0:64]=phi_q, [64:128]=phi_k
__device__ float g_KH [(size_t)BB*PP*EE];      // phi_k^T @ H
__device__ float g_KHp[(size_t)NSPLIT*BB*PP*EE];
__device__ float g_KVW[(size_t)BB*PP*EE];      // KH @ WvWo
__device__ float g_WVWO[(size_t)LL*EE*EE];     // Wv @ Wo per layer
__device__ float g_Z  [(size_t)BB*PP];
__device__ float g_Zp [(size_t)NSPLIT*BB*PP];
__device__ float g_DEN[(size_t)MROWS];
// last-layer small buffers
__device__ float g_DEN8[(size_t)BB];
__device__ float g_ATT8[(size_t)BB*EE];
__device__ float g_LN8 [(size_t)BB*EE];
__device__ float g_M8  [(size_t)BB*FF];
__device__ float g_H8  [(size_t)BB*EE];

// packed bf16x2 hi/lo
__device__ unsigned g_Hh [(size_t)MROWS*(EE/2)],  g_Hl [(size_t)MROWS*(EE/2)];
__device__ unsigned g_LNh[(size_t)MROWS*(EE/2)],  g_LNl[(size_t)MROWS*(EE/2)];
__device__ unsigned g_Mbh[(size_t)MROWS*(FF/2)],  g_Mbl[(size_t)MROWS*(FF/2)];
__device__ unsigned g_Qh [(size_t)MROWS*(PP/2)],  g_Ql [(size_t)MROWS*(PP/2)];
__device__ unsigned g_KVTh[(size_t)BB*EE*(PP/2)], g_KVTl[(size_t)BB*EE*(PP/2)];
// bf16 weights [N][K/2]
__device__ unsigned g_WQKh[(size_t)LL*2*PP*(EE/2)], g_WQKl[(size_t)LL*2*PP*(EE/2)];
__device__ unsigned g_W1h[(size_t)LL*FF*(EE/2)],  g_W1l_[(size_t)LL*FF*(EE/2)];
__device__ unsigned g_W2h[(size_t)LL*EE*(FF/2)],  g_W2l_[(size_t)LL*EE*(FF/2)];

// ---------------- helpers ----------------
__device__ __forceinline__ void cp_async16(void* smem, const void* gmem) {
    unsigned sa = (unsigned)__cvta_generic_to_shared(smem);
    asm volatile("cp.async.cg.shared.global [%0], [%1], 16;" :: "r"(sa), "l"(gmem));
}
__device__ __forceinline__ void cp_commit() { asm volatile("cp.async.commit_group;"); }
template<int N>
__device__ __forceinline__ void cp_wait() {
    asm volatile("cp.async.wait_group %0;" :: "n"(N));
}

__device__ __forceinline__ void split2(float x, float y, unsigned& hi, unsigned& lo) {
    asm("cvt.rn.bf16x2.f32 %0, %1, %2;" : "=r"(hi) : "f"(y), "f"(x));
    float hx = __uint_as_float(hi << 16);
    float hy = __uint_as_float(hi & 0xFFFF0000u);
    asm("cvt.rn.bf16x2.f32 %0, %1, %2;" : "=r"(lo) : "f"(y - hy), "f"(x - hx));
}

__device__ __forceinline__ void mma_bf16(float c[4], const unsigned a[4], const unsigned b[2]) {
    asm volatile(
        "mma.sync.aligned.m16n8k16.row.col.f32.bf16.bf16.f32 "
        "{%0,%1,%2,%3}, {%4,%5,%6,%7}, {%8,%9}, {%0,%1,%2,%3};"
        : "+f"(c[0]), "+f"(c[1]), "+f"(c[2]), "+f"(c[3])
        : "r"(a[0]), "r"(a[1]), "r"(a[2]), "r"(a[3]), "r"(b[0]), "r"(b[1]));
}

__device__ __forceinline__ float gelu_f(float v) {
    float u = 0.7978845608028654f * (v + 0.044715f * v * v * v);
    return 0.5f * v * (1.f + tanhf(u));
}

// ---------------- transpose + split ----------------
__device__ __forceinline__ void wsplit_tile(const float* Wl, unsigned* Th, unsigned* Tl,
                                            int K, int N, int k0, int n0, float (*t)[33]) {
    int tx = threadIdx.x, ty = threadIdx.y;
    #pragma unroll
    for (int i = 0; i < 4; i++)
        t[ty + i * 8][tx] = Wl[(size_t)(k0 + ty + i * 8) * N + n0 + tx];
    __syncthreads();
    int tid = ty * 32 + tx;
    #pragma unroll
    for (int i = 0; i < 2; i++) {
        int w = tid + i * 256;
        int n = w >> 4, kp = w & 15;
        unsigned h, l;
        split2(t[2 * kp][n], t[2 * kp + 1][n], h, l);
        size_t o = (size_t)(n0 + n) * (K >> 1) + (k0 >> 1) + kp;
        Th[o] = h; Tl[o] = l;
    }
}

// per-batch/layer version; lstr = layer/batch stride (words) of output
__global__ void wsplit_kernel(const float* __restrict__ W,
                              unsigned* __restrict__ Th, unsigned* __restrict__ Tl,
                              int K, int N, size_t in_str, size_t lstr) {
    __shared__ float t[32][33];
    wsplit_tile(W + (size_t)blockIdx.z * in_str,
                Th + (size_t)blockIdx.z * lstr,
                Tl + (size_t)blockIdx.z * lstr,
                K, N, blockIdx.y * 32, blockIdx.x * 32, t);
}

struct WSEntry { const float* W; unsigned* Th; unsigned* Tl; int K; int N;
                 size_t lstr; int nblk; };
struct WSPack  { WSEntry e[4]; int cnt; };
__global__ void wsplit_multi(WSPack p) {
    __shared__ float t[32][33];
    int bid = blockIdx.x, i = 0;
    while (i + 1 < p.cnt && bid >= p.e[i].nblk) { bid -= p.e[i].nblk; i++; }
    WSEntry E = p.e[i];
    int tiles_n = E.N / 32, tpl = tiles_n * (E.K / 32);
    int layer = bid / tpl, rem = bid % tpl;
    wsplit_tile(E.W + (size_t)layer * E.K * E.N,
                E.Th + (size_t)layer * E.lstr,
                E.Tl + (size_t)layer * E.lstr,
                E.K, E.N, (rem / tiles_n) * 32, (rem % tiles_n) * 32, t);
}

// ---------------- WvWo = Wv @ Wo (per layer, fp32, one-time) ----------------
__global__ void __launch_bounds__(256)
wvwo_kernel(const float* __restrict__ Wv, const float* __restrict__ Wo,
            float* __restrict__ WVWO) {
    int l = blockIdx.z;
    const float* Av = Wv + (size_t)l * EE * EE;
    const float* Bo = Wo + (size_t)l * EE * EE;
    float* C = WVWO + (size_t)l * EE * EE;
    int k0 = blockIdx.y * 64, n0 = blockIdx.x * 64;
    __shared__ float As[32][65];
    __shared__ float Bs[32][64];
    int tid = threadIdx.x, tx = tid % 16, ty = tid / 16;
    float acc[4][4];
    #pragma unroll
    for (int i = 0; i < 4; i++)
        #pragma unroll
        for (int j = 0; j < 4; j++) acc[i][j] = 0.f;
    for (int e0 = 0; e0 < EE; e0 += 32) {
        #pragma unroll
        for (int i = 0; i < 8; i++) {
            int idx = tid + i * 256;
            int r = idx / 32, c = idx % 32;
            As[c][r] = Av[(size_t)(k0 + r) * EE + e0 + c];
        }
        #pragma unroll
        for (int i = 0; i < 2; i++) {
            int idx = tid + i * 256;
            int r = idx / 16, c4 = idx % 16;
            *(float4*)&Bs[r][c4 * 4] =
                *(const float4*)(Bo + (size_t)(e0 + r) * EE + n0 + c4 * 4);
        }
        __syncthreads();
        #pragma unroll
        for (int e = 0; e < 32; e++) {
            float ra[4], rb[4];
            #pragma unroll
            for (int i = 0; i < 4; i++) ra[i] = As[e][ty * 4 + i];
            #pragma unroll
            for (int j = 0; j < 4; j++) rb[j] = Bs[e][tx * 4 + j];
            #pragma unroll
            for (int i = 0; i < 4; i++)
                #pragma unroll
                for (int j = 0; j < 4; j++)
                    acc[i][j] = fmaf(ra[i], rb[j], acc[i][j]);
        }
        __syncthreads();
    }
    #pragma unroll
    for (int i = 0; i < 4; i++)
        #pragma unroll
        for (int j = 0; j < 4; j++)
            C[(size_t)(k0 + ty * 4 + i) * EE + n0 + tx * 4 + j] = acc[i][j];
}

// ---------------- KVW = KH @ WvWo (per batch, fp32) ----------------
__global__ void __launch_bounds__(256)
kvwo_kernel(const float* __restrict__ KH, const float* __restrict__ WVWOl,
            float* __restrict__ KVW) {
    int b = blockIdx.y, n0 = blockIdx.x * 64;
    const float* Ak = KH + (size_t)b * PP * EE;
    float* C = KVW + (size_t)b * PP * EE;
    __shared__ float As[32][65];
    __shared__ float Bs[32][64];
    int tid = threadIdx.x, tx = tid % 16, ty = tid / 16;
    float acc[4][4];
    #pragma unroll
    for (int i = 0; i < 4; i++)
        #pragma unroll
        for (int j = 0; j < 4; j++) acc[i][j] = 0.f;
    for (int e0 = 0; e0 < EE; e0 += 32) {
        #pragma unroll
        for (int i = 0; i < 8; i++) {
            int idx = tid + i * 256;
            int r = idx / 32, c = idx % 32;
            As[c][r] = Ak[(size_t)r * EE + e0 + c];
        }
        #pragma unroll
        for (int i = 0; i < 2; i++) {
            int idx = tid + i * 256;
            int r = idx / 16, c4 = idx % 16;
            *(float4*)&Bs[r][c4 * 4] =
                *(const float4*)(WVWOl + (size_t)(e0 + r) * EE + n0 + c4 * 4);
        }
        __syncthreads();
        #pragma unroll
        for (int e = 0; e < 32; e++) {
            float ra[4], rb[4];
            #pragma unroll
            for (int i = 0; i < 4; i++) ra[i] = As[e][ty * 4 + i];
            #pragma unroll
            for (int j = 0; j < 4; j++) rb[j] = Bs[e][tx * 4 + j];
            #pragma unroll
            for (int i = 0; i < 4; i++)
                #pragma unroll
                for (int j = 0; j < 4; j++)
                    acc[i][j] = fmaf(ra[i], rb[j], acc[i][j]);
        }
        __syncthreads();
    }
    #pragma unroll
    for (int i = 0; i < 4; i++)
        #pragma unroll
        for (int j = 0; j < 4; j++)
            C[(size_t)(ty * 4 + i) * EE + n0 + tx * 4 + j] = acc[i][j];
}

// ---------------- embedding ----------------
__global__ void embed_kernel(const int* __restrict__ x, const float* __restrict__ emb,
                             const float* __restrict__ pos, float* __restrict__ H,
                             unsigned* __restrict__ Hh, unsigned* __restrict__ Hl) {
    int row = blockIdx.x, s = row & (SS - 1), tok = x[row];
    const float4* e4 = (const float4*)(emb + (size_t)tok * EE);
    const float4* p4 = (const float4*)(pos + (size_t)s * EE);
    int t = threadIdx.x;
    float4 a = e4[t], b = p4[t];
    float4 o = make_float4(a.x + b.x, a.y + b.y, a.z + b.z, a.w + b.w);
    ((float4*)(H + (size_t)row * EE))[t] = o;
    unsigned h0, l0, h1, l1;
    split2(o.x, o.y, h0, l0);
    split2(o.z, o.w, h1, l1);
    size_t wo = (size_t)row * (EE / 2) + 2 * t;
    Hh[wo] = h0; Hh[wo + 1] = h1;
    Hl[wo] = l0; Hl[wo + 1] = l1;
}

// ---------------- bf16x2 split GEMM ----------------
template<int BM, int BN, int WM, int WN, int EPI, bool WF32, bool WPACK, bool BATCHB>
__global__ void __launch_bounds__((BM/WM)*(BN/WN)*32)
gemm_pk(int M, int N, int K,
        const unsigned* __restrict__ Ah, const unsigned* __restrict__ Al,
        const unsigned* __restrict__ Bh, const unsigned* __restrict__ Bl,
        const float* __restrict__ bias, const float* __restrict__ res,
        float* __restrict__ C, unsigned* __restrict__ Ch, unsigned* __restrict__ Cl)
{
    constexpr int WARPS_N = BN / WN;
    constexpr int NTH = (BM / WM) * WARPS_N * 32;
    constexpr int LDW = 20;
    constexpr int ASZ = BM * LDW, BSZ = BN * LDW;
    constexpr int MT = WM / 16, NT = WN / 8;
    constexpr int A_CNT = BM * 4 / NTH, B_CNT = BN * 4 / NTH;

    extern __shared__ unsigned smw[];
    unsigned* Ash = smw;
    unsigned* Asl = smw + 3 * ASZ;
    unsigned* Bsh = smw + 6 * ASZ;
    unsigned* Bsl = smw + 6 * ASZ + 3 * BSZ;

    const int tid = threadIdx.x, lane = tid & 31, warp = tid >> 5;
    const int wm = warp / WARPS_N, wn = warp % WARPS_N;
    const int lr = lane >> 2, lc = lane & 3;
    const int row0 = blockIdx.y * BM, col0 = blockIdx.x * BN;
    const int KW = K >> 1, KT = K / 32;

    const unsigned* Bhp = Bh;
    const unsigned* Blp = Bl;
    if (BATCHB) {
        size_t boff = (size_t)(blockIdx.y / (SS / BM)) * N * KW;
        Bhp += boff; Blp += boff;
    }

    float acc[MT][NT][4];
    #pragma unroll
    for (int i = 0; i < MT; i++)
        #pragma unroll
        for (int j = 0; j < NT; j++)
            #pragma unroll
            for (int q = 0; q < 4; q++) acc[i][j][q] = 0.f;

    auto issue = [&](int kt, int st) {
        int goff = kt * 16;
        #pragma unroll
        for (int i = 0; i < A_CNT; i++) {
            int idx = tid + i * NTH;
            int r = idx >> 2, c = (idx & 3) * 4;
            size_t g = (size_t)(row0 + r) * KW + goff + c;
            cp_async16(Ash + st * ASZ + r * LDW + c, Ah + g);
            cp_async16(Asl + st * ASZ + r * LDW + c, Al + g);
        }
        #pragma unroll
        for (int i = 0; i < B_CNT; i++) {
            int idx = tid + i * NTH;
            int r = idx >> 2, c = (idx & 3) * 4;
            size_t g = (size_t)(col0 + r) * KW + goff + c;
            cp_async16(Bsh + st * BSZ + r * LDW + c, Bhp + g);
            cp_async16(Bsl + st * BSZ + r * LDW + c, Blp + g);
        }
    };

    auto compute = [&](int st) {
        const unsigned* Ah_ = Ash + st * ASZ;
        const unsigned* Al_ = Asl + st * ASZ;
        const unsigned* Bh_ = Bsh + st * BSZ;
        const unsigned* Bl_ = Bsl + st * BSZ;
        #pragma unroll
        for (int kk = 0; kk < 2; kk++) {
            unsigned ah[MT][4], al[MT][4];
            #pragma unroll
            for (int i = 0; i < MT; i++) {
                int base = (wm * WM + i * 16 + lr) * LDW + kk * 8 + lc;
                ah[i][0] = Ah_[base];               al[i][0] = Al_[base];
                ah[i][1] = Ah_[base + 8 * LDW];     al[i][1] = Al_[base + 8 * LDW];
                ah[i][2] = Ah_[base + 4];           al[i][2] = Al_[base + 4];
                ah[i][3] = Ah_[base + 8 * LDW + 4]; al[i][3] = Al_[base + 8 * LDW + 4];
            }
            #pragma unroll
            for (int j = 0; j < NT; j++) {
                int bbase = (wn * WN + j * 8 + lr) * LDW + kk * 8 + lc;
                unsigned bh[2], bl[2];
                bh[0] = Bh_[bbase];     bl[0] = Bl_[bbase];
                bh[1] = Bh_[bbase + 4]; bl[1] = Bl_[bbase + 4];
                #pragma unroll
                for (int i = 0; i < MT; i++) {
                    mma_bf16(acc[i][j], ah[i], bh);
                    mma_bf16(acc[i][j], ah[i], bl);
                    mma_bf16(acc[i][j], al[i], bh);
                }
            }
        }
    };

    issue(0, 0); cp_commit();
    issue(1, 1); cp_commit();
    cp_wait<1>();
    __syncthreads();
    for (int kt = 0; kt < KT; kt++) {
        if (kt + 2 < KT) issue(kt + 2, (kt + 2) % 3);
        cp_commit();
        compute(kt % 3);
        cp_wait<1>();
        __syncthreads();
    }

    auto epi = [&](float v, int rr, int cc) -> float {
        if (EPI == EPI_PHI || EPI == EPI_QK) return v > 0.f ? v + 1.f : expf(v);
        if (EPI == EPI_GELU) return gelu_f(v + bias[cc]);
        if (EPI == EPI_RES)  return v + bias[cc] + res[(size_t)rr * N + cc];
        if (EPI == EPI_DIV)  return v * bias[rr];
        return v;
    };

    #pragma unroll
    for (int i = 0; i < MT; i++) {
        #pragma unroll
        for (int j = 0; j < NT; j++) {
            int rr = row0 + wm * WM + i * 16 + lr;
            int cc = col0 + wn * WN + j * 8 + 2 * lc;
            float e00 = epi(acc[i][j][0], rr, cc);
            float e01 = epi(acc[i][j][1], rr, cc + 1);
            float e10 = epi(acc[i][j][2], rr + 8, cc);
            float e11 = epi(acc[i][j][3], rr + 8, cc + 1);
            if (WF32) {
                *(float2*)(C + (size_t)rr * N + cc)       = make_float2(e00, e01);
                *(float2*)(C + (size_t)(rr + 8) * N + cc) = make_float2(e10, e11);
            }
            if (WPACK) {
                const int halfN = (EPI == EPI_QK) ? PP : N;
                if (EPI != EPI_QK || cc < PP) {
                    unsigned h, l;
                    split2(e00, e01, h, l);
                    size_t w0 = (size_t)rr * (halfN >> 1) + (cc >> 1);
                    Ch[w0] = h; Cl[w0] = l;
                    split2(e10, e11, h, l);
                    size_t w1 = (size_t)(rr + 8) * (halfN >> 1) + (cc >> 1);
                    Ch[w1] = h; Cl[w1] = l;
                }
            }
        }
    }
}

// ---------------- KH partials: phi_k^T @ H, split over S ----------------
// phi_k lives in QK[row][64:128] (row stride 128)
__global__ void __launch_bounds__(256)
kv_kernel(const float* __restrict__ QK, const float* __restrict__ Hm,
          float* __restrict__ KHp)
{
    int b = blockIdx.y, f0 = blockIdx.x * 64, sp = blockIdx.z;
    const float* Kb = QK + (size_t)b * SS * 2 * PP + PP;
    const float* Vb = Hm + (size_t)b * SS * EE;
    __shared__ float Ks[32 * 64];
    __shared__ float Vs[32 * 64];
    int tid = threadIdx.x, tx = tid % 16, ty = tid / 16;
    float acc[4][4];
    #pragma unroll
    for (int i = 0; i < 4; i++)
        #pragma unroll
        for (int j = 0; j < 4; j++) acc[i][j] = 0.f;
    int sbeg = sp * (SS / NSPLIT), send = sbeg + (SS / NSPLIT);
    for (int s0 = sbeg; s0 < send; s0 += 32) {
        #pragma unroll
        for (int i = 0; i < 2; i++) {
            int idx = tid + i * 256;
            int r = idx / 16, c4 = idx % 16;
            *(float4*)(Ks + r * 64 + c4 * 4) =
                *(const float4*)(Kb + (size_t)(s0 + r) * 2 * PP + c4 * 4);
            *(float4*)(Vs + r * 64 + c4 * 4) =
                *(const float4*)(Vb + (size_t)(s0 + r) * EE + f0 + c4 * 4);
        }
        __syncthreads();
        #pragma unroll
        for (int k = 0; k < 32; k++) {
            float rp[4], rv[4];
            #pragma unroll
            for (int i = 0; i < 4; i++) rp[i] = Ks[k * 64 + ty * 4 + i];
            #pragma unroll
            for (int j = 0; j < 4; j++) rv[j] = Vs[k * 64 + tx * 4 + j];
            #pragma unroll
            for (int i = 0; i < 4; i++)
                #pragma unroll
                for (int j = 0; j < 4; j++)
                    acc[i][j] = fmaf(rp[i], rv[j], acc[i][j]);
        }
        __syncthreads();
    }
    float* out = KHp + (size_t)sp * BB * PP * EE;
    #pragma unroll
    for (int i = 0; i < 4; i++)
        #pragma unroll
        for (int j = 0; j < 4; j++)
            out[((size_t)b * PP + ty * 4 + i) * EE + f0 + tx * 4 + j] = acc[i][j];
}

__global__ void reduce_kv(const float* __restrict__ KHp, float* __restrict__ KH) {
    size_t idx = (size_t)blockIdx.x * 256 + threadIdx.x;
    float s = 0.f;
    #pragma unroll
    for (int sp = 0; sp < NSPLIT; sp++) s += KHp[(size_t)sp * BB * PP * EE + idx];
    KH[idx] = s;
}

__global__ void z_kernel(const float* __restrict__ QK, float* __restrict__ Zp) {
    int b = blockIdx.x, sp = blockIdx.y;
    int tid = threadIdx.x, p = tid & 63, g = tid >> 6;
    const float* Kb = QK + (size_t)b * SS * 2 * PP + PP;
    float acc = 0.f;
    int sbeg = sp * (SS / NSPLIT), send = sbeg + (SS / NSPLIT);
    for (int s = sbeg + g; s < send; s += 4) acc += Kb[(size_t)s * 2 * PP + p];
    __shared__ float smem[256];
    smem[tid] = acc;
    __syncthreads();
    if (g == 0)
        Zp[(size_t)sp * BB * PP + b * PP + p] =
            smem[p] + smem[64 + p] + smem[128 + p] + smem[192 + p];
}

__global__ void reduce_z(const float* __restrict__ Zp, float* __restrict__ Z) {
    int idx = blockIdx.x * 256 + threadIdx.x;
    if (idx < BB * PP) {
        float s = 0.f;
        #pragma unroll
        for (int sp = 0; sp < NSPLIT; sp++) s += Zp[sp * BB * PP + idx];
        Z[idx] = s;
    }
}

__global__ void den_kernel(const float* __restrict__ QK, const float* __restrict__ Z,
                           float* __restrict__ inv) {
    int row = blockIdx.x * 8 + (threadIdx.x >> 5);
    int lane = threadIdx.x & 31;
    int b = row >> 12;
    const float* q = QK + (size_t)row * 2 * PP;
    const float* z = Z + b * PP;
    float s = q[lane] * z[lane] + q[lane + 32] * z[lane + 32];
    #pragma unroll
    for (int o = 16; o; o >>= 1) s += __shfl_xor_sync(0xffffffffu, s, o);
    if (lane == 0) inv[row] = 1.f / (s + 1e-6f);
}

// ---------------- layernorm: fp32 in -> packed out ----------------
__global__ void ln_kernel(const float* __restrict__ X,
                          const float* __restrict__ gam, const float* __restrict__ bet,
                          unsigned* __restrict__ Oh, unsigned* __restrict__ Ol) {
    int row = blockIdx.x;
    const float* xr = X + (size_t)row * EE;
    int tid = threadIdx.x;
    float4 v = ((const float4*)xr)[tid];
    float s = v.x + v.y + v.z + v.w;
    float q = v.x * v.x + v.y * v.y + v.z * v.z + v.w * v.w;
    #pragma unroll
    for (int o = 16; o; o >>= 1) {
        s += __shfl_xor_sync(0xffffffffu, s, o);
        q += __shfl_xor_sync(0xffffffffu, q, o);
    }
    __shared__ float ss[4], qq[4];
    int w = tid >> 5;
    if ((tid & 31) == 0) { ss[w] = s; qq[w] = q; }
    __syncthreads();
    s = ss[0] + ss[1] + ss[2] + ss[3];
    q = qq[0] + qq[1] + qq[2] + qq[3];
    float mu = s * (1.f / EE);
    float var = q * (1.f / EE) - mu * mu;
    float inv = rsqrtf(var + 1e-5f);
    float4 g4 = ((const float4*)gam)[tid];
    float4 b4 = ((const float4*)bet)[tid];
    float o0 = (v.x - mu) * inv * g4.x + b4.x;
    float o1 = (v.y - mu) * inv * g4.y + b4.y;
    float o2 = (v.z - mu) * inv * g4.z + b4.z;
    float o3 = (v.w - mu) * inv * g4.w + b4.w;
    unsigned h0, l0, h1, l1;
    split2(o0, o1, h0, l0);
    split2(o2, o3, h1, l1);
    size_t wo = (size_t)row * (EE / 2) + 2 * tid;
    Oh[wo] = h0; Oh[wo + 1] = h1;
    Ol[wo] = l0; Ol[wo + 1] = l1;
}

// ---------------- last-layer (s=0 only) fp32 chain ----------------
// den from precomputed phi_q (QK rows at s=0)
__global__ void last_den_kernel(const float* __restrict__ QK,
                                const float* __restrict__ Z,
                                float* __restrict__ DEN8) {
    int b = blockIdx.x, p = threadIdx.x;           // 64 threads
    const float* q = QK + (size_t)b * SS * 2 * PP;  // row s=0
    __shared__ float sm[PP];
    sm[p] = q[p] * Z[b * PP + p];
    __syncthreads();
    if (p == 0) {
        float s = 0.f;
        for (int i = 0; i < PP; i++) s += sm[i];
        DEN8[b] = 1.f / (s + 1e-6f);
    }
}

// ATT8 = phi_q @ KVW * inv (= attn @ Wo via WvWo fusion)
__global__ void last_attn_kernel(const float* __restrict__ QK,
                                 const float* __restrict__ KVW,
                                 const float* __restrict__ DEN8,
                                 float* __restrict__ ATT8) {
    int b = blockIdx.x, tid = threadIdx.x;
    __shared__ float ph[PP];
    if (tid < PP) ph[tid] = QK[(size_t)b * SS * 2 * PP + tid];
    __syncthreads();
    float inv = DEN8[b];
    for (int f = tid; f < EE; f += 256) {
        float a = 0.f;
        for (int p = 0; p < PP; p++)
            a = fmaf(ph[p], KVW[((size_t)b * PP + p) * EE + f], a);
        ATT8[b * EE + f] = a * inv;
    }
}

__global__ void last_ln_kernel(const float* __restrict__ ATT8,
                               const float* __restrict__ gam,
                               const float* __restrict__ bet,
                               float* __restrict__ LN8) {
    int b = blockIdx.x, e = threadIdx.x;
    float a = ATT8[b * EE + e];
    float s = a, q = a * a;
    #pragma unroll
    for (int o = 16; o; o >>= 1) {
        s += __shfl_xor_sync(0xffffffffu, s, o);
        q += __shfl_xor_sync(0xffffffffu, q, o);
    }
    __shared__ float ssum[16], ssq[16];
    int w = e >> 5;
    if ((e & 31) == 0) { ssum[w] = s; ssq[w] = q; }
    __syncthreads();
    float S = 0.f, Qq = 0.f;
    #pragma unroll
    for (int i = 0; i < 16; i++) { S += ssum[i]; Qq += ssq[i]; }
    float mu = S * (1.f / EE);
    float var = Qq * (1.f / EE) - mu * mu;
    float inv = rsqrtf(var + 1e-5f);
    LN8[b * EE + e] = (a - mu) * inv * gam[e] + bet[e];
}

__global__ void last_mlp1_kernel(const float* __restrict__ LN8,
                                 const float* __restrict__ W1,
                                 const float* __restrict__ b1,
                                 float* __restrict__ M8) {
    int b = blockIdx.y, j = blockIdx.x * 512 + threadIdx.x;
    __shared__ float ln[EE];
    for (int i = threadIdx.x; i < EE; i += 512) ln[i] = LN8[b * EE + i];
    __syncthreads();
    float acc = b1[j];
    for (int e = 0; e < EE; e++) acc = fmaf(ln[e], W1[(size_t)e * FF + j], acc);
    M8[b * FF + j] = gelu_f(acc);
}

__global__ void last_mlp2_kernel(const float* __restrict__ M8,
                                 const float* __restrict__ W2,
                                 const float* __restrict__ b2,
                                 const float* __restrict__ H,
                                 float* __restrict__ H8) {
    int b = blockIdx.x, e = threadIdx.x;
    float acc = b2[e];
    const float* m = M8 + (size_t)b * FF;
    for (int j = 0; j < FF; j++) acc = fmaf(m[j], W2[(size_t)j * EE + e], acc);
    H8[b * EE + e] = acc + H[(size_t)b * SS * EE + e];
}

// ---------------- head ----------------
__global__ void head_kernel(const float* __restrict__ H8, const float* __restrict__ Wh1,
                            const float* __restrict__ bh1, const float* __restrict__ Wh2,
                            const float* __restrict__ bh2, float* __restrict__ out) {
    int b = blockIdx.x, tid = threadIdx.x;
    const float* hr = H8 + (size_t)b * EE;
    float acc = bh1[tid];
    for (int e = 0; e < EE; e++) acc = fmaf(hr[e], Wh1[e * HH + tid], acc);
    acc = fmaxf(acc, 0.f);
    __shared__ float hid[HH];
    hid[tid] = acc;
    __syncthreads();
    if (tid < CC) {
        float a = bh2[tid];
        for (int h = 0; h < HH; h++) a = fmaf(hid[h], Wh2[h * CC + tid], a);
        out[b * CC + tid] = a;
    }
}

// ---------------- launch ----------------
static size_t gemm_smem(int BM, int BN) {
    return (size_t)(3 * (BM * 20 * 2 + BN * 20 * 2)) * 4;
}

extern "C" void kernel_launch(void* const* d_in, const int* in_sizes, int n_in,
                              void* d_out, int out_size) {
    const int*   x    = (const int*)  d_in[0];
    const float* emb  = (const float*)d_in[1];
    const float* pos  = (const float*)d_in[2];
    const float* Wq   = (const float*)d_in[3];
    const float* Wk   = (const float*)d_in[4];
    const float* Wv   = (const float*)d_in[5];
    const float* Wo   = (const float*)d_in[6];
    const float* ln_g = (const float*)d_in[7];
    const float* ln_b = (const float*)d_in[8];
    const float* W1   = (const float*)d_in[9];
    const float* b1   = (const float*)d_in[10];
    const float* W2   = (const float*)d_in[11];
    const float* b2   = (const float*)d_in[12];
    const float* Wh1  = (const float*)d_in[13];
    const float* bh1  = (const float*)d_in[14];
    const float* Wh2  = (const float*)d_in[15];
    const float* bh2  = (const float*)d_in[16];
    float* out = (float*)d_out;

    float *H, *A, *QK, *KH, *KHp, *KVW, *WVWO, *Z, *Zp, *DEN;
    float *DEN8, *ATT8, *LN8, *M8, *H8;
    cudaGetSymbolAddress((void**)&H,    g_H);
    cudaGetSymbolAddress((void**)&A,    g_A);
    cudaGetSymbolAddress((void**)&QK,   g_QK);
    cudaGetSymbolAddress((void**)&KH,   g_KH);
    cudaGetSymbolAddress((void**)&KHp,  g_KHp);
    cudaGetSymbolAddress((void**)&KVW,  g_KVW);
    cudaGetSymbolAddress((void**)&WVWO, g_WVWO);
    cudaGetSymbolAddress((void**)&Z,    g_Z);
    cudaGetSymbolAddress((void**)&Zp,   g_Zp);
    cudaGetSymbolAddress((void**)&DEN,  g_DEN);
    cudaGetSymbolAddress((void**)&DEN8, g_DEN8);
    cudaGetSymbolAddress((void**)&ATT8, g_ATT8);
    cudaGetSymbolAddress((void**)&LN8,  g_LN8);
    cudaGetSymbolAddress((void**)&M8,   g_M8);
    cudaGetSymbolAddress((void**)&H8,   g_H8);

    unsigned *Hh, *Hl, *LNh, *LNl, *Mbh, *Mbl, *Qh, *Ql, *KVTh, *KVTl;
    cudaGetSymbolAddress((void**)&Hh,   g_Hh);   cudaGetSymbolAddress((void**)&Hl,   g_Hl);
    cudaGetSymbolAddress((void**)&LNh,  g_LNh);  cudaGetSymbolAddress((void**)&LNl,  g_LNl);
    cudaGetSymbolAddress((void**)&Mbh,  g_Mbh);  cudaGetSymbolAddress((void**)&Mbl,  g_Mbl);
    cudaGetSymbolAddress((void**)&Qh,   g_Qh);   cudaGetSymbolAddress((void**)&Ql,   g_Ql);
    cudaGetSymbolAddress((void**)&KVTh, g_KVTh); cudaGetSymbolAddress((void**)&KVTl, g_KVTl);

    unsigned *WQKh, *WQKl, *W1h, *W1l, *W2h, *W2l;
    cudaGetSymbolAddress((void**)&WQKh, g_WQKh); cudaGetSymbolAddress((void**)&WQKl, g_WQKl);
    cudaGetSymbolAddress((void**)&W1h,  g_W1h);  cudaGetSymbolAddress((void**)&W1l,  g_W1l_);
    cudaGetSymbolAddress((void**)&W2h,  g_W2h);  cudaGetSymbolAddress((void**)&W2l,  g_W2l_);

    const size_t smQK  = gemm_smem(128, 128);
    const size_t smBIG = gemm_smem(128, 256);
    cudaFuncSetAttribute(gemm_pk<128, 128, 64, 32, EPI_QK, true, true, false>,
                         cudaFuncAttributeMaxDynamicSharedMemorySize, (int)smQK);
    cudaFuncSetAttribute(gemm_pk<128, 256, 64, 64, EPI_DIV, true, false, true>,
                         cudaFuncAttributeMaxDynamicSharedMemorySize, (int)smBIG);
    cudaFuncSetAttribute(gemm_pk<128, 256, 64, 64, EPI_GELU, false, true, false>,
                         cudaFuncAttributeMaxDynamicSharedMemorySize, (int)smBIG);
    cudaFuncSetAttribute(gemm_pk<128, 256, 64, 64, EPI_RES, true, true, false>,
                         cudaFuncAttributeMaxDynamicSharedMemorySize, (int)smBIG);

    // one-time weight prep: WQK combined [128][K/2] per layer (rows 0-63 Wq, 64-127 Wk)
    dim3 wt(32, 8);
    {
        WSPack pA;
        const size_t qkL = (size_t)2 * PP * (EE / 2);
        pA.e[0] = { Wq, WQKh, WQKl, EE, PP, qkL, LL * (EE / 32) * (PP / 32) };
        pA.e[1] = { Wk, WQKh + (size_t)PP * (EE / 2), WQKl + (size_t)PP * (EE / 2),
                    EE, PP, qkL, LL * (EE / 32) * (PP / 32) };
        pA.e[2] = { W1, W1h, W1l, EE, FF, (size_t)FF * (EE / 2), LL * (EE / 32) * (FF / 32) };
        pA.e[3] = { W2, W2h, W2l, FF, EE, (size_t)EE * (FF / 2), LL * (FF / 32) * (EE / 32) };
        pA.cnt = 4;
        int nA = pA.e[0].nblk + pA.e[1].nblk + pA.e[2].nblk + pA.e[3].nblk;
        wsplit_multi<<<nA, wt>>>(pA);
    }
    wvwo_kernel<<<dim3(EE / 64, EE / 64, LL), 256>>>(Wv, Wo, WVWO);

    embed_kernel<<<MROWS, 128>>>(x, emb, pos, H, Hh, Hl);

    for (int l = 0; l < LL; l++) {
        size_t oQK = (size_t)l * 2 * PP * (EE / 2);
        size_t oW1 = (size_t)l * FF * (EE / 2);
        size_t oW2 = (size_t)l * EE * (FF / 2);
        const bool last = (l == LL - 1);

        // fused phi_q | phi_k projection -> QK [row][128] + packed phi_q
        gemm_pk<128, 128, 64, 32, EPI_QK, true, true, false>
            <<<dim3(1, MROWS / 128), 256, smQK>>>(
                MROWS, 2 * PP, EE, Hh, Hl, WQKh + oQK, WQKl + oQK,
                nullptr, nullptr, QK, Qh, Ql);

        kv_kernel<<<dim3(EE / 64, BB, NSPLIT), 256>>>(QK, H, KHp);
        z_kernel<<<dim3(BB, NSPLIT), 256>>>(QK, Zp);
        reduce_kv<<<(BB * PP * EE) / 256, 256>>>(KHp, KH);
        reduce_z<<<2, 256>>>(Zp, Z);
        kvwo_kernel<<<dim3(EE / 64, BB), 256>>>(KH, WVWO + (size_t)l * EE * EE, KVW);

        if (!last) {
            wsplit_kernel<<<dim3(EE / 32, PP / 32, BB), wt>>>(
                KVW, KVTh, KVTl, PP, EE,
                (size_t)PP * EE, (size_t)EE * (PP / 2));
            den_kernel<<<MROWS / 8, 256>>>(QK, Z, DEN);

            gemm_pk<128, 256, 64, 64, EPI_DIV, true, false, true>
                <<<dim3(EE / 256, MROWS / 128), 256, smBIG>>>(
                    MROWS, EE, PP, Qh, Ql, KVTh, KVTl,
                    DEN, nullptr, A, nullptr, nullptr);

            ln_kernel<<<MROWS, 128>>>(A, ln_g + (size_t)l * EE,
                                      ln_b + (size_t)l * EE, LNh, LNl);

            gemm_pk<128, 256, 64, 64, EPI_GELU, false, true, false>
                <<<dim3(FF / 256, MROWS / 128), 256, smBIG>>>(
                    MROWS, FF, EE, LNh, LNl, W1h + oW1, W1l + oW1,
                    b1 + (size_t)l * FF, nullptr, nullptr, Mbh, Mbl);
            gemm_pk<128, 256, 64, 64, EPI_RES, true, true, false>
                <<<dim3(EE / 256, MROWS / 128), 256, smBIG>>>(
                    MROWS, EE, FF, Mbh, Mbl, W2h + oW2, W2l + oW2,
                    b2 + (size_t)l * EE, H, H, Hh, Hl);
        } else {
            const float* W1l3 = W1 + (size_t)l * EE * FF;
            const float* W2l3 = W2 + (size_t)l * FF * EE;
            last_den_kernel<<<BB, PP>>>(QK, Z, DEN8);
            last_attn_kernel<<<BB, 256>>>(QK, KVW, DEN8, ATT8);
            last_ln_kernel<<<BB, EE>>>(ATT8, ln_g + (size_t)l * EE,
                                       ln_b + (size_t)l * EE, LN8);
            last_mlp1_kernel<<<dim3(FF / 512, BB), 512>>>(LN8, W1l3,
                                                          b1 + (size_t)l * FF, M8);
            last_mlp2_kernel<<<BB, EE>>>(M8, W2l3, b2 + (size_t)l * EE, H, H8);
        }
    }

    head_kernel<<<BB, HH>>>(H8, Wh1, bh1, Wh2, bh2, out);
}

// round 15
// speedup vs baseline: 3.0624x; 1.0076x over previous
#include <cuda_runtime.h>
#include <math.h>

#define BB   8
#define SS   4096
#define EE   512
#define PP   64
#define LL   4
#define HH   256
#define CC   2
#define FF   2048
#define MROWS (BB*SS)
#define NSPLIT 32

enum { EPI_NONE = 0, EPI_PHI = 1, EPI_GELU = 2, EPI_RES = 3, EPI_DIV = 4, EPI_QK = 5 };

// ---------------- scratch ----------------
__device__ float g_H  [(size_t)MROWS*EE];
__device__ float g_A  [(size_t)MROWS*EE];
__device__ float g_QK [(size_t)MROWS*2*PP];    // [row][0:64]=phi_q, [64:128]=phi_k
__device__ float g_KH [(size_t)BB*PP*EE];      // phi_k^T @ H
__device__ float g_KHp[(size_t)NSPLIT*BB*PP*EE];
__device__ float g_KVW[(size_t)BB*PP*EE];      // KH @ WvWo (fp32, last layer)
__device__ float g_WVWO[(size_t)LL*EE*EE];     // Wv @ Wo per layer
__device__ float g_Z  [(size_t)BB*PP];
__device__ float g_Zp [(size_t)NSPLIT*BB*PP];
__device__ float g_DEN[(size_t)MROWS];
// last-layer small buffers
__device__ float g_DEN8[(size_t)BB];
__device__ float g_ATT8[(size_t)BB*EE];
__device__ float g_LN8 [(size_t)BB*EE];
__device__ float g_M8  [(size_t)BB*FF];
__device__ float g_H8  [(size_t)BB*EE];

// packed bf16x2 hi/lo
__device__ unsigned g_Hh [(size_t)MROWS*(EE/2)],  g_Hl [(size_t)MROWS*(EE/2)];
__device__ unsigned g_LNh[(size_t)MROWS*(EE/2)],  g_LNl[(size_t)MROWS*(EE/2)];
__device__ unsigned g_Mbh[(size_t)MROWS*(FF/2)],  g_Mbl[(size_t)MROWS*(FF/2)];
__device__ unsigned g_Qh [(size_t)MROWS*(PP/2)],  g_Ql [(size_t)MROWS*(PP/2)];
__device__ unsigned g_KVTh[(size_t)BB*EE*(PP/2)], g_KVTl[(size_t)BB*EE*(PP/2)];
// bf16 weights [N][K/2]
__device__ unsigned g_WQKh[(size_t)LL*2*PP*(EE/2)], g_WQKl[(size_t)LL*2*PP*(EE/2)];
__device__ unsigned g_W1h[(size_t)LL*FF*(EE/2)],  g_W1l_[(size_t)LL*FF*(EE/2)];
__device__ unsigned g_W2h[(size_t)LL*EE*(FF/2)],  g_W2l_[(size_t)LL*EE*(FF/2)];

// ---------------- helpers ----------------
__device__ __forceinline__ void cp_async16(void* smem, const void* gmem) {
    unsigned sa = (unsigned)__cvta_generic_to_shared(smem);
    asm volatile("cp.async.cg.shared.global [%0], [%1], 16;" :: "r"(sa), "l"(gmem));
}
__device__ __forceinline__ void cp_commit() { asm volatile("cp.async.commit_group;"); }
template<int N>
__device__ __forceinline__ void cp_wait() {
    asm volatile("cp.async.wait_group %0;" :: "n"(N));
}

__device__ __forceinline__ void split2(float x, float y, unsigned& hi, unsigned& lo) {
    asm("cvt.rn.bf16x2.f32 %0, %1, %2;" : "=r"(hi) : "f"(y), "f"(x));
    float hx = __uint_as_float(hi << 16);
    float hy = __uint_as_float(hi & 0xFFFF0000u);
    asm("cvt.rn.bf16x2.f32 %0, %1, %2;" : "=r"(lo) : "f"(y - hy), "f"(x - hx));
}

__device__ __forceinline__ void mma_bf16(float c[4], const unsigned a[4], const unsigned b[2]) {
    asm volatile(
        "mma.sync.aligned.m16n8k16.row.col.f32.bf16.bf16.f32 "
        "{%0,%1,%2,%3}, {%4,%5,%6,%7}, {%8,%9}, {%0,%1,%2,%3};"
        : "+f"(c[0]), "+f"(c[1]), "+f"(c[2]), "+f"(c[3])
        : "r"(a[0]), "r"(a[1]), "r"(a[2]), "r"(a[3]), "r"(b[0]), "r"(b[1]));
}

__device__ __forceinline__ float gelu_f(float v) {
    float u = 0.7978845608028654f * (v + 0.044715f * v * v * v);
    return 0.5f * v * (1.f + tanhf(u));
}

// ---------------- transpose + split ----------------
__device__ __forceinline__ void wsplit_tile(const float* Wl, unsigned* Th, unsigned* Tl,
                                            int K, int N, int k0, int n0, float (*t)[33]) {
    int tx = threadIdx.x, ty = threadIdx.y;
    #pragma unroll
    for (int i = 0; i < 4; i++)
        t[ty + i * 8][tx] = Wl[(size_t)(k0 + ty + i * 8) * N + n0 + tx];
    __syncthreads();
    int tid = ty * 32 + tx;
    #pragma unroll
    for (int i = 0; i < 2; i++) {
        int w = tid + i * 256;
        int n = w >> 4, kp = w & 15;
        unsigned h, l;
        split2(t[2 * kp][n], t[2 * kp + 1][n], h, l);
        size_t o = (size_t)(n0 + n) * (K >> 1) + (k0 >> 1) + kp;
        Th[o] = h; Tl[o] = l;
    }
}

struct WSEntry { const float* W; unsigned* Th; unsigned* Tl; int K; int N;
                 size_t lstr; int nblk; };
struct WSPack  { WSEntry e[4]; int cnt; };
__global__ void wsplit_multi(WSPack p) {
    __shared__ float t[32][33];
    int bid = blockIdx.x, i = 0;
    while (i + 1 < p.cnt && bid >= p.e[i].nblk) { bid -= p.e[i].nblk; i++; }
    WSEntry E = p.e[i];
    int tiles_n = E.N / 32, tpl = tiles_n * (E.K / 32);
    int layer = bid / tpl, rem = bid % tpl;
    wsplit_tile(E.W + (size_t)layer * E.K * E.N,
                E.Th + (size_t)layer * E.lstr,
                E.Tl + (size_t)layer * E.lstr,
                E.K, E.N, (rem / tiles_n) * 32, (rem % tiles_n) * 32, t);
}

// ---------------- WvWo = Wv @ Wo (per layer, fp32, one-time) ----------------
__global__ void __launch_bounds__(256)
wvwo_kernel(const float* __restrict__ Wv, const float* __restrict__ Wo,
            float* __restrict__ WVWO) {
    int l = blockIdx.z;
    const float* Av = Wv + (size_t)l * EE * EE;
    const float* Bo = Wo + (size_t)l * EE * EE;
    float* C = WVWO + (size_t)l * EE * EE;
    int k0 = blockIdx.y * 64, n0 = blockIdx.x * 64;
    __shared__ float As[32][65];
    __shared__ float Bs[32][64];
    int tid = threadIdx.x, tx = tid % 16, ty = tid / 16;
    float acc[4][4];
    #pragma unroll
    for (int i = 0; i < 4; i++)
        #pragma unroll
        for (int j = 0; j < 4; j++) acc[i][j] = 0.f;
    for (int e0 = 0; e0 < EE; e0 += 32) {
        #pragma unroll
        for (int i = 0; i < 8; i++) {
            int idx = tid + i * 256;
            int r = idx / 32, c = idx % 32;
            As[c][r] = Av[(size_t)(k0 + r) * EE + e0 + c];
        }
        #pragma unroll
        for (int i = 0; i < 2; i++) {
            int idx = tid + i * 256;
            int r = idx / 16, c4 = idx % 16;
            *(float4*)&Bs[r][c4 * 4] =
                *(const float4*)(Bo + (size_t)(e0 + r) * EE + n0 + c4 * 4);
        }
        __syncthreads();
        #pragma unroll
        for (int e = 0; e < 32; e++) {
            float ra[4], rb[4];
            #pragma unroll
            for (int i = 0; i < 4; i++) ra[i] = As[e][ty * 4 + i];
            #pragma unroll
            for (int j = 0; j < 4; j++) rb[j] = Bs[e][tx * 4 + j];
            #pragma unroll
            for (int i = 0; i < 4; i++)
                #pragma unroll
                for (int j = 0; j < 4; j++)
                    acc[i][j] = fmaf(ra[i], rb[j], acc[i][j]);
        }
        __syncthreads();
    }
    #pragma unroll
    for (int i = 0; i < 4; i++)
        #pragma unroll
        for (int j = 0; j < 4; j++)
            C[(size_t)(k0 + ty * 4 + i) * EE + n0 + tx * 4 + j] = acc[i][j];
}

// ---------------- KVW = KH @ WvWo; fused packed-transposed KVT output ----------------
__global__ void __launch_bounds__(256)
kvwo_kernel(const float* __restrict__ KH, const float* __restrict__ WVWOl,
            float* __restrict__ KVW,
            unsigned* __restrict__ KVTh, unsigned* __restrict__ KVTl) {
    int b = blockIdx.y, n0 = blockIdx.x * 64;
    const float* Ak = KH + (size_t)b * PP * EE;
    float* C = KVW + (size_t)b * PP * EE;
    __shared__ float As[32][65];
    __shared__ float Bs[32][64];
    int tid = threadIdx.x, tx = tid % 16, ty = tid / 16;
    float acc[4][4];
    #pragma unroll
    for (int i = 0; i < 4; i++)
        #pragma unroll
        for (int j = 0; j < 4; j++) acc[i][j] = 0.f;
    for (int e0 = 0; e0 < EE; e0 += 32) {
        #pragma unroll
        for (int i = 0; i < 8; i++) {
            int idx = tid + i * 256;
            int r = idx / 32, c = idx % 32;
            As[c][r] = Ak[(size_t)r * EE + e0 + c];
        }
        #pragma unroll
        for (int i = 0; i < 2; i++) {
            int idx = tid + i * 256;
            int r = idx / 16, c4 = idx % 16;
            *(float4*)&Bs[r][c4 * 4] =
                *(const float4*)(WVWOl + (size_t)(e0 + r) * EE + n0 + c4 * 4);
        }
        __syncthreads();
        #pragma unroll
        for (int e = 0; e < 32; e++) {
            float ra[4], rb[4];
            #pragma unroll
            for (int i = 0; i < 4; i++) ra[i] = As[e][ty * 4 + i];
            #pragma unroll
            for (int j = 0; j < 4; j++) rb[j] = Bs[e][tx * 4 + j];
            #pragma unroll
            for (int i = 0; i < 4; i++)
                #pragma unroll
                for (int j = 0; j < 4; j++)
                    acc[i][j] = fmaf(ra[i], rb[j], acc[i][j]);
        }
        __syncthreads();
    }
    // fp32 out (used by last layer)
    #pragma unroll
    for (int i = 0; i < 4; i++)
        #pragma unroll
        for (int j = 0; j < 4; j++)
            C[(size_t)(ty * 4 + i) * EE + n0 + tx * 4 + j] = acc[i][j];
    // packed transposed out: KVT[n][p/2], pairs along p (rows ty*4+{0,1} / {2,3})
    #pragma unroll
    for (int j = 0; j < 4; j++) {
        int n = n0 + tx * 4 + j;
        size_t base = ((size_t)b * EE + n) * (PP / 2) + ty * 2;
        unsigned h, l;
        split2(acc[0][j], acc[1][j], h, l);
        KVTh[base] = h; KVTl[base] = l;
        split2(acc[2][j], acc[3][j], h, l);
        KVTh[base + 1] = h; KVTl[base + 1] = l;
    }
}

// ---------------- embedding ----------------
__global__ void embed_kernel(const int* __restrict__ x, const float* __restrict__ emb,
                             const float* __restrict__ pos, float* __restrict__ H,
                             unsigned* __restrict__ Hh, unsigned* __restrict__ Hl) {
    int row = blockIdx.x, s = row & (SS - 1), tok = x[row];
    const float4* e4 = (const float4*)(emb + (size_t)tok * EE);
    const float4* p4 = (const float4*)(pos + (size_t)s * EE);
    int t = threadIdx.x;
    float4 a = e4[t], b = p4[t];
    float4 o = make_float4(a.x + b.x, a.y + b.y, a.z + b.z, a.w + b.w);
    ((float4*)(H + (size_t)row * EE))[t] = o;
    unsigned h0, l0, h1, l1;
    split2(o.x, o.y, h0, l0);
    split2(o.z, o.w, h1, l1);
    size_t wo = (size_t)row * (EE / 2) + 2 * t;
    Hh[wo] = h0; Hh[wo + 1] = h1;
    Hl[wo] = l0; Hl[wo + 1] = l1;
}

// ---------------- bf16x2 split GEMM ----------------
template<int BM, int BN, int WM, int WN, int EPI, bool WF32, bool WPACK, bool BATCHB>
__global__ void __launch_bounds__((BM/WM)*(BN/WN)*32)
gemm_pk(int M, int N, int K,
        const unsigned* __restrict__ Ah, const unsigned* __restrict__ Al,
        const unsigned* __restrict__ Bh, const unsigned* __restrict__ Bl,
        const float* __restrict__ bias, const float* __restrict__ res,
        float* __restrict__ C, unsigned* __restrict__ Ch, unsigned* __restrict__ Cl)
{
    constexpr int WARPS_N = BN / WN;
    constexpr int NTH = (BM / WM) * WARPS_N * 32;
    constexpr int LDW = 20;
    constexpr int ASZ = BM * LDW, BSZ = BN * LDW;
    constexpr int MT = WM / 16, NT = WN / 8;
    constexpr int A_CNT = BM * 4 / NTH, B_CNT = BN * 4 / NTH;

    extern __shared__ unsigned smw[];
    unsigned* Ash = smw;
    unsigned* Asl = smw + 3 * ASZ;
    unsigned* Bsh = smw + 6 * ASZ;
    unsigned* Bsl = smw + 6 * ASZ + 3 * BSZ;

    const int tid = threadIdx.x, lane = tid & 31, warp = tid >> 5;
    const int wm = warp / WARPS_N, wn = warp % WARPS_N;
    const int lr = lane >> 2, lc = lane & 3;
    const int row0 = blockIdx.y * BM, col0 = blockIdx.x * BN;
    const int KW = K >> 1, KT = K / 32;

    const unsigned* Bhp = Bh;
    const unsigned* Blp = Bl;
    if (BATCHB) {
        size_t boff = (size_t)(blockIdx.y / (SS / BM)) * N * KW;
        Bhp += boff; Blp += boff;
    }

    float acc[MT][NT][4];
    #pragma unroll
    for (int i = 0; i < MT; i++)
        #pragma unroll
        for (int j = 0; j < NT; j++)
            #pragma unroll
            for (int q = 0; q < 4; q++) acc[i][j][q] = 0.f;

    auto issue = [&](int kt, int st) {
        int goff = kt * 16;
        #pragma unroll
        for (int i = 0; i < A_CNT; i++) {
            int idx = tid + i * NTH;
            int r = idx >> 2, c = (idx & 3) * 4;
            size_t g = (size_t)(row0 + r) * KW + goff + c;
            cp_async16(Ash + st * ASZ + r * LDW + c, Ah + g);
            cp_async16(Asl + st * ASZ + r * LDW + c, Al + g);
        }
        #pragma unroll
        for (int i = 0; i < B_CNT; i++) {
            int idx = tid + i * NTH;
            int r = idx >> 2, c = (idx & 3) * 4;
            size_t g = (size_t)(col0 + r) * KW + goff + c;
            cp_async16(Bsh + st * BSZ + r * LDW + c, Bhp + g);
            cp_async16(Bsl + st * BSZ + r * LDW + c, Blp + g);
        }
    };

    auto compute = [&](int st) {
        const unsigned* Ah_ = Ash + st * ASZ;
        const unsigned* Al_ = Asl + st * ASZ;
        const unsigned* Bh_ = Bsh + st * BSZ;
        const unsigned* Bl_ = Bsl + st * BSZ;
        #pragma unroll
        for (int kk = 0; kk < 2; kk++) {
            unsigned ah[MT][4], al[MT][4];
            #pragma unroll
            for (int i = 0; i < MT; i++) {
                int base = (wm * WM + i * 16 + lr) * LDW + kk * 8 + lc;
                ah[i][0] = Ah_[base];               al[i][0] = Al_[base];
                ah[i][1] = Ah_[base + 8 * LDW];     al[i][1] = Al_[base + 8 * LDW];
                ah[i][2] = Ah_[base + 4];           al[i][2] = Al_[base + 4];
                ah[i][3] = Ah_[base + 8 * LDW + 4]; al[i][3] = Al_[base + 8 * LDW + 4];
            }
            #pragma unroll
            for (int j = 0; j < NT; j++) {
                int bbase = (wn * WN + j * 8 + lr) * LDW + kk * 8 + lc;
                unsigned bh[2], bl[2];
                bh[0] = Bh_[bbase];     bl[0] = Bl_[bbase];
                bh[1] = Bh_[bbase + 4]; bl[1] = Bl_[bbase + 4];
                #pragma unroll
                for (int i = 0; i < MT; i++) {
                    mma_bf16(acc[i][j], ah[i], bh);
                    mma_bf16(acc[i][j], ah[i], bl);
                    mma_bf16(acc[i][j], al[i], bh);
                }
            }
        }
    };

    issue(0, 0); cp_commit();
    issue(1, 1); cp_commit();
    cp_wait<1>();
    __syncthreads();
    for (int kt = 0; kt < KT; kt++) {
        if (kt + 2 < KT) issue(kt + 2, (kt + 2) % 3);
        cp_commit();
        compute(kt % 3);
        cp_wait<1>();
        __syncthreads();
    }

    auto epi = [&](float v, int rr, int cc) -> float {
        if (EPI == EPI_PHI || EPI == EPI_QK) return v > 0.f ? v + 1.f : expf(v);
        if (EPI == EPI_GELU) return gelu_f(v + bias[cc]);
        if (EPI == EPI_RES)  return v + bias[cc] + res[(size_t)rr * N + cc];
        if (EPI == EPI_DIV)  return v * bias[rr];
        return v;
    };

    #pragma unroll
    for (int i = 0; i < MT; i++) {
        #pragma unroll
        for (int j = 0; j < NT; j++) {
            int rr = row0 + wm * WM + i * 16 + lr;
            int cc = col0 + wn * WN + j * 8 + 2 * lc;
            float e00 = epi(acc[i][j][0], rr, cc);
            float e01 = epi(acc[i][j][1], rr, cc + 1);
            float e10 = epi(acc[i][j][2], rr + 8, cc);
            float e11 = epi(acc[i][j][3], rr + 8, cc + 1);
            if (WF32) {
                *(float2*)(C + (size_t)rr * N + cc)       = make_float2(e00, e01);
                *(float2*)(C + (size_t)(rr + 8) * N + cc) = make_float2(e10, e11);
            }
            if (WPACK) {
                const int halfN = (EPI == EPI_QK) ? PP : N;
                if (EPI != EPI_QK || cc < PP) {
                    unsigned h, l;
                    split2(e00, e01, h, l);
                    size_t w0 = (size_t)rr * (halfN >> 1) + (cc >> 1);
                    Ch[w0] = h; Cl[w0] = l;
                    split2(e10, e11, h, l);
                    size_t w1 = (size_t)(rr + 8) * (halfN >> 1) + (cc >> 1);
                    Ch[w1] = h; Cl[w1] = l;
                }
            }
        }
    }
}

// ---------------- KH partials + z partials (fused), split over S ----------------
__global__ void __launch_bounds__(256)
kv_kernel(const float* __restrict__ QK, const float* __restrict__ Hm,
          float* __restrict__ KHp, float* __restrict__ Zp)
{
    int b = blockIdx.y, f0 = blockIdx.x * 64, sp = blockIdx.z;
    const float* Kb = QK + (size_t)b * SS * 2 * PP + PP;
    const float* Vb = Hm + (size_t)b * SS * EE;
    __shared__ float Ks[32 * 64];
    __shared__ float Vs[32 * 64];
    int tid = threadIdx.x, tx = tid % 16, ty = tid / 16;
    const bool doz = (blockIdx.x == 0);
    int zp = tid & 63, zg = tid >> 6;
    float zacc = 0.f;
    float acc[4][4];
    #pragma unroll
    for (int i = 0; i < 4; i++)
        #pragma unroll
        for (int j = 0; j < 4; j++) acc[i][j] = 0.f;
    int sbeg = sp * (SS / NSPLIT), send = sbeg + (SS / NSPLIT);
    for (int s0 = sbeg; s0 < send; s0 += 32) {
        #pragma unroll
        for (int i = 0; i < 2; i++) {
            int idx = tid + i * 256;
            int r = idx / 16, c4 = idx % 16;
            *(float4*)(Ks + r * 64 + c4 * 4) =
                *(const float4*)(Kb + (size_t)(s0 + r) * 2 * PP + c4 * 4);
            *(float4*)(Vs + r * 64 + c4 * 4) =
                *(const float4*)(Vb + (size_t)(s0 + r) * EE + f0 + c4 * 4);
        }
        __syncthreads();
        #pragma unroll
        for (int k = 0; k < 32; k++) {
            float rp[4], rv[4];
            #pragma unroll
            for (int i = 0; i < 4; i++) rp[i] = Ks[k * 64 + ty * 4 + i];
            #pragma unroll
            for (int j = 0; j < 4; j++) rv[j] = Vs[k * 64 + tx * 4 + j];
            #pragma unroll
            for (int i = 0; i < 4; i++)
                #pragma unroll
                for (int j = 0; j < 4; j++)
                    acc[i][j] = fmaf(rp[i], rv[j], acc[i][j]);
        }
        if (doz) {
            #pragma unroll
            for (int r = 0; r < 8; r++)
                zacc += Ks[(zg + r * 4) * 64 + zp];
        }
        __syncthreads();
    }
    float* out = KHp + (size_t)sp * BB * PP * EE;
    #pragma unroll
    for (int i = 0; i < 4; i++)
        #pragma unroll
        for (int j = 0; j < 4; j++)
            out[((size_t)b * PP + ty * 4 + i) * EE + f0 + tx * 4 + j] = acc[i][j];
    if (doz) {
        __shared__ float zsm[256];
        zsm[tid] = zacc;
        __syncthreads();
        if (zg == 0)
            Zp[(size_t)sp * BB * PP + b * PP + zp] =
                zsm[zp] + zsm[64 + zp] + zsm[128 + zp] + zsm[192 + zp];
    }
}

// merged reduction: blocks [0, NKV) reduce KH; blocks NKV.. reduce z (512 elems)
__global__ void reduce_all(const float* __restrict__ KHp, float* __restrict__ KH,
                           const float* __restrict__ Zp, float* __restrict__ Z) {
    const int NKV = (BB * PP * EE) / 256;
    if ((int)blockIdx.x < NKV) {
        size_t idx = (size_t)blockIdx.x * 256 + threadIdx.x;
        float s = 0.f;
        #pragma unroll
        for (int sp = 0; sp < NSPLIT; sp++) s += KHp[(size_t)sp * BB * PP * EE + idx];
        KH[idx] = s;
    } else {
        int idx = threadIdx.x + 256 * (blockIdx.x - NKV);
        if (idx < BB * PP) {
            float s = 0.f;
            #pragma unroll
            for (int sp = 0; sp < NSPLIT; sp++) s += Zp[sp * BB * PP + idx];
            Z[idx] = s;
        }
    }
}

__global__ void den_kernel(const float* __restrict__ QK, const float* __restrict__ Z,
                           float* __restrict__ inv) {
    int row = blockIdx.x * 8 + (threadIdx.x >> 5);
    int lane = threadIdx.x & 31;
    int b = row >> 12;
    const float* q = QK + (size_t)row * 2 * PP;
    const float* z = Z + b * PP;
    float s = q[lane] * z[lane] + q[lane + 32] * z[lane + 32];
    #pragma unroll
    for (int o = 16; o; o >>= 1) s += __shfl_xor_sync(0xffffffffu, s, o);
    if (lane == 0) inv[row] = 1.f / (s + 1e-6f);
}

// ---------------- layernorm: fp32 in -> packed out ----------------
__global__ void ln_kernel(const float* __restrict__ X,
                          const float* __restrict__ gam, const float* __restrict__ bet,
                          unsigned* __restrict__ Oh, unsigned* __restrict__ Ol) {
    int row = blockIdx.x;
    const float* xr = X + (size_t)row * EE;
    int tid = threadIdx.x;
    float4 v = ((const float4*)xr)[tid];
    float s = v.x + v.y + v.z + v.w;
    float q = v.x * v.x + v.y * v.y + v.z * v.z + v.w * v.w;
    #pragma unroll
    for (int o = 16; o; o >>= 1) {
        s += __shfl_xor_sync(0xffffffffu, s, o);
        q += __shfl_xor_sync(0xffffffffu, q, o);
    }
    __shared__ float ss[4], qq[4];
    int w = tid >> 5;
    if ((tid & 31) == 0) { ss[w] = s; qq[w] = q; }
    __syncthreads();
    s = ss[0] + ss[1] + ss[2] + ss[3];
    q = qq[0] + qq[1] + qq[2] + qq[3];
    float mu = s * (1.f / EE);
    float var = q * (1.f / EE) - mu * mu;
    float inv = rsqrtf(var + 1e-5f);
    float4 g4 = ((const float4*)gam)[tid];
    float4 b4 = ((const float4*)bet)[tid];
    float o0 = (v.x - mu) * inv * g4.x + b4.x;
    float o1 = (v.y - mu) * inv * g4.y + b4.y;
    float o2 = (v.z - mu) * inv * g4.z + b4.z;
    float o3 = (v.w - mu) * inv * g4.w + b4.w;
    unsigned h0, l0, h1, l1;
    split2(o0, o1, h0, l0);
    split2(o2, o3, h1, l1);
    size_t wo = (size_t)row * (EE / 2) + 2 * tid;
    Oh[wo] = h0; Oh[wo + 1] = h1;
    Ol[wo] = l0; Ol[wo + 1] = l1;
}

// ---------------- last-layer (s=0 only) fp32 chain ----------------
__global__ void last_den_kernel(const float* __restrict__ QK,
                                const float* __restrict__ Z,
                                float* __restrict__ DEN8) {
    int b = blockIdx.x, p = threadIdx.x;
    const float* q = QK + (size_t)b * SS * 2 * PP;
    __shared__ float sm[PP];
    sm[p] = q[p] * Z[b * PP + p];
    __syncthreads();
    if (p == 0) {
        float s = 0.f;
        for (int i = 0; i < PP; i++) s += sm[i];
        DEN8[b] = 1.f / (s + 1e-6f);
    }
}

__global__ void last_attn_kernel(const float* __restrict__ QK,
                                 const float* __restrict__ KVW,
                                 const float* __restrict__ DEN8,
                                 float* __restrict__ ATT8) {
    int b = blockIdx.x, tid = threadIdx.x;
    __shared__ float ph[PP];
    if (tid < PP) ph[tid] = QK[(size_t)b * SS * 2 * PP + tid];
    __syncthreads();
    float inv = DEN8[b];
    for (int f = tid; f < EE; f += 256) {
        float a = 0.f;
        for (int p = 0; p < PP; p++)
            a = fmaf(ph[p], KVW[((size_t)b * PP + p) * EE + f], a);
        ATT8[b * EE + f] = a * inv;
    }
}

__global__ void last_ln_kernel(const float* __restrict__ ATT8,
                               const float* __restrict__ gam,
                               const float* __restrict__ bet,
                               float* __restrict__ LN8) {
    int b = blockIdx.x, e = threadIdx.x;
    float a = ATT8[b * EE + e];
    float s = a, q = a * a;
    #pragma unroll
    for (int o = 16; o; o >>= 1) {
        s += __shfl_xor_sync(0xffffffffu, s, o);
        q += __shfl_xor_sync(0xffffffffu, q, o);
    }
    __shared__ float ssum[16], ssq[16];
    int w = e >> 5;
    if ((e & 31) == 0) { ssum[w] = s; ssq[w] = q; }
    __syncthreads();
    float S = 0.f, Qq = 0.f;
    #pragma unroll
    for (int i = 0; i < 16; i++) { S += ssum[i]; Qq += ssq[i]; }
    float mu = S * (1.f / EE);
    float var = Qq * (1.f / EE) - mu * mu;
    float inv = rsqrtf(var + 1e-5f);
    LN8[b * EE + e] = (a - mu) * inv * gam[e] + bet[e];
}

__global__ void last_mlp1_kernel(const float* __restrict__ LN8,
                                 const float* __restrict__ W1,
                                 const float* __restrict__ b1,
                                 float* __restrict__ M8) {
    int b = blockIdx.y, j = blockIdx.x * 512 + threadIdx.x;
    __shared__ float ln[EE];
    for (int i = threadIdx.x; i < EE; i += 512) ln[i] = LN8[b * EE + i];
    __syncthreads();
    float acc = b1[j];
    for (int e = 0; e < EE; e++) acc = fmaf(ln[e], W1[(size_t)e * FF + j], acc);
    M8[b * FF + j] = gelu_f(acc);
}

__global__ void last_mlp2_kernel(const float* __restrict__ M8,
                                 const float* __restrict__ W2,
                                 const float* __restrict__ b2,
                                 const float* __restrict__ H,
                                 float* __restrict__ H8) {
    int b = blockIdx.x, e = threadIdx.x;
    float acc = b2[e];
    const float* m = M8 + (size_t)b * FF;
    for (int j = 0; j < FF; j++) acc = fmaf(m[j], W2[(size_t)j * EE + e], acc);
    H8[b * EE + e] = acc + H[(size_t)b * SS * EE + e];
}

// ---------------- head ----------------
__global__ void head_kernel(const float* __restrict__ H8, const float* __restrict__ Wh1,
                            const float* __restrict__ bh1, const float* __restrict__ Wh2,
                            const float* __restrict__ bh2, float* __restrict__ out) {
    int b = blockIdx.x, tid = threadIdx.x;
    const float* hr = H8 + (size_t)b * EE;
    float acc = bh1[tid];
    for (int e = 0; e < EE; e++) acc = fmaf(hr[e], Wh1[e * HH + tid], acc);
    acc = fmaxf(acc, 0.f);
    __shared__ float hid[HH];
    hid[tid] = acc;
    __syncthreads();
    if (tid < CC) {
        float a = bh2[tid];
        for (int h = 0; h < HH; h++) a = fmaf(hid[h], Wh2[h * CC + tid], a);
        out[b * CC + tid] = a;
    }
}

// ---------------- launch ----------------
static size_t gemm_smem(int BM, int BN) {
    return (size_t)(3 * (BM * 20 * 2 + BN * 20 * 2)) * 4;
}

extern "C" void kernel_launch(void* const* d_in, const int* in_sizes, int n_in,
                              void* d_out, int out_size) {
    const int*   x    = (const int*)  d_in[0];
    const float* emb  = (const float*)d_in[1];
    const float* pos  = (const float*)d_in[2];
    const float* Wq   = (const float*)d_in[3];
    const float* Wk   = (const float*)d_in[4];
    const float* Wv   = (const float*)d_in[5];
    const float* Wo   = (const float*)d_in[6];
    const float* ln_g = (const float*)d_in[7];
    const float* ln_b = (const float*)d_in[8];
    const float* W1   = (const float*)d_in[9];
    const float* b1   = (const float*)d_in[10];
    const float* W2   = (const float*)d_in[11];
    const float* b2   = (const float*)d_in[12];
    const float* Wh1  = (const float*)d_in[13];
    const float* bh1  = (const float*)d_in[14];
    const float* Wh2  = (const float*)d_in[15];
    const float* bh2  = (const float*)d_in[16];
    float* out = (float*)d_out;

    float *H, *A, *QK, *KH, *KHp, *KVW, *WVWO, *Z, *Zp, *DEN;
    float *DEN8, *ATT8, *LN8, *M8, *H8;
    cudaGetSymbolAddress((void**)&H,    g_H);
    cudaGetSymbolAddress((void**)&A,    g_A);
    cudaGetSymbolAddress((void**)&QK,   g_QK);
    cudaGetSymbolAddress((void**)&KH,   g_KH);
    cudaGetSymbolAddress((void**)&KHp,  g_KHp);
    cudaGetSymbolAddress((void**)&KVW,  g_KVW);
    cudaGetSymbolAddress((void**)&WVWO, g_WVWO);
    cudaGetSymbolAddress((void**)&Z,    g_Z);
    cudaGetSymbolAddress((void**)&Zp,   g_Zp);
    cudaGetSymbolAddress((void**)&DEN,  g_DEN);
    cudaGetSymbolAddress((void**)&DEN8, g_DEN8);
    cudaGetSymbolAddress((void**)&ATT8, g_ATT8);
    cudaGetSymbolAddress((void**)&LN8,  g_LN8);
    cudaGetSymbolAddress((void**)&M8,   g_M8);
    cudaGetSymbolAddress((void**)&H8,   g_H8);

    unsigned *Hh, *Hl, *LNh, *LNl, *Mbh, *Mbl, *Qh, *Ql, *KVTh, *KVTl;
    cudaGetSymbolAddress((void**)&Hh,   g_Hh);   cudaGetSymbolAddress((void**)&Hl,   g_Hl);
    cudaGetSymbolAddress((void**)&LNh,  g_LNh);  cudaGetSymbolAddress((void**)&LNl,  g_LNl);
    cudaGetSymbolAddress((void**)&Mbh,  g_Mbh);  cudaGetSymbolAddress((void**)&Mbl,  g_Mbl);
    cudaGetSymbolAddress((void**)&Qh,   g_Qh);   cudaGetSymbolAddress((void**)&Ql,   g_Ql);
    cudaGetSymbolAddress((void**)&KVTh, g_KVTh); cudaGetSymbolAddress((void**)&KVTl, g_KVTl);

    unsigned *WQKh, *WQKl, *W1h, *W1l, *W2h, *W2l;
    cudaGetSymbolAddress((void**)&WQKh, g_WQKh); cudaGetSymbolAddress((void**)&WQKl, g_WQKl);
    cudaGetSymbolAddress((void**)&W1h,  g_W1h);  cudaGetSymbolAddress((void**)&W1l,  g_W1l_);
    cudaGetSymbolAddress((void**)&W2h,  g_W2h);  cudaGetSymbolAddress((void**)&W2l,  g_W2l_);

    const size_t smQK  = gemm_smem(128, 128);
    const size_t smBIG = gemm_smem(128, 256);
    cudaFuncSetAttribute(gemm_pk<128, 128, 64, 32, EPI_QK, true, true, false>,
                         cudaFuncAttributeMaxDynamicSharedMemorySize, (int)smQK);
    cudaFuncSetAttribute(gemm_pk<128, 256, 64, 64, EPI_DIV, true, false, true>,
                         cudaFuncAttributeMaxDynamicSharedMemorySize, (int)smBIG);
    cudaFuncSetAttribute(gemm_pk<128, 256, 64, 64, EPI_GELU, false, true, false>,
                         cudaFuncAttributeMaxDynamicSharedMemorySize, (int)smBIG);
    cudaFuncSetAttribute(gemm_pk<128, 256, 64, 64, EPI_RES, true, true, false>,
                         cudaFuncAttributeMaxDynamicSharedMemorySize, (int)smBIG);

    // one-time weight prep
    dim3 wt(32, 8);
    {
        WSPack pA;
        const size_t qkL = (size_t)2 * PP * (EE / 2);
        pA.e[0] = { Wq, WQKh, WQKl, EE, PP, qkL, LL * (EE / 32) * (PP / 32) };
        pA.e[1] = { Wk, WQKh + (size_t)PP * (EE / 2), WQKl + (size_t)PP * (EE / 2),
                    EE, PP, qkL, LL * (EE / 32) * (PP / 32) };
        pA.e[2] = { W1, W1h, W1l, EE, FF, (size_t)FF * (EE / 2), LL * (EE / 32) * (FF / 32) };
        pA.e[3] = { W2, W2h, W2l, FF, EE, (size_t)EE * (FF / 2), LL * (FF / 32) * (EE / 32) };
        pA.cnt = 4;
        int nA = pA.e[0].nblk + pA.e[1].nblk + pA.e[2].nblk + pA.e[3].nblk;
        wsplit_multi<<<nA, wt>>>(pA);
    }
    wvwo_kernel<<<dim3(EE / 64, EE / 64, LL), 256>>>(Wv, Wo, WVWO);

    embed_kernel<<<MROWS, 128>>>(x, emb, pos, H, Hh, Hl);

    // KH blocks + 2 z blocks (BB*PP = 512 elements)
    const int NRED = (BB * PP * EE) / 256 + 2;

    for (int l = 0; l < LL; l++) {
        size_t oQK = (size_t)l * 2 * PP * (EE / 2);
        size_t oW1 = (size_t)l * FF * (EE / 2);
        size_t oW2 = (size_t)l * EE * (FF / 2);
        const bool last = (l == LL - 1);

        gemm_pk<128, 128, 64, 32, EPI_QK, true, true, false>
            <<<dim3(1, MROWS / 128), 256, smQK>>>(
                MROWS, 2 * PP, EE, Hh, Hl, WQKh + oQK, WQKl + oQK,
                nullptr, nullptr, QK, Qh, Ql);

        kv_kernel<<<dim3(EE / 64, BB, NSPLIT), 256>>>(QK, H, KHp, Zp);
        reduce_all<<<NRED, 256>>>(KHp, KH, Zp, Z);
        kvwo_kernel<<<dim3(EE / 64, BB), 256>>>(KH, WVWO + (size_t)l * EE * EE,
                                                KVW, KVTh, KVTl);

        if (!last) {
            den_kernel<<<MROWS / 8, 256>>>(QK, Z, DEN);

            gemm_pk<128, 256, 64, 64, EPI_DIV, true, false, true>
                <<<dim3(EE / 256, MROWS / 128), 256, smBIG>>>(
                    MROWS, EE, PP, Qh, Ql, KVTh, KVTl,
                    DEN, nullptr, A, nullptr, nullptr);

            ln_kernel<<<MROWS, 128>>>(A, ln_g + (size_t)l * EE,
                                      ln_b + (size_t)l * EE, LNh, LNl);

            gemm_pk<128, 256, 64, 64, EPI_GELU, false, true, false>
                <<<dim3(FF / 256, MROWS / 128), 256, smBIG>>>(
                    MROWS, FF, EE, LNh, LNl, W1h + oW1, W1l + oW1,
                    b1 + (size_t)l * FF, nullptr, nullptr, Mbh, Mbl);
            gemm_pk<128, 256, 64, 64, EPI_RES, true, true, false>
                <<<dim3(EE / 256, MROWS / 128), 256, smBIG>>>(
                    MROWS, EE, FF, Mbh, Mbl, W2h + oW2, W2l + oW2,
                    b2 + (size_t)l * EE, H, H, Hh, Hl);
        } else {
            const float* W1l3 = W1 + (size_t)l * EE * FF;
            const float* W2l3 = W2 + (size_t)l * FF * EE;
            last_den_kernel<<<BB, PP>>>(QK, Z, DEN8);
            last_attn_kernel<<<BB, 256>>>(QK, KVW, DEN8, ATT8);
            last_ln_kernel<<<BB, EE>>>(ATT8, ln_g + (size_t)l * EE,
                                       ln_b + (size_t)l * EE, LN8);
            last_mlp1_kernel<<<dim3(FF / 512, BB), 512>>>(LN8, W1l3,
                                                          b1 + (size_t)l * FF, M8);
            last_mlp2_kernel<<<BB, EE>>>(M8, W2l3, b2 + (size_t)l * EE, H, H8);
        }
    }

    head_kernel<<<BB, HH>>>(H8, Wh1, bh1, Wh2, bh2, out);
}

// round 16
// speedup vs baseline: 3.0751x; 1.0042x over previous
#include <cuda_runtime.h>
#include <math.h>

#define BB   8
#define SS   4096
#define EE   512
#define PP   64
#define LL   4
#define HH   256
#define CC   2
#define FF   2048
#define MROWS (BB*SS)
#define NSPLIT 32

enum { EPI_NONE = 0, EPI_PHI = 1, EPI_GELU = 2, EPI_RES = 3, EPI_DIV = 4, EPI_QK = 5 };

// ---------------- scratch ----------------
__device__ float g_H  [(size_t)MROWS*EE];
__device__ float g_QK [(size_t)MROWS*2*PP];    // [row][0:64]=phi_q, [64:128]=phi_k
__device__ float g_KH [(size_t)BB*PP*EE];      // phi_k^T @ H
__device__ float g_KHp[(size_t)NSPLIT*BB*PP*EE];
__device__ float g_KVW[(size_t)BB*PP*EE];      // KH @ WvWo (fp32, last layer)
__device__ float g_WVWO[(size_t)LL*EE*EE];     // Wv @ Wo per layer
__device__ float g_Z  [(size_t)BB*PP];
__device__ float g_Zp [(size_t)NSPLIT*BB*PP];
__device__ float g_DEN[(size_t)MROWS];
// last-layer small buffers
__device__ float g_DEN8[(size_t)BB];
__device__ float g_ATT8[(size_t)BB*EE];
__device__ float g_LN8 [(size_t)BB*EE];
__device__ float g_M8  [(size_t)BB*FF];
__device__ float g_H8  [(size_t)BB*EE];

// packed bf16x2 hi/lo
__device__ unsigned g_Hh [(size_t)MROWS*(EE/2)],  g_Hl [(size_t)MROWS*(EE/2)];
__device__ unsigned g_LNh[(size_t)MROWS*(EE/2)],  g_LNl[(size_t)MROWS*(EE/2)];
__device__ unsigned g_Mbh[(size_t)MROWS*(FF/2)],  g_Mbl[(size_t)MROWS*(FF/2)];
__device__ unsigned g_Qh [(size_t)MROWS*(PP/2)],  g_Ql [(size_t)MROWS*(PP/2)];
__device__ unsigned g_KVTh[(size_t)BB*EE*(PP/2)], g_KVTl[(size_t)BB*EE*(PP/2)];
// bf16 weights [N][K/2]
__device__ unsigned g_WQKh[(size_t)LL*2*PP*(EE/2)], g_WQKl[(size_t)LL*2*PP*(EE/2)];
__device__ unsigned g_W1h[(size_t)LL*FF*(EE/2)],  g_W1l_[(size_t)LL*FF*(EE/2)];
__device__ unsigned g_W2h[(size_t)LL*EE*(FF/2)],  g_W2l_[(size_t)LL*EE*(FF/2)];

// ---------------- helpers ----------------
__device__ __forceinline__ void cp_async16(void* smem, const void* gmem) {
    unsigned sa = (unsigned)__cvta_generic_to_shared(smem);
    asm volatile("cp.async.cg.shared.global [%0], [%1], 16;" :: "r"(sa), "l"(gmem));
}
__device__ __forceinline__ void cp_commit() { asm volatile("cp.async.commit_group;"); }
template<int N>
__device__ __forceinline__ void cp_wait() {
    asm volatile("cp.async.wait_group %0;" :: "n"(N));
}

__device__ __forceinline__ void split2(float x, float y, unsigned& hi, unsigned& lo) {
    asm("cvt.rn.bf16x2.f32 %0, %1, %2;" : "=r"(hi) : "f"(y), "f"(x));
    float hx = __uint_as_float(hi << 16);
    float hy = __uint_as_float(hi & 0xFFFF0000u);
    asm("cvt.rn.bf16x2.f32 %0, %1, %2;" : "=r"(lo) : "f"(y - hy), "f"(x - hx));
}

__device__ __forceinline__ void mma_bf16(float c[4], const unsigned a[4], const unsigned b[2]) {
    asm volatile(
        "mma.sync.aligned.m16n8k16.row.col.f32.bf16.bf16.f32 "
        "{%0,%1,%2,%3}, {%4,%5,%6,%7}, {%8,%9}, {%0,%1,%2,%3};"
        : "+f"(c[0]), "+f"(c[1]), "+f"(c[2]), "+f"(c[3])
        : "r"(a[0]), "r"(a[1]), "r"(a[2]), "r"(a[3]), "r"(b[0]), "r"(b[1]));
}

__device__ __forceinline__ float gelu_f(float v) {
    float u = 0.7978845608028654f * (v + 0.044715f * v * v * v);
    return 0.5f * v * (1.f + tanhf(u));
}

// ---------------- transpose + split ----------------
__device__ __forceinline__ void wsplit_tile(const float* Wl, unsigned* Th, unsigned* Tl,
                                            int K, int N, int k0, int n0, float (*t)[33]) {
    int tx = threadIdx.x, ty = threadIdx.y;
    #pragma unroll
    for (int i = 0; i < 4; i++)
        t[ty + i * 8][tx] = Wl[(size_t)(k0 + ty + i * 8) * N + n0 + tx];
    __syncthreads();
    int tid = ty * 32 + tx;
    #pragma unroll
    for (int i = 0; i < 2; i++) {
        int w = tid + i * 256;
        int n = w >> 4, kp = w & 15;
        unsigned h, l;
        split2(t[2 * kp][n], t[2 * kp + 1][n], h, l);
        size_t o = (size_t)(n0 + n) * (K >> 1) + (k0 >> 1) + kp;
        Th[o] = h; Tl[o] = l;
    }
}

struct WSEntry { const float* W; unsigned* Th; unsigned* Tl; int K; int N;
                 size_t lstr; int nblk; };
struct WSPack  { WSEntry e[4]; int cnt; };
__global__ void wsplit_multi(WSPack p) {
    __shared__ float t[32][33];
    int bid = blockIdx.x, i = 0;
    while (i + 1 < p.cnt && bid >= p.e[i].nblk) { bid -= p.e[i].nblk; i++; }
    WSEntry E = p.e[i];
    int tiles_n = E.N / 32, tpl = tiles_n * (E.K / 32);
    int layer = bid / tpl, rem = bid % tpl;
    wsplit_tile(E.W + (size_t)layer * E.K * E.N,
                E.Th + (size_t)layer * E.lstr,
                E.Tl + (size_t)layer * E.lstr,
                E.K, E.N, (rem / tiles_n) * 32, (rem % tiles_n) * 32, t);
}

// ---------------- WvWo = Wv @ Wo (per layer, fp32, one-time) ----------------
__global__ void __launch_bounds__(256)
wvwo_kernel(const float* __restrict__ Wv, const float* __restrict__ Wo,
            float* __restrict__ WVWO) {
    int l = blockIdx.z;
    const float* Av = Wv + (size_t)l * EE * EE;
    const float* Bo = Wo + (size_t)l * EE * EE;
    float* C = WVWO + (size_t)l * EE * EE;
    int k0 = blockIdx.y * 64, n0 = blockIdx.x * 64;
    __shared__ float As[32][65];
    __shared__ float Bs[32][64];
    int tid = threadIdx.x, tx = tid % 16, ty = tid / 16;
    float acc[4][4];
    #pragma unroll
    for (int i = 0; i < 4; i++)
        #pragma unroll
        for (int j = 0; j < 4; j++) acc[i][j] = 0.f;
    for (int e0 = 0; e0 < EE; e0 += 32) {
        #pragma unroll
        for (int i = 0; i < 8; i++) {
            int idx = tid + i * 256;
            int r = idx / 32, c = idx % 32;
            As[c][r] = Av[(size_t)(k0 + r) * EE + e0 + c];
        }
        #pragma unroll
        for (int i = 0; i < 2; i++) {
            int idx = tid + i * 256;
            int r = idx / 16, c4 = idx % 16;
            *(float4*)&Bs[r][c4 * 4] =
                *(const float4*)(Bo + (size_t)(e0 + r) * EE + n0 + c4 * 4);
        }
        __syncthreads();
        #pragma unroll
        for (int e = 0; e < 32; e++) {
            float ra[4], rb[4];
            #pragma unroll
            for (int i = 0; i < 4; i++) ra[i] = As[e][ty * 4 + i];
            #pragma unroll
            for (int j = 0; j < 4; j++) rb[j] = Bs[e][tx * 4 + j];
            #pragma unroll
            for (int i = 0; i < 4; i++)
                #pragma unroll
                for (int j = 0; j < 4; j++)
                    acc[i][j] = fmaf(ra[i], rb[j], acc[i][j]);
        }
        __syncthreads();
    }
    #pragma unroll
    for (int i = 0; i < 4; i++)
        #pragma unroll
        for (int j = 0; j < 4; j++)
            C[(size_t)(k0 + ty * 4 + i) * EE + n0 + tx * 4 + j] = acc[i][j];
}

// ---------------- KVW = KH @ WvWo; fused packed-transposed KVT output ----------------
__global__ void __launch_bounds__(256)
kvwo_kernel(const float* __restrict__ KH, const float* __restrict__ WVWOl,
            float* __restrict__ KVW,
            unsigned* __restrict__ KVTh, unsigned* __restrict__ KVTl) {
    int b = blockIdx.y, n0 = blockIdx.x * 64;
    const float* Ak = KH + (size_t)b * PP * EE;
    float* C = KVW + (size_t)b * PP * EE;
    __shared__ float As[32][65];
    __shared__ float Bs[32][64];
    int tid = threadIdx.x, tx = tid % 16, ty = tid / 16;
    float acc[4][4];
    #pragma unroll
    for (int i = 0; i < 4; i++)
        #pragma unroll
        for (int j = 0; j < 4; j++) acc[i][j] = 0.f;
    for (int e0 = 0; e0 < EE; e0 += 32) {
        #pragma unroll
        for (int i = 0; i < 8; i++) {
            int idx = tid + i * 256;
            int r = idx / 32, c = idx % 32;
            As[c][r] = Ak[(size_t)r * EE + e0 + c];
        }
        #pragma unroll
        for (int i = 0; i < 2; i++) {
            int idx = tid + i * 256;
            int r = idx / 16, c4 = idx % 16;
            *(float4*)&Bs[r][c4 * 4] =
                *(const float4*)(WVWOl + (size_t)(e0 + r) * EE + n0 + c4 * 4);
        }
        __syncthreads();
        #pragma unroll
        for (int e = 0; e < 32; e++) {
            float ra[4], rb[4];
            #pragma unroll
            for (int i = 0; i < 4; i++) ra[i] = As[e][ty * 4 + i];
            #pragma unroll
            for (int j = 0; j < 4; j++) rb[j] = Bs[e][tx * 4 + j];
            #pragma unroll
            for (int i = 0; i < 4; i++)
                #pragma unroll
                for (int j = 0; j < 4; j++)
                    acc[i][j] = fmaf(ra[i], rb[j], acc[i][j]);
        }
        __syncthreads();
    }
    #pragma unroll
    for (int i = 0; i < 4; i++)
        #pragma unroll
        for (int j = 0; j < 4; j++)
            C[(size_t)(ty * 4 + i) * EE + n0 + tx * 4 + j] = acc[i][j];
    #pragma unroll
    for (int j = 0; j < 4; j++) {
        int n = n0 + tx * 4 + j;
        size_t base = ((size_t)b * EE + n) * (PP / 2) + ty * 2;
        unsigned h, l;
        split2(acc[0][j], acc[1][j], h, l);
        KVTh[base] = h; KVTl[base] = l;
        split2(acc[2][j], acc[3][j], h, l);
        KVTh[base + 1] = h; KVTl[base + 1] = l;
    }
}

// ---------------- embedding ----------------
__global__ void embed_kernel(const int* __restrict__ x, const float* __restrict__ emb,
                             const float* __restrict__ pos, float* __restrict__ H,
                             unsigned* __restrict__ Hh, unsigned* __restrict__ Hl) {
    int row = blockIdx.x, s = row & (SS - 1), tok = x[row];
    const float4* e4 = (const float4*)(emb + (size_t)tok * EE);
    const float4* p4 = (const float4*)(pos + (size_t)s * EE);
    int t = threadIdx.x;
    float4 a = e4[t], b = p4[t];
    float4 o = make_float4(a.x + b.x, a.y + b.y, a.z + b.z, a.w + b.w);
    ((float4*)(H + (size_t)row * EE))[t] = o;
    unsigned h0, l0, h1, l1;
    split2(o.x, o.y, h0, l0);
    split2(o.z, o.w, h1, l1);
    size_t wo = (size_t)row * (EE / 2) + 2 * t;
    Hh[wo] = h0; Hh[wo + 1] = h1;
    Hl[wo] = l0; Hl[wo + 1] = l1;
}

// ---------------- bf16x2 split GEMM ----------------
template<int BM, int BN, int WM, int WN, int EPI, bool WF32, bool WPACK, bool BATCHB>
__global__ void __launch_bounds__((BM/WM)*(BN/WN)*32)
gemm_pk(int M, int N, int K,
        const unsigned* __restrict__ Ah, const unsigned* __restrict__ Al,
        const unsigned* __restrict__ Bh, const unsigned* __restrict__ Bl,
        const float* __restrict__ bias, const float* __restrict__ res,
        float* __restrict__ C, unsigned* __restrict__ Ch, unsigned* __restrict__ Cl)
{
    constexpr int WARPS_N = BN / WN;
    constexpr int NTH = (BM / WM) * WARPS_N * 32;
    constexpr int LDW = 20;
    constexpr int ASZ = BM * LDW, BSZ = BN * LDW;
    constexpr int MT = WM / 16, NT = WN / 8;
    constexpr int A_CNT = BM * 4 / NTH, B_CNT = BN * 4 / NTH;

    extern __shared__ unsigned smw[];
    unsigned* Ash = smw;
    unsigned* Asl = smw + 3 * ASZ;
    unsigned* Bsh = smw + 6 * ASZ;
    unsigned* Bsl = smw + 6 * ASZ + 3 * BSZ;

    const int tid = threadIdx.x, lane = tid & 31, warp = tid >> 5;
    const int wm = warp / WARPS_N, wn = warp % WARPS_N;
    const int lr = lane >> 2, lc = lane & 3;
    const int row0 = blockIdx.y * BM, col0 = blockIdx.x * BN;
    const int KW = K >> 1, KT = K / 32;

    const unsigned* Bhp = Bh;
    const unsigned* Blp = Bl;
    if (BATCHB) {
        size_t boff = (size_t)(blockIdx.y / (SS / BM)) * N * KW;
        Bhp += boff; Blp += boff;
    }

    float acc[MT][NT][4];
    #pragma unroll
    for (int i = 0; i < MT; i++)
        #pragma unroll
        for (int j = 0; j < NT; j++)
            #pragma unroll
            for (int q = 0; q < 4; q++) acc[i][j][q] = 0.f;

    auto issue = [&](int kt, int st) {
        int goff = kt * 16;
        #pragma unroll
        for (int i = 0; i < A_CNT; i++) {
            int idx = tid + i * NTH;
            int r = idx >> 2, c = (idx & 3) * 4;
            size_t g = (size_t)(row0 + r) * KW + goff + c;
            cp_async16(Ash + st * ASZ + r * LDW + c, Ah + g);
            cp_async16(Asl + st * ASZ + r * LDW + c, Al + g);
        }
        #pragma unroll
        for (int i = 0; i < B_CNT; i++) {
            int idx = tid + i * NTH;
            int r = idx >> 2, c = (idx & 3) * 4;
            size_t g = (size_t)(col0 + r) * KW + goff + c;
            cp_async16(Bsh + st * BSZ + r * LDW + c, Bhp + g);
            cp_async16(Bsl + st * BSZ + r * LDW + c, Blp + g);
        }
    };

    auto compute = [&](int st) {
        const unsigned* Ah_ = Ash + st * ASZ;
        const unsigned* Al_ = Asl + st * ASZ;
        const unsigned* Bh_ = Bsh + st * BSZ;
        const unsigned* Bl_ = Bsl + st * BSZ;
        #pragma unroll
        for (int kk = 0; kk < 2; kk++) {
            unsigned ah[MT][4], al[MT][4];
            #pragma unroll
            for (int i = 0; i < MT; i++) {
                int base = (wm * WM + i * 16 + lr) * LDW + kk * 8 + lc;
                ah[i][0] = Ah_[base];               al[i][0] = Al_[base];
                ah[i][1] = Ah_[base + 8 * LDW];     al[i][1] = Al_[base + 8 * LDW];
                ah[i][2] = Ah_[base + 4];           al[i][2] = Al_[base + 4];
                ah[i][3] = Ah_[base + 8 * LDW + 4]; al[i][3] = Al_[base + 8 * LDW + 4];
            }
            #pragma unroll
            for (int j = 0; j < NT; j++) {
                int bbase = (wn * WN + j * 8 + lr) * LDW + kk * 8 + lc;
                unsigned bh[2], bl[2];
                bh[0] = Bh_[bbase];     bl[0] = Bl_[bbase];
                bh[1] = Bh_[bbase + 4]; bl[1] = Bl_[bbase + 4];
                #pragma unroll
                for (int i = 0; i < MT; i++) {
                    mma_bf16(acc[i][j], ah[i], bh);
                    mma_bf16(acc[i][j], ah[i], bl);
                    mma_bf16(acc[i][j], al[i], bh);
                }
            }
        }
    };

    issue(0, 0); cp_commit();
    issue(1, 1); cp_commit();
    cp_wait<1>();
    __syncthreads();
    for (int kt = 0; kt < KT; kt++) {
        if (kt + 2 < KT) issue(kt + 2, (kt + 2) % 3);
        cp_commit();
        compute(kt % 3);
        cp_wait<1>();
        __syncthreads();
    }

    auto epi = [&](float v, int rr, int cc) -> float {
        if (EPI == EPI_PHI || EPI == EPI_QK) return v > 0.f ? v + 1.f : expf(v);
        if (EPI == EPI_GELU) return gelu_f(v + bias[cc]);
        if (EPI == EPI_RES)  return v + bias[cc] + res[(size_t)rr * N + cc];
        if (EPI == EPI_DIV)  return v * bias[rr];
        return v;
    };

    #pragma unroll
    for (int i = 0; i < MT; i++) {
        #pragma unroll
        for (int j = 0; j < NT; j++) {
            int rr = row0 + wm * WM + i * 16 + lr;
            int cc = col0 + wn * WN + j * 8 + 2 * lc;
            float e00 = epi(acc[i][j][0], rr, cc);
            float e01 = epi(acc[i][j][1], rr, cc + 1);
            float e10 = epi(acc[i][j][2], rr + 8, cc);
            float e11 = epi(acc[i][j][3], rr + 8, cc + 1);
            if (WF32) {
                *(float2*)(C + (size_t)rr * N + cc)       = make_float2(e00, e01);
                *(float2*)(C + (size_t)(rr + 8) * N + cc) = make_float2(e10, e11);
            }
            if (WPACK) {
                const int halfN = (EPI == EPI_QK) ? PP : N;
                if (EPI != EPI_QK || cc < PP) {
                    unsigned h, l;
                    split2(e00, e01, h, l);
                    size_t w0 = (size_t)rr * (halfN >> 1) + (cc >> 1);
                    Ch[w0] = h; Cl[w0] = l;
                    split2(e10, e11, h, l);
                    size_t w1 = (size_t)(rr + 8) * (halfN >> 1) + (cc >> 1);
                    Ch[w1] = h; Cl[w1] = l;
                }
            }
        }
    }
}

// ---------------- fused attn GEMM (K=64) + row LN, packed out ----------------
// Tile 64 x 512 per CTA (whole row in one CTA). 256 threads = 8 warps,
// warp tile 64x64 (WARPS_M=1, wn = warp). acc scaled by inv[row] pre-LN.
#define ALN_LDW 36
__global__ void __launch_bounds__(256)
attn_ln_kernel(const unsigned* __restrict__ Qh, const unsigned* __restrict__ Ql,
               const unsigned* __restrict__ KVTh, const unsigned* __restrict__ KVTl,
               const float* __restrict__ DEN,
               const float* __restrict__ gam, const float* __restrict__ bet,
               unsigned* __restrict__ Oh, unsigned* __restrict__ Ol)
{
    extern __shared__ unsigned sm[];
    unsigned* Ah_ = sm;                                   // 64 x 36
    unsigned* Al_ = sm + 64 * ALN_LDW;
    unsigned* Bh_ = sm + 2 * 64 * ALN_LDW;                // 512 x 36
    unsigned* Bl_ = sm + 2 * 64 * ALN_LDW + 512 * ALN_LDW;

    const int tid = threadIdx.x, lane = tid & 31, wn = tid >> 5;
    const int lr = lane >> 2, lc = lane & 3;
    const int row0 = blockIdx.x * 64;
    const int b = blockIdx.x / (SS / 64);
    const int KW = PP / 2;          // 32 words

    // A: 64 rows x 8 chunks = 512 chunks; 256 threads -> 2 each per array
    #pragma unroll
    for (int i = 0; i < 2; i++) {
        int idx = tid + i * 256;
        int r = idx >> 3, c = (idx & 7) * 4;
        size_t g = (size_t)(row0 + r) * KW + c;
        cp_async16(Ah_ + r * ALN_LDW + c, Qh + g);
        cp_async16(Al_ + r * ALN_LDW + c, Ql + g);
    }
    // B: 512 rows x 8 chunks = 4096 -> 16 each per array
    const unsigned* Kh = KVTh + (size_t)b * EE * KW;
    const unsigned* Kl = KVTl + (size_t)b * EE * KW;
    #pragma unroll
    for (int i = 0; i < 16; i++) {
        int idx = tid + i * 256;
        int r = idx >> 3, c = (idx & 7) * 4;
        size_t g = (size_t)r * KW + c;
        cp_async16(Bh_ + r * ALN_LDW + c, Kh + g);
        cp_async16(Bl_ + r * ALN_LDW + c, Kl + g);
    }
    cp_commit();
    cp_wait<0>();
    __syncthreads();

    float acc[4][8][4];
    #pragma unroll
    for (int i = 0; i < 4; i++)
        #pragma unroll
        for (int j = 0; j < 8; j++)
            #pragma unroll
            for (int q = 0; q < 4; q++) acc[i][j][q] = 0.f;

    #pragma unroll
    for (int kk = 0; kk < 4; kk++) {
        unsigned ah[4][4], al[4][4];
        #pragma unroll
        for (int i = 0; i < 4; i++) {
            int base = (i * 16 + lr) * ALN_LDW + kk * 8 + lc;
            ah[i][0] = Ah_[base];                   al[i][0] = Al_[base];
            ah[i][1] = Ah_[base + 8 * ALN_LDW];     al[i][1] = Al_[base + 8 * ALN_LDW];
            ah[i][2] = Ah_[base + 4];               al[i][2] = Al_[base + 4];
            ah[i][3] = Ah_[base + 8 * ALN_LDW + 4]; al[i][3] = Al_[base + 8 * ALN_LDW + 4];
        }
        #pragma unroll
        for (int j = 0; j < 8; j++) {
            int bbase = (wn * 64 + j * 8 + lr) * ALN_LDW + kk * 8 + lc;
            unsigned bh[2], bl[2];
            bh[0] = Bh_[bbase];     bl[0] = Bl_[bbase];
            bh[1] = Bh_[bbase + 4]; bl[1] = Bl_[bbase + 4];
            #pragma unroll
            for (int i = 0; i < 4; i++) {
                mma_bf16(acc[i][j], ah[i], bh);
                mma_bf16(acc[i][j], ah[i], bl);
                mma_bf16(acc[i][j], al[i], bh);
            }
        }
    }

    // scale by inv, compute row sums / sumsq
    __syncthreads();                         // smem free for reduction reuse
    float* red = (float*)sm;                 // [i(4)][v(2)][lr(8)][wn(8)] x2 arrays
    #pragma unroll
    for (int i = 0; i < 4; i++) {
        int r0 = row0 + i * 16 + lr;
        float inv0 = DEN[r0], inv1 = DEN[r0 + 8];
        float s0 = 0.f, q0 = 0.f, s1 = 0.f, q1 = 0.f;
        #pragma unroll
        for (int j = 0; j < 8; j++) {
            acc[i][j][0] *= inv0; acc[i][j][1] *= inv0;
            acc[i][j][2] *= inv1; acc[i][j][3] *= inv1;
            s0 += acc[i][j][0] + acc[i][j][1];
            q0 += acc[i][j][0] * acc[i][j][0] + acc[i][j][1] * acc[i][j][1];
            s1 += acc[i][j][2] + acc[i][j][3];
            q1 += acc[i][j][2] * acc[i][j][2] + acc[i][j][3] * acc[i][j][3];
        }
        #pragma unroll
        for (int o = 1; o <= 2; o <<= 1) {
            s0 += __shfl_xor_sync(0xffffffffu, s0, o);
            q0 += __shfl_xor_sync(0xffffffffu, q0, o);
            s1 += __shfl_xor_sync(0xffffffffu, s1, o);
            q1 += __shfl_xor_sync(0xffffffffu, q1, o);
        }
        if (lc == 0) {
            int i0 = ((i * 2 + 0) * 8 + lr) * 8 + wn;
            int i1 = ((i * 2 + 1) * 8 + lr) * 8 + wn;
            red[i0] = s0; red[512 + i0] = q0;
            red[i1] = s1; red[512 + i1] = q1;
        }
    }
    __syncthreads();

    #pragma unroll
    for (int i = 0; i < 4; i++) {
        #pragma unroll
        for (int v = 0; v < 2; v++) {
            int base = ((i * 2 + v) * 8 + lr) * 8;
            float S = 0.f, Q = 0.f;
            #pragma unroll
            for (int w = 0; w < 8; w++) { S += red[base + w]; Q += red[512 + base + w]; }
            float mu = S * (1.f / EE);
            float var = Q * (1.f / EE) - mu * mu;
            float invs = rsqrtf(var + 1e-5f);
            int row = row0 + i * 16 + lr + 8 * v;
            #pragma unroll
            for (int j = 0; j < 8; j++) {
                int c0 = wn * 64 + j * 8 + 2 * lc;
                float o0 = (acc[i][j][2 * v]     - mu) * invs * gam[c0]     + bet[c0];
                float o1 = (acc[i][j][2 * v + 1] - mu) * invs * gam[c0 + 1] + bet[c0 + 1];
                unsigned h, l;
                split2(o0, o1, h, l);
                size_t wo = (size_t)row * (EE / 2) + (c0 >> 1);
                Oh[wo] = h; Ol[wo] = l;
            }
        }
    }
}

// ---------------- KH partials + z partials (fused), split over S ----------------
__global__ void __launch_bounds__(256)
kv_kernel(const float* __restrict__ QK, const float* __restrict__ Hm,
          float* __restrict__ KHp, float* __restrict__ Zp)
{
    int b = blockIdx.y, f0 = blockIdx.x * 64, sp = blockIdx.z;
    const float* Kb = QK + (size_t)b * SS * 2 * PP + PP;
    const float* Vb = Hm + (size_t)b * SS * EE;
    __shared__ float Ks[32 * 64];
    __shared__ float Vs[32 * 64];
    int tid = threadIdx.x, tx = tid % 16, ty = tid / 16;
    const bool doz = (blockIdx.x == 0);
    int zp = tid & 63, zg = tid >> 6;
    float zacc = 0.f;
    float acc[4][4];
    #pragma unroll
    for (int i = 0; i < 4; i++)
        #pragma unroll
        for (int j = 0; j < 4; j++) acc[i][j] = 0.f;
    int sbeg = sp * (SS / NSPLIT), send = sbeg + (SS / NSPLIT);
    for (int s0 = sbeg; s0 < send; s0 += 32) {
        #pragma unroll
        for (int i = 0; i < 2; i++) {
            int idx = tid + i * 256;
            int r = idx / 16, c4 = idx % 16;
            *(float4*)(Ks + r * 64 + c4 * 4) =
                *(const float4*)(Kb + (size_t)(s0 + r) * 2 * PP + c4 * 4);
            *(float4*)(Vs + r * 64 + c4 * 4) =
                *(const float4*)(Vb + (size_t)(s0 + r) * EE + f0 + c4 * 4);
        }
        __syncthreads();
        #pragma unroll
        for (int k = 0; k < 32; k++) {
            float rp[4], rv[4];
            #pragma unroll
            for (int i = 0; i < 4; i++) rp[i] = Ks[k * 64 + ty * 4 + i];
            #pragma unroll
            for (int j = 0; j < 4; j++) rv[j] = Vs[k * 64 + tx * 4 + j];
            #pragma unroll
            for (int i = 0; i < 4; i++)
                #pragma unroll
                for (int j = 0; j < 4; j++)
                    acc[i][j] = fmaf(rp[i], rv[j], acc[i][j]);
        }
        if (doz) {
            #pragma unroll
            for (int r = 0; r < 8; r++)
                zacc += Ks[(zg + r * 4) * 64 + zp];
        }
        __syncthreads();
    }
    float* out = KHp + (size_t)sp * BB * PP * EE;
    #pragma unroll
    for (int i = 0; i < 4; i++)
        #pragma unroll
        for (int j = 0; j < 4; j++)
            out[((size_t)b * PP + ty * 4 + i) * EE + f0 + tx * 4 + j] = acc[i][j];
    if (doz) {
        __shared__ float zsm[256];
        zsm[tid] = zacc;
        __syncthreads();
        if (zg == 0)
            Zp[(size_t)sp * BB * PP + b * PP + zp] =
                zsm[zp] + zsm[64 + zp] + zsm[128 + zp] + zsm[192 + zp];
    }
}

__global__ void reduce_all(const float* __restrict__ KHp, float* __restrict__ KH,
                           const float* __restrict__ Zp, float* __restrict__ Z) {
    const int NKV = (BB * PP * EE) / 256;
    if ((int)blockIdx.x < NKV) {
        size_t idx = (size_t)blockIdx.x * 256 + threadIdx.x;
        float s = 0.f;
        #pragma unroll
        for (int sp = 0; sp < NSPLIT; sp++) s += KHp[(size_t)sp * BB * PP * EE + idx];
        KH[idx] = s;
    } else {
        int idx = threadIdx.x + 256 * (blockIdx.x - NKV);
        if (idx < BB * PP) {
            float s = 0.f;
            #pragma unroll
            for (int sp = 0; sp < NSPLIT; sp++) s += Zp[sp * BB * PP + idx];
            Z[idx] = s;
        }
    }
}

__global__ void den_kernel(const float* __restrict__ QK, const float* __restrict__ Z,
                           float* __restrict__ inv) {
    int row = blockIdx.x * 8 + (threadIdx.x >> 5);
    int lane = threadIdx.x & 31;
    int b = row >> 12;
    const float* q = QK + (size_t)row * 2 * PP;
    const float* z = Z + b * PP;
    float s = q[lane] * z[lane] + q[lane + 32] * z[lane + 32];
    #pragma unroll
    for (int o = 16; o; o >>= 1) s += __shfl_xor_sync(0xffffffffu, s, o);
    if (lane == 0) inv[row] = 1.f / (s + 1e-6f);
}

// ---------------- last-layer (s=0 only) fp32 chain ----------------
__global__ void last_den_kernel(const float* __restrict__ QK,
                                const float* __restrict__ Z,
                                float* __restrict__ DEN8) {
    int b = blockIdx.x, p = threadIdx.x;
    const float* q = QK + (size_t)b * SS * 2 * PP;
    __shared__ float sm[PP];
    sm[p] = q[p] * Z[b * PP + p];
    __syncthreads();
    if (p == 0) {
        float s = 0.f;
        for (int i = 0; i < PP; i++) s += sm[i];
        DEN8[b] = 1.f / (s + 1e-6f);
    }
}

__global__ void last_attn_kernel(const float* __restrict__ QK,
                                 const float* __restrict__ KVW,
                                 const float* __restrict__ DEN8,
                                 float* __restrict__ ATT8) {
    int b = blockIdx.x, tid = threadIdx.x;
    __shared__ float ph[PP];
    if (tid < PP) ph[tid] = QK[(size_t)b * SS * 2 * PP + tid];
    __syncthreads();
    float inv = DEN8[b];
    for (int f = tid; f < EE; f += 256) {
        float a = 0.f;
        for (int p = 0; p < PP; p++)
            a = fmaf(ph[p], KVW[((size_t)b * PP + p) * EE + f], a);
        ATT8[b * EE + f] = a * inv;
    }
}

__global__ void last_ln_kernel(const float* __restrict__ ATT8,
                               const float* __restrict__ gam,
                               const float* __restrict__ bet,
                               float* __restrict__ LN8) {
    int b = blockIdx.x, e = threadIdx.x;
    float a = ATT8[b * EE + e];
    float s = a, q = a * a;
    #pragma unroll
    for (int o = 16; o; o >>= 1) {
        s += __shfl_xor_sync(0xffffffffu, s, o);
        q += __shfl_xor_sync(0xffffffffu, q, o);
    }
    __shared__ float ssum[16], ssq[16];
    int w = e >> 5;
    if ((e & 31) == 0) { ssum[w] = s; ssq[w] = q; }
    __syncthreads();
    float S = 0.f, Qq = 0.f;
    #pragma unroll
    for (int i = 0; i < 16; i++) { S += ssum[i]; Qq += ssq[i]; }
    float mu = S * (1.f / EE);
    float var = Qq * (1.f / EE) - mu * mu;
    float inv = rsqrtf(var + 1e-5f);
    LN8[b * EE + e] = (a - mu) * inv * gam[e] + bet[e];
}

__global__ void last_mlp1_kernel(const float* __restrict__ LN8,
                                 const float* __restrict__ W1,
                                 const float* __restrict__ b1,
                                 float* __restrict__ M8) {
    int b = blockIdx.y, j = blockIdx.x * 512 + threadIdx.x;
    __shared__ float ln[EE];
    for (int i = threadIdx.x; i < EE; i += 512) ln[i] = LN8[b * EE + i];
    __syncthreads();
    float acc = b1[j];
    for (int e = 0; e < EE; e++) acc = fmaf(ln[e], W1[(size_t)e * FF + j], acc);
    M8[b * FF + j] = gelu_f(acc);
}

__global__ void last_mlp2_kernel(const float* __restrict__ M8,
                                 const float* __restrict__ W2,
                                 const float* __restrict__ b2,
                                 const float* __restrict__ H,
                                 float* __restrict__ H8) {
    int b = blockIdx.x, e = threadIdx.x;
    float acc = b2[e];
    const float* m = M8 + (size_t)b * FF;
    for (int j = 0; j < FF; j++) acc = fmaf(m[j], W2[(size_t)j * EE + e], acc);
    H8[b * EE + e] = acc + H[(size_t)b * SS * EE + e];
}

// ---------------- head ----------------
__global__ void head_kernel(const float* __restrict__ H8, const float* __restrict__ Wh1,
                            const float* __restrict__ bh1, const float* __restrict__ Wh2,
                            const float* __restrict__ bh2, float* __restrict__ out) {
    int b = blockIdx.x, tid = threadIdx.x;
    const float* hr = H8 + (size_t)b * EE;
    float acc = bh1[tid];
    for (int e = 0; e < EE; e++) acc = fmaf(hr[e], Wh1[e * HH + tid], acc);
    acc = fmaxf(acc, 0.f);
    __shared__ float hid[HH];
    hid[tid] = acc;
    __syncthreads();
    if (tid < CC) {
        float a = bh2[tid];
        for (int h = 0; h < HH; h++) a = fmaf(hid[h], Wh2[h * CC + tid], a);
        out[b * CC + tid] = a;
    }
}

// ---------------- launch ----------------
static size_t gemm_smem(int BM, int BN) {
    return (size_t)(3 * (BM * 20 * 2 + BN * 20 * 2)) * 4;
}

extern "C" void kernel_launch(void* const* d_in, const int* in_sizes, int n_in,
                              void* d_out, int out_size) {
    const int*   x    = (const int*)  d_in[0];
    const float* emb  = (const float*)d_in[1];
    const float* pos  = (const float*)d_in[2];
    const float* Wq   = (const float*)d_in[3];
    const float* Wk   = (const float*)d_in[4];
    const float* Wv   = (const float*)d_in[5];
    const float* Wo   = (const float*)d_in[6];
    const float* ln_g = (const float*)d_in[7];
    const float* ln_b = (const float*)d_in[8];
    const float* W1   = (const float*)d_in[9];
    const float* b1   = (const float*)d_in[10];
    const float* W2   = (const float*)d_in[11];
    const float* b2   = (const float*)d_in[12];
    const float* Wh1  = (const float*)d_in[13];
    const float* bh1  = (const float*)d_in[14];
    const float* Wh2  = (const float*)d_in[15];
    const float* bh2  = (const float*)d_in[16];
    float* out = (float*)d_out;

    float *H, *QK, *KH, *KHp, *KVW, *WVWO, *Z, *Zp, *DEN;
    float *DEN8, *ATT8, *LN8, *M8, *H8;
    cudaGetSymbolAddress((void**)&H,    g_H);
    cudaGetSymbolAddress((void**)&QK,   g_QK);
    cudaGetSymbolAddress((void**)&KH,   g_KH);
    cudaGetSymbolAddress((void**)&KHp,  g_KHp);
    cudaGetSymbolAddress((void**)&KVW,  g_KVW);
    cudaGetSymbolAddress((void**)&WVWO, g_WVWO);
    cudaGetSymbolAddress((void**)&Z,    g_Z);
    cudaGetSymbolAddress((void**)&Zp,   g_Zp);
    cudaGetSymbolAddress((void**)&DEN,  g_DEN);
    cudaGetSymbolAddress((void**)&DEN8, g_DEN8);
    cudaGetSymbolAddress((void**)&ATT8, g_ATT8);
    cudaGetSymbolAddress((void**)&LN8,  g_LN8);
    cudaGetSymbolAddress((void**)&M8,   g_M8);
    cudaGetSymbolAddress((void**)&H8,   g_H8);

    unsigned *Hh, *Hl, *LNh, *LNl, *Mbh, *Mbl, *Qh, *Ql, *KVTh, *KVTl;
    cudaGetSymbolAddress((void**)&Hh,   g_Hh);   cudaGetSymbolAddress((void**)&Hl,   g_Hl);
    cudaGetSymbolAddress((void**)&LNh,  g_LNh);  cudaGetSymbolAddress((void**)&LNl,  g_LNl);
    cudaGetSymbolAddress((void**)&Mbh,  g_Mbh);  cudaGetSymbolAddress((void**)&Mbl,  g_Mbl);
    cudaGetSymbolAddress((void**)&Qh,   g_Qh);   cudaGetSymbolAddress((void**)&Ql,   g_Ql);
    cudaGetSymbolAddress((void**)&KVTh, g_KVTh); cudaGetSymbolAddress((void**)&KVTl, g_KVTl);

    unsigned *WQKh, *WQKl, *W1h, *W1l, *W2h, *W2l;
    cudaGetSymbolAddress((void**)&WQKh, g_WQKh); cudaGetSymbolAddress((void**)&WQKl, g_WQKl);
    cudaGetSymbolAddress((void**)&W1h,  g_W1h);  cudaGetSymbolAddress((void**)&W1l,  g_W1l_);
    cudaGetSymbolAddress((void**)&W2h,  g_W2h);  cudaGetSymbolAddress((void**)&W2l,  g_W2l_);

    const size_t smQK  = gemm_smem(128, 128);
    const size_t smBIG = gemm_smem(128, 256);
    const size_t smALN = (size_t)(2 * 64 * ALN_LDW + 2 * 512 * ALN_LDW) * 4;
    cudaFuncSetAttribute(gemm_pk<128, 128, 64, 32, EPI_QK, true, true, false>,
                         cudaFuncAttributeMaxDynamicSharedMemorySize, (int)smQK);
    cudaFuncSetAttribute(gemm_pk<128, 256, 64, 64, EPI_GELU, false, true, false>,
                         cudaFuncAttributeMaxDynamicSharedMemorySize, (int)smBIG);
    cudaFuncSetAttribute(gemm_pk<128, 256, 64, 64, EPI_RES, true, true, false>,
                         cudaFuncAttributeMaxDynamicSharedMemorySize, (int)smBIG);
    cudaFuncSetAttribute(attn_ln_kernel,
                         cudaFuncAttributeMaxDynamicSharedMemorySize, (int)smALN);

    // one-time weight prep
    dim3 wt(32, 8);
    {
        WSPack pA;
        const size_t qkL = (size_t)2 * PP * (EE / 2);
        pA.e[0] = { Wq, WQKh, WQKl, EE, PP, qkL, LL * (EE / 32) * (PP / 32) };
        pA.e[1] = { Wk, WQKh + (size_t)PP * (EE / 2), WQKl + (size_t)PP * (EE / 2),
                    EE, PP, qkL, LL * (EE / 32) * (PP / 32) };
        pA.e[2] = { W1, W1h, W1l, EE, FF, (size_t)FF * (EE / 2), LL * (EE / 32) * (FF / 32) };
        pA.e[3] = { W2, W2h, W2l, FF, EE, (size_t)EE * (FF / 2), LL * (FF / 32) * (EE / 32) };
        pA.cnt = 4;
        int nA = pA.e[0].nblk + pA.e[1].nblk + pA.e[2].nblk + pA.e[3].nblk;
        wsplit_multi<<<nA, wt>>>(pA);
    }
    wvwo_kernel<<<dim3(EE / 64, EE / 64, LL), 256>>>(Wv, Wo, WVWO);

    embed_kernel<<<MROWS, 128>>>(x, emb, pos, H, Hh, Hl);

    const int NRED = (BB * PP * EE) / 256 + 2;

    for (int l = 0; l < LL; l++) {
        size_t oQK = (size_t)l * 2 * PP * (EE / 2);
        size_t oW1 = (size_t)l * FF * (EE / 2);
        size_t oW2 = (size_t)l * EE * (FF / 2);
        const bool last = (l == LL - 1);

        gemm_pk<128, 128, 64, 32, EPI_QK, true, true, false>
            <<<dim3(1, MROWS / 128), 256, smQK>>>(
                MROWS, 2 * PP, EE, Hh, Hl, WQKh + oQK, WQKl + oQK,
                nullptr, nullptr, QK, Qh, Ql);

        kv_kernel<<<dim3(EE / 64, BB, NSPLIT), 256>>>(QK, H, KHp, Zp);
        reduce_all<<<NRED, 256>>>(KHp, KH, Zp, Z);
        kvwo_kernel<<<dim3(EE / 64, BB), 256>>>(KH, WVWO + (size_t)l * EE * EE,
                                                KVW, KVTh, KVTl);

        if (!last) {
            den_kernel<<<MROWS / 8, 256>>>(QK, Z, DEN);

            // fused: LN((phi_q @ KVT) * inv) -> packed LNh/LNl, no fp32 round-trip
            attn_ln_kernel<<<MROWS / 64, 256, smALN>>>(
                Qh, Ql, KVTh, KVTl, DEN,
                ln_g + (size_t)l * EE, ln_b + (size_t)l * EE, LNh, LNl);

            gemm_pk<128, 256, 64, 64, EPI_GELU, false, true, false>
                <<<dim3(FF / 256, MROWS / 128), 256, smBIG>>>(
                    MROWS, FF, EE, LNh, LNl, W1h + oW1, W1l + oW1,
                    b1 + (size_t)l * FF, nullptr, nullptr, Mbh, Mbl);
            gemm_pk<128, 256, 64, 64, EPI_RES, true, true, false>
                <<<dim3(EE / 256, MROWS / 128), 256, smBIG>>>(
                    MROWS, EE, FF, Mbh, Mbl, W2h + oW2, W2l + oW2,
                    b2 + (size_t)l * EE, H, H, Hh, Hl);
        } else {
            const float* W1l3 = W1 + (size_t)l * EE * FF;
            const float* W2l3 = W2 + (size_t)l * FF * EE;
            last_den_kernel<<<BB, PP>>>(QK, Z, DEN8);
            last_attn_kernel<<<BB, 256>>>(QK, KVW, DEN8, ATT8);
            last_ln_kernel<<<BB, EE>>>(ATT8, ln_g + (size_t)l * EE,
                                       ln_b + (size_t)l * EE, LN8);
            last_mlp1_kernel<<<dim3(FF / 512, BB), 512>>>(LN8, W1l3,
                                                          b1 + (size_t)l * FF, M8);
            last_mlp2_kernel<<<BB, EE>>>(M8, W2l3, b2 + (size_t)l * EE, H, H8);
        }
    }

    head_kernel<<<BB, HH>>>(H8, Wh1, bh1, Wh2, bh2, out);
}